// round 9
// baseline (speedup 1.0000x reference)
#include <cuda_runtime.h>
#include <cuda_bf16.h>
#include <math.h>

#define NR 8192
#define SS 128
#define GRIDF 444          // 3 CTAs/SM x 148 SMs
#define THREADS 128        // 4 warps = 1 ray per iteration

typedef unsigned int u32;

// ---------------- smem layout (bytes), per CTA ----------------
#define OFF_AH   0                 // 4 warps x 32 rows x 144B (bf16 hi)
#define OFF_AL   18432             // lo plane
#define OFF_W1H  36864             // W1^T [64n][72 bf16 stride], K pad 64
#define OFF_W1L  46080
#define OFF_W2H  55296             // W2^T [16n][72]
#define OFF_W2L  57600
#define OFF_B3H  59904             // V1[0:15]^T shifted: [64n][20 bf16 stride], k0=0
#define OFF_B3L  62464
#define OFF_B4H  65024             // V2^T [8n][72], n>=3 zero
#define OFF_B4L  66176
#define OFF_B1   67328             // b1 (64 f32)
#define OFF_B2   67584             // b2 (16 f32)
#define OFF_C2   67648             // c2 (8 f32, padded)
#define OFF_RED  67680             // 4 warp products / dt partials
#define OFF_PART 67712             // 4 warps x 4 floats
#define OFF_GB   67776             // per-ray g_base (64 f32)
#define SMEM_TOTAL 68032

static __device__ __forceinline__ u32 pk2(__nv_bfloat16 a, __nv_bfloat16 b) {
    return (u32)__bfloat16_as_ushort(a) | ((u32)__bfloat16_as_ushort(b) << 16);
}
static __device__ __forceinline__ void split2(float x, float y, u32& hi, u32& lo) {
    __nv_bfloat16 hx = __float2bfloat16(x), hy = __float2bfloat16(y);
    hi = pk2(hx, hy);
    lo = pk2(__float2bfloat16(x - __bfloat162float(hx)),
             __float2bfloat16(y - __bfloat162float(hy)));
}
static __device__ __forceinline__ void mma4(float* d, const u32* a, u32 b0, u32 b1) {
    asm volatile(
        "mma.sync.aligned.m16n8k16.row.col.f32.bf16.bf16.f32 "
        "{%0,%1,%2,%3}, {%4,%5,%6,%7}, {%8,%9}, {%0,%1,%2,%3};"
        : "+f"(d[0]), "+f"(d[1]), "+f"(d[2]), "+f"(d[3])
        : "r"(a[0]), "r"(a[1]), "r"(a[2]), "r"(a[3]), "r"(b0), "r"(b1));
}

// ---------------------------------------------------------------------------
// Fused ray-marcher, single kernel. CTA = 128 threads = 4 warps = one ray/iter.
// dt computed per-CTA at start (deterministic, identical everywhere);
// per-ray g_base computed in-iteration into smem by threads 0..63.
// ---------------------------------------------------------------------------
__global__ __launch_bounds__(THREADS, 3)
void fused_kernel(const float* __restrict__ orig, const float* __restrict__ dirs,
                  const float* __restrict__ tmin, const float* __restrict__ tmax,
                  const float* __restrict__ W1, const float* __restrict__ b1,
                  const float* __restrict__ W2, const float* __restrict__ b2,
                  const float* __restrict__ V1, const float* __restrict__ c1,
                  const float* __restrict__ V2, const float* __restrict__ c2,
                  float* __restrict__ outp) {
    extern __shared__ char dsm[];
    const int tid = threadIdx.x;
    const int w = tid >> 5, lane = tid & 31, g = lane >> 2, tig = lane & 3;
    const u32 FULL = 0xffffffffu;

    // ---------------- dt = mean(tmax - tmin) / SS (every CTA, same order) ---
    float dtv;
    {
        float s = 0.f;
#pragma unroll 1
        for (int i = tid; i < NR; i += THREADS) s += tmax[i] - tmin[i];
#pragma unroll
        for (int o = 16; o > 0; o >>= 1) s += __shfl_down_sync(FULL, s, o);
        float* red = (float*)(dsm + OFF_RED);
        if (lane == 0) red[w] = s;
        __syncthreads();
        dtv = (red[0] + red[1] + red[2] + red[3]) / (float)(NR * SS);
        __syncthreads();
    }

    // ---------------- stage weights: split bf16 hi/lo, K-major padded ------
    for (int i = tid; i < 64 * 64; i += THREADS) {            // W1^T, K pad 64
        int n = i >> 6, k = i & 63;
        float v = (k < 63) ? W1[k * 64 + n] : 0.f;
        __nv_bfloat16 h = __float2bfloat16(v);
        *(__nv_bfloat16*)(dsm + OFF_W1H + n * 144 + k * 2) = h;
        *(__nv_bfloat16*)(dsm + OFF_W1L + n * 144 + k * 2) =
            __float2bfloat16(v - __bfloat162float(h));
    }
    for (int i = tid; i < 16 * 64; i += THREADS) {            // W2^T
        int n = i >> 6, k = i & 63;
        float v = W2[k * 16 + n];
        __nv_bfloat16 h = __float2bfloat16(v);
        *(__nv_bfloat16*)(dsm + OFF_W2H + n * 144 + k * 2) = h;
        *(__nv_bfloat16*)(dsm + OFF_W2L + n * 144 + k * 2) =
            __float2bfloat16(v - __bfloat162float(h));
    }
    for (int i = tid; i < 64 * 16; i += THREADS) {            // B3 = shifted V1[0:15]^T
        int n = i >> 4, k = i & 15;
        float v = (k >= 1) ? V1[(k - 1) * 64 + n] : 0.f;
        __nv_bfloat16 h = __float2bfloat16(v);
        *(__nv_bfloat16*)(dsm + OFF_B3H + n * 40 + k * 2) = h;
        *(__nv_bfloat16*)(dsm + OFF_B3L + n * 40 + k * 2) =
            __float2bfloat16(v - __bfloat162float(h));
    }
    for (int i = tid; i < 8 * 64; i += THREADS) {             // B4 = V2^T, n pad 8
        int n = i >> 6, k = i & 63;
        float v = (n < 3) ? V2[k * 3 + n] : 0.f;
        __nv_bfloat16 h = __float2bfloat16(v);
        *(__nv_bfloat16*)(dsm + OFF_B4H + n * 144 + k * 2) = h;
        *(__nv_bfloat16*)(dsm + OFF_B4L + n * 144 + k * 2) =
            __float2bfloat16(v - __bfloat162float(h));
    }
    for (int i = tid; i < 64; i += THREADS) ((float*)(dsm + OFF_B1))[i] = b1[i];
    if (tid < 16) ((float*)(dsm + OFF_B2))[tid] = b2[tid];
    if (tid < 8)  ((float*)(dsm + OFF_C2))[tid] = (tid < 3) ? c2[tid] : 0.f;
    __syncthreads();

    for (int ray = blockIdx.x; ray < NR; ray += GRIDF) {
        const int s = (w << 5) + lane;

        // ---------------- positional encoding, row = lane -------------------
        const float dx = dirs[ray * 3 + 0], dy = dirs[ray * 3 + 1], dz = dirs[ray * 3 + 2];
        const float t0 = tmin[ray], t1 = tmax[ray];
        const float tt = t0 + (float)s * (1.0f / (SS - 1)) * (t1 - t0);
        float enc[64];
        enc[0] = fmaf(dx, tt, orig[ray * 3 + 0]);
        enc[1] = fmaf(dy, tt, orig[ray * 3 + 1]);
        enc[2] = fmaf(dz, tt, orig[ray * 3 + 2]);
        {
            float sx, cx, sy, cy, sz, cz;
            sincosf(enc[0], &sx, &cx); sincosf(enc[1], &sy, &cy); sincosf(enc[2], &sz, &cz);
#pragma unroll
            for (int i = 0; i < 10; i++) {
                enc[3 + 6 * i + 0] = sx; enc[3 + 6 * i + 1] = sy; enc[3 + 6 * i + 2] = sz;
                enc[3 + 6 * i + 3] = cx; enc[3 + 6 * i + 4] = cy; enc[3 + 6 * i + 5] = cz;
                const float nsx = 2.f * sx * cx, ncx = fmaf(-2.f * sx, sx, 1.f);
                const float nsy = 2.f * sy * cy, ncy = fmaf(-2.f * sy, sy, 1.f);
                const float nsz = 2.f * sz * cz, ncz = fmaf(-2.f * sz, sz, 1.f);
                sx = nsx; cx = ncx; sy = nsy; cy = ncy; sz = nsz; cz = ncz;
            }
        }
        enc[63] = 0.f;
        {
            char* Ah = dsm + OFF_AH + w * 4608 + lane * 144;
            char* Al = dsm + OFF_AL + w * 4608 + lane * 144;
#pragma unroll
            for (int j8 = 0; j8 < 8; j8++) {
                u32 h0, l0, h1, l1, h2, l2, h3, l3;
                split2(enc[8 * j8 + 0], enc[8 * j8 + 1], h0, l0);
                split2(enc[8 * j8 + 2], enc[8 * j8 + 3], h1, l1);
                split2(enc[8 * j8 + 4], enc[8 * j8 + 5], h2, l2);
                split2(enc[8 * j8 + 6], enc[8 * j8 + 7], h3, l3);
                *(uint4*)(Ah + j8 * 16) = make_uint4(h0, h1, h2, h3);
                *(uint4*)(Al + j8 * 16) = make_uint4(l0, l1, l2, l3);
            }
        }
        __syncwarp();

        // ---------------- per-ray g_base into smem (threads 0..63) ----------
        if (tid < 64) {
            const float nrm = sqrtf(dx * dx + dy * dy + dz * dz) + 1e-8f;
            const float inv = 1.0f / nrm;
            const float vx = dx * inv, vy = dy * inv, vz = dz * inv;
            float v[27];
            v[0] = vx; v[1] = vy; v[2] = vz;
            {
                float sx, cx, sy, cy, sz, cz;
                sincosf(vx, &sx, &cx); sincosf(vy, &sy, &cy); sincosf(vz, &sz, &cz);
#pragma unroll
                for (int i = 0; i < 4; i++) {
                    v[3 + 6 * i + 0] = sx; v[3 + 6 * i + 1] = sy; v[3 + 6 * i + 2] = sz;
                    v[3 + 6 * i + 3] = cx; v[3 + 6 * i + 4] = cy; v[3 + 6 * i + 5] = cz;
                    const float nsx = 2.f * sx * cx, ncx = fmaf(-2.f * sx, sx, 1.f);
                    const float nsy = 2.f * sy * cy, ncy = fmaf(-2.f * sy, sy, 1.f);
                    const float nsz = 2.f * sz * cz, ncz = fmaf(-2.f * sz, sz, 1.f);
                    sx = nsx; cx = ncx; sy = nsy; cy = ncy; sz = nsz; cz = ncz;
                }
            }
            float acc0 = c1[tid];
#pragma unroll 1
            for (int i = 0; i < 27; i++) acc0 = fmaf(v[i], V1[(15 + i) * 64 + tid], acc0);
            ((float*)(dsm + OFF_GB))[tid] = acc0;
        }
        __syncthreads();

        // ---------------- MLP1: enc(64) @ W1 -> 32x64 -----------------------
        float acc[2][8][4];
#pragma unroll
        for (int mt = 0; mt < 2; mt++)
#pragma unroll
            for (int nt = 0; nt < 8; nt++)
#pragma unroll
                for (int r = 0; r < 4; r++) acc[mt][nt][r] = 0.f;

        const char* AHb = dsm + OFF_AH + w * 4608;
        const char* ALb = dsm + OFF_AL + w * 4608;
#pragma unroll
        for (int kt = 0; kt < 4; kt++) {
            u32 AH[2][4], AL[2][4];
#pragma unroll
            for (int mt = 0; mt < 2; mt++) {
                int ab = mt * 2304 + g * 144 + kt * 32 + tig * 4;
                AH[mt][0] = *(const u32*)(AHb + ab);
                AH[mt][1] = *(const u32*)(AHb + ab + 1152);
                AH[mt][2] = *(const u32*)(AHb + ab + 16);
                AH[mt][3] = *(const u32*)(AHb + ab + 1168);
                AL[mt][0] = *(const u32*)(ALb + ab);
                AL[mt][1] = *(const u32*)(ALb + ab + 1152);
                AL[mt][2] = *(const u32*)(ALb + ab + 16);
                AL[mt][3] = *(const u32*)(ALb + ab + 1168);
            }
#pragma unroll
            for (int nt = 0; nt < 8; nt++) {
                int bo = (nt * 8 + g) * 144 + kt * 32 + tig * 4;
                u32 bh0 = *(const u32*)(dsm + OFF_W1H + bo);
                u32 bh1 = *(const u32*)(dsm + OFF_W1H + bo + 16);
                u32 bl0 = *(const u32*)(dsm + OFF_W1L + bo);
                u32 bl1 = *(const u32*)(dsm + OFF_W1L + bo + 16);
#pragma unroll
                for (int mt = 0; mt < 2; mt++) {
                    mma4(acc[mt][nt], AH[mt], bh0, bh1);
                    mma4(acc[mt][nt], AH[mt], bl0, bl1);
                    mma4(acc[mt][nt], AL[mt], bh0, bh1);
                }
            }
        }

        // ---------------- epi1: h = relu(D + b1) -> A frags (regs) ----------
        u32 HF[2][4][4], HL[2][4][4];
#pragma unroll
        for (int kt = 0; kt < 4; kt++)
#pragma unroll
            for (int j = 0; j < 2; j++) {
                const int nt = 2 * kt + j;
                const float2 bb = *(const float2*)(dsm + OFF_B1 + (nt * 8 + tig * 2) * 4);
#pragma unroll
                for (int mt = 0; mt < 2; mt++) {
                    float v0 = fmaxf(acc[mt][nt][0] + bb.x, 0.f);
                    float v1 = fmaxf(acc[mt][nt][1] + bb.y, 0.f);
                    float v2 = fmaxf(acc[mt][nt][2] + bb.x, 0.f);
                    float v3 = fmaxf(acc[mt][nt][3] + bb.y, 0.f);
                    split2(v0, v1, HF[mt][kt][2 * j + 0], HL[mt][kt][2 * j + 0]);
                    split2(v2, v3, HF[mt][kt][2 * j + 1], HL[mt][kt][2 * j + 1]);
                }
            }

        // ---------------- MLP2: h @ W2 -> 32x16 -----------------------------
        float a2c[2][2][4];
#pragma unroll
        for (int mt = 0; mt < 2; mt++)
#pragma unroll
            for (int n2 = 0; n2 < 2; n2++)
#pragma unroll
                for (int r = 0; r < 4; r++) a2c[mt][n2][r] = 0.f;
#pragma unroll
        for (int kt = 0; kt < 4; kt++)
#pragma unroll
            for (int n2 = 0; n2 < 2; n2++) {
                int bo = (n2 * 8 + g) * 144 + kt * 32 + tig * 4;
                u32 bh0 = *(const u32*)(dsm + OFF_W2H + bo);
                u32 bh1 = *(const u32*)(dsm + OFF_W2H + bo + 16);
                u32 bl0 = *(const u32*)(dsm + OFF_W2L + bo);
                u32 bl1 = *(const u32*)(dsm + OFF_W2L + bo + 16);
#pragma unroll
                for (int mt = 0; mt < 2; mt++) {
                    mma4(a2c[mt][n2], HF[mt][kt], bh0, bh1);
                    mma4(a2c[mt][n2], HF[mt][kt], bl0, bl1);
                    mma4(a2c[mt][n2], HL[mt][kt], bh0, bh1);
                }
            }

        // ---------------- epi2: sigma raw + feat frags ----------------------
        float sgm[2][2];
        u32 FF[2][4], FL[2][4];
        {
            const float2 b20 = *(const float2*)(dsm + OFF_B2 + tig * 8);
            const float2 b21 = *(const float2*)(dsm + OFF_B2 + 32 + tig * 8);
#pragma unroll
            for (int mt = 0; mt < 2; mt++) {
                float v0 = a2c[mt][0][0] + b20.x;
                float v1 = a2c[mt][0][1] + b20.y;
                float v2 = a2c[mt][0][2] + b20.x;
                float v3 = a2c[mt][0][3] + b20.y;
                float u0 = a2c[mt][1][0] + b21.x;
                float u1 = a2c[mt][1][1] + b21.y;
                float u2 = a2c[mt][1][2] + b21.x;
                float u3 = a2c[mt][1][3] + b21.y;
                sgm[mt][0] = v0;
                sgm[mt][1] = v2;
                split2(v0, v1, FF[mt][0], FL[mt][0]);
                split2(v2, v3, FF[mt][1], FL[mt][1]);
                split2(u0, u1, FF[mt][2], FL[mt][2]);
                split2(u2, u3, FF[mt][3], FL[mt][3]);
            }
        }

        // ---------------- MLP3: feats(16) @ B3 -> 32x64 ---------------------
        float a3c[2][8][4];
#pragma unroll
        for (int mt = 0; mt < 2; mt++)
#pragma unroll
            for (int nt = 0; nt < 8; nt++)
#pragma unroll
                for (int r = 0; r < 4; r++) a3c[mt][nt][r] = 0.f;
#pragma unroll
        for (int nt = 0; nt < 8; nt++) {
            int bo = (nt * 8 + g) * 40 + tig * 4;
            u32 bh0 = *(const u32*)(dsm + OFF_B3H + bo);
            u32 bh1 = *(const u32*)(dsm + OFF_B3H + bo + 16);
            u32 bl0 = *(const u32*)(dsm + OFF_B3L + bo);
            u32 bl1 = *(const u32*)(dsm + OFF_B3L + bo + 16);
#pragma unroll
            for (int mt = 0; mt < 2; mt++) {
                mma4(a3c[mt][nt], FF[mt], bh0, bh1);
                mma4(a3c[mt][nt], FF[mt], bl0, bl1);
                mma4(a3c[mt][nt], FL[mt], bh0, bh1);
            }
        }

        // ---------------- epi3: g = relu(D + g_base) -> g frags -------------
        u32 GF[2][4][4], GL[2][4][4];
        const float* gbs = (const float*)(dsm + OFF_GB);
#pragma unroll
        for (int kt = 0; kt < 4; kt++)
#pragma unroll
            for (int j = 0; j < 2; j++) {
                const int nt = 2 * kt + j;
                const float2 gv = *(const float2*)(gbs + nt * 8 + tig * 2);
#pragma unroll
                for (int mt = 0; mt < 2; mt++) {
                    float v0 = fmaxf(a3c[mt][nt][0] + gv.x, 0.f);
                    float v1 = fmaxf(a3c[mt][nt][1] + gv.y, 0.f);
                    float v2 = fmaxf(a3c[mt][nt][2] + gv.x, 0.f);
                    float v3 = fmaxf(a3c[mt][nt][3] + gv.y, 0.f);
                    split2(v0, v1, GF[mt][kt][2 * j + 0], GL[mt][kt][2 * j + 0]);
                    split2(v2, v3, GF[mt][kt][2 * j + 1], GL[mt][kt][2 * j + 1]);
                }
            }

        // ---------------- MLP4: g @ V2 -> 32x8 ------------------------------
        float a4[2][4];
#pragma unroll
        for (int mt = 0; mt < 2; mt++)
#pragma unroll
            for (int r = 0; r < 4; r++) a4[mt][r] = 0.f;
#pragma unroll
        for (int kt = 0; kt < 4; kt++) {
            int bo = g * 144 + kt * 32 + tig * 4;
            u32 bh0 = *(const u32*)(dsm + OFF_B4H + bo);
            u32 bh1 = *(const u32*)(dsm + OFF_B4H + bo + 16);
            u32 bl0 = *(const u32*)(dsm + OFF_B4L + bo);
            u32 bl1 = *(const u32*)(dsm + OFF_B4L + bo + 16);
#pragma unroll
            for (int mt = 0; mt < 2; mt++) {
                mma4(a4[mt], GF[mt][kt], bh0, bh1);
                mma4(a4[mt], GF[mt][kt], bl0, bl1);
                mma4(a4[mt], GL[mt][kt], bh0, bh1);
            }
        }

        // ---------------- epi4 + redistribution lane<->row ------------------
        float o0[2], o1[2], o2[2], o3[2];
        {
            const float2 cc = *(const float2*)(dsm + OFF_C2 + tig * 8);
#pragma unroll
            for (int mt = 0; mt < 2; mt++) {
                o0[mt] = a4[mt][0] + cc.x;
                o1[mt] = a4[mt][1] + cc.y;
                o2[mt] = a4[mt][2] + cc.x;
                o3[mt] = a4[mt][3] + cc.y;
            }
        }
        const int q4 = (lane & 7) * 4;
        const int selv = lane >> 3;
        float x0, x1, x2, x3;
        x0 = __shfl_sync(FULL, sgm[0][0], q4);
        x1 = __shfl_sync(FULL, sgm[0][1], q4);
        x2 = __shfl_sync(FULL, sgm[1][0], q4);
        x3 = __shfl_sync(FULL, sgm[1][1], q4);
        const float sigma = fmaxf(selv == 0 ? x0 : selv == 1 ? x1 : selv == 2 ? x2 : x3, 0.f);
        x0 = __shfl_sync(FULL, o0[0], q4);
        x1 = __shfl_sync(FULL, o2[0], q4);
        x2 = __shfl_sync(FULL, o0[1], q4);
        x3 = __shfl_sync(FULL, o2[1], q4);
        const float rv = selv == 0 ? x0 : selv == 1 ? x1 : selv == 2 ? x2 : x3;
        x0 = __shfl_sync(FULL, o1[0], q4);
        x1 = __shfl_sync(FULL, o3[0], q4);
        x2 = __shfl_sync(FULL, o1[1], q4);
        x3 = __shfl_sync(FULL, o3[1], q4);
        const float gvv = selv == 0 ? x0 : selv == 1 ? x1 : selv == 2 ? x2 : x3;
        x0 = __shfl_sync(FULL, o0[0], q4 + 1);
        x1 = __shfl_sync(FULL, o2[0], q4 + 1);
        x2 = __shfl_sync(FULL, o0[1], q4 + 1);
        x3 = __shfl_sync(FULL, o2[1], q4 + 1);
        const float bv = selv == 0 ? x0 : selv == 1 ? x1 : selv == 2 ? x2 : x3;
        const float rr = 1.f / (1.f + __expf(-rv));
        const float rg = 1.f / (1.f + __expf(-gvv));
        const float rb = 1.f / (1.f + __expf(-bv));

        // ---------------- transmittance scan --------------------------------
        {
            const float ex = __expf(-sigma * dtv);      // one_minus
            const float alpha = 1.f - ex;
            float p = ex;
#pragma unroll
            for (int o = 1; o < 32; o <<= 1) {
                float q = __shfl_up_sync(FULL, p, o);
                if (lane >= o) p *= q;
            }
            float* red = (float*)(dsm + OFF_RED);
            if (lane == 31) red[w] = p;
            __syncthreads();
            float wpre = 1.f;
#pragma unroll
            for (int k = 0; k < 3; k++)
                if (k < w) wpre *= red[k];
            const float pm1 = __shfl_up_sync(FULL, p, 1);
            const float excl = (lane == 0) ? wpre : wpre * pm1;
            const bool active = excl > 1e-4f;
            const float wgt = active ? excl * alpha : 0.f;
            float sr = wgt * rr, sg2 = wgt * rg, sb = wgt * rb;
            float ft = active ? ex : 1.f;
#pragma unroll
            for (int o = 16; o > 0; o >>= 1) {
                sr += __shfl_xor_sync(FULL, sr, o);
                sg2 += __shfl_xor_sync(FULL, sg2, o);
                sb += __shfl_xor_sync(FULL, sb, o);
                ft *= __shfl_xor_sync(FULL, ft, o);
            }
            float* part = (float*)(dsm + OFF_PART) + w * 4;
            if (lane == 0) { part[0] = sr; part[1] = sg2; part[2] = sb; part[3] = ft; }
            __syncthreads();
            if (tid == 0) {
                const float* pp = (const float*)(dsm + OFF_PART);
                float R = 0, G = 0, B = 0, T = 1.f;
#pragma unroll
                for (int k = 0; k < 4; k++) {
                    R += pp[k * 4 + 0]; G += pp[k * 4 + 1];
                    B += pp[k * 4 + 2]; T *= pp[k * 4 + 3];
                }
                outp[ray * 3 + 0] = R;
                outp[ray * 3 + 1] = G;
                outp[ray * 3 + 2] = B;
                outp[3 * NR + ray] = T;
            }
            __syncthreads();
        }
    }
}

// ---------------------------------------------------------------------------
extern "C" void kernel_launch(void* const* d_in, const int* in_sizes, int n_in,
                              void* d_out, int out_size) {
    const float* orig = (const float*)d_in[0];
    const float* dirs = (const float*)d_in[1];
    const float* tmin = (const float*)d_in[2];
    const float* tmax = (const float*)d_in[3];
    const float* W1   = (const float*)d_in[4];
    const float* b1   = (const float*)d_in[5];
    const float* W2   = (const float*)d_in[6];
    const float* b2   = (const float*)d_in[7];
    const float* V1   = (const float*)d_in[8];
    const float* c1   = (const float*)d_in[9];
    const float* V2   = (const float*)d_in[10];
    const float* c2   = (const float*)d_in[11];

    cudaFuncSetAttribute(fused_kernel, cudaFuncAttributeMaxDynamicSharedMemorySize, SMEM_TOTAL);

    fused_kernel<<<GRIDF, THREADS, SMEM_TOTAL>>>(orig, dirs, tmin, tmax,
                                                 W1, b1, W2, b2, V1, c1, V2, c2,
                                                 (float*)d_out);
}

// round 10
// speedup vs baseline: 1.4748x; 1.4748x over previous
#include <cuda_runtime.h>
#include <cuda_bf16.h>
#include <math.h>

#define NR 8192
#define SS 128
#define GRIDF 592          // 4 CTAs/SM x 148 SMs
#define THREADS 128        // 4 warps = 1 ray per iteration

typedef unsigned int u32;

__device__ float g_base_arr[NR * 64];   // c1 + vd_enc @ V1[15:42]  (per ray)
__device__ float g_dt;

// ---------------- smem layout (bytes), per CTA ----------------
#define OFF_AH   0                 // 4 warps x 32 rows x 144B (bf16 hi only)
#define OFF_W1H  18432             // W1^T [64n][72 bf16 stride], K pad 64
#define OFF_W1L  27648
#define OFF_W2H  36864             // W2^T [16n][72]
#define OFF_W2L  39168
#define OFF_B3H  41472             // V1[0:15]^T shifted: [64n][20 bf16 stride], k0=0
#define OFF_B3L  44032
#define OFF_B4H  46592             // V2^T [8n][72], n>=3 zero
#define OFF_B4L  47744
#define OFF_B1   48896             // b1 (64 f32)
#define OFF_B2   49152             // b2 (16 f32)
#define OFF_C2   49216             // c2 (8 f32, padded)
#define OFF_RED  49248             // 4 warp products
#define OFF_PART 49280             // 4 warps x 4 floats
#define SMEM_TOTAL 49408

static __device__ __forceinline__ u32 pk2(__nv_bfloat16 a, __nv_bfloat16 b) {
    return (u32)__bfloat16_as_ushort(a) | ((u32)__bfloat16_as_ushort(b) << 16);
}
static __device__ __forceinline__ void split2(float x, float y, u32& hi, u32& lo) {
    __nv_bfloat16 hx = __float2bfloat16(x), hy = __float2bfloat16(y);
    hi = pk2(hx, hy);
    lo = pk2(__float2bfloat16(x - __bfloat162float(hx)),
             __float2bfloat16(y - __bfloat162float(hy)));
}
static __device__ __forceinline__ void mma4(float* d, const u32* a, u32 b0, u32 b1) {
    asm volatile(
        "mma.sync.aligned.m16n8k16.row.col.f32.bf16.bf16.f32 "
        "{%0,%1,%2,%3}, {%4,%5,%6,%7}, {%8,%9}, {%0,%1,%2,%3};"
        : "+f"(d[0]), "+f"(d[1]), "+f"(d[2]), "+f"(d[3])
        : "r"(a[0]), "r"(a[1]), "r"(a[2]), "r"(a[3]), "r"(b0), "r"(b1));
}

// ---------------------------------------------------------------------------
// dt = mean(tmax - tmin) / S
// ---------------------------------------------------------------------------
__global__ __launch_bounds__(1024)
void dt_kernel(const float* __restrict__ tmin, const float* __restrict__ tmax) {
    __shared__ float red[32];
    const int t = threadIdx.x;
    const float4* a = (const float4*)tmin;
    const float4* b = (const float4*)tmax;
    float s = 0.f;
    for (int i = t; i < NR / 4; i += 1024) {
        float4 x = a[i], y = b[i];
        s += (y.x - x.x) + (y.y - x.y) + (y.z - x.z) + (y.w - x.w);
    }
#pragma unroll
    for (int o = 16; o > 0; o >>= 1) s += __shfl_down_sync(0xffffffffu, s, o);
    if ((t & 31) == 0) red[t >> 5] = s;
    __syncthreads();
    if (t < 32) {
        float v = red[t];
#pragma unroll
        for (int o = 16; o > 0; o >>= 1) v += __shfl_down_sync(0xffffffffu, v, o);
        if (t == 0) g_dt = v / (float)(NR * SS);
    }
}

// ---------------------------------------------------------------------------
// Per-ray: g_base = c1 + vd_enc @ V1[15:42]
// ---------------------------------------------------------------------------
__global__ __launch_bounds__(128)
void ray_kernel(const float* __restrict__ dirs,
                const float* __restrict__ V1, const float* __restrict__ c1) {
    const int ray = blockIdx.x * 128 + threadIdx.x;
    if (ray >= NR) return;
    const float dx = dirs[ray * 3 + 0], dy = dirs[ray * 3 + 1], dz = dirs[ray * 3 + 2];
    const float nrm = sqrtf(dx * dx + dy * dy + dz * dz) + 1e-8f;
    const float inv = 1.0f / nrm;
    const float vx = dx * inv, vy = dy * inv, vz = dz * inv;

    float v[27];
    v[0] = vx; v[1] = vy; v[2] = vz;
    {
        float sx, cx, sy, cy, sz, cz;
        sincosf(vx, &sx, &cx); sincosf(vy, &sy, &cy); sincosf(vz, &sz, &cz);
#pragma unroll
        for (int i = 0; i < 4; i++) {
            v[3 + 6 * i + 0] = sx; v[3 + 6 * i + 1] = sy; v[3 + 6 * i + 2] = sz;
            v[3 + 6 * i + 3] = cx; v[3 + 6 * i + 4] = cy; v[3 + 6 * i + 5] = cz;
            const float nsx = 2.f * sx * cx, ncx = fmaf(-2.f * sx, sx, 1.f);
            const float nsy = 2.f * sy * cy, ncy = fmaf(-2.f * sy, sy, 1.f);
            const float nsz = 2.f * sz * cz, ncz = fmaf(-2.f * sz, sz, 1.f);
            sx = nsx; cx = ncx; sy = nsy; cy = ncy; sz = nsz; cz = ncz;
        }
    }
    float acc[64];
#pragma unroll
    for (int j = 0; j < 64; j++) acc[j] = c1[j];
#pragma unroll 1
    for (int i = 0; i < 27; i++) {
        const float vi = v[i];
        const float* w = V1 + (15 + i) * 64;
#pragma unroll
        for (int j = 0; j < 64; j++) acc[j] = fmaf(vi, w[j], acc[j]);
    }
#pragma unroll
    for (int j = 0; j < 64; j++) g_base_arr[ray * 64 + j] = acc[j];
}

// ---------------------------------------------------------------------------
// Fused ray-marcher: CTA = 128 threads = 4 warps = one ray per iteration.
// 4 CTAs/SM -> 4 warps/SMSP. MLP1 uses 2-pass split (A hi only).
// ---------------------------------------------------------------------------
__global__ __launch_bounds__(THREADS, 4)
void fused_kernel(const float* __restrict__ orig, const float* __restrict__ dirs,
                  const float* __restrict__ tmin, const float* __restrict__ tmax,
                  const float* __restrict__ W1, const float* __restrict__ b1,
                  const float* __restrict__ W2, const float* __restrict__ b2,
                  const float* __restrict__ V1, const float* __restrict__ V2,
                  const float* __restrict__ c2, float* __restrict__ outp) {
    extern __shared__ char dsm[];
    const int tid = threadIdx.x;
    const int w = tid >> 5, lane = tid & 31, g = lane >> 2, tig = lane & 3;

    // ---------------- stage weights: split bf16 hi/lo, K-major padded ------
    for (int i = tid; i < 64 * 64; i += THREADS) {            // W1^T, K pad 64
        int n = i >> 6, k = i & 63;
        float v = (k < 63) ? W1[k * 64 + n] : 0.f;
        __nv_bfloat16 h = __float2bfloat16(v);
        *(__nv_bfloat16*)(dsm + OFF_W1H + n * 144 + k * 2) = h;
        *(__nv_bfloat16*)(dsm + OFF_W1L + n * 144 + k * 2) =
            __float2bfloat16(v - __bfloat162float(h));
    }
    for (int i = tid; i < 16 * 64; i += THREADS) {            // W2^T
        int n = i >> 6, k = i & 63;
        float v = W2[k * 16 + n];
        __nv_bfloat16 h = __float2bfloat16(v);
        *(__nv_bfloat16*)(dsm + OFF_W2H + n * 144 + k * 2) = h;
        *(__nv_bfloat16*)(dsm + OFF_W2L + n * 144 + k * 2) =
            __float2bfloat16(v - __bfloat162float(h));
    }
    for (int i = tid; i < 64 * 16; i += THREADS) {            // B3 = shifted V1[0:15]^T
        int n = i >> 4, k = i & 15;
        float v = (k >= 1) ? V1[(k - 1) * 64 + n] : 0.f;
        __nv_bfloat16 h = __float2bfloat16(v);
        *(__nv_bfloat16*)(dsm + OFF_B3H + n * 40 + k * 2) = h;
        *(__nv_bfloat16*)(dsm + OFF_B3L + n * 40 + k * 2) =
            __float2bfloat16(v - __bfloat162float(h));
    }
    for (int i = tid; i < 8 * 64; i += THREADS) {             // B4 = V2^T, n pad 8
        int n = i >> 6, k = i & 63;
        float v = (n < 3) ? V2[k * 3 + n] : 0.f;
        __nv_bfloat16 h = __float2bfloat16(v);
        *(__nv_bfloat16*)(dsm + OFF_B4H + n * 144 + k * 2) = h;
        *(__nv_bfloat16*)(dsm + OFF_B4L + n * 144 + k * 2) =
            __float2bfloat16(v - __bfloat162float(h));
    }
    for (int i = tid; i < 64; i += THREADS) ((float*)(dsm + OFF_B1))[i] = b1[i];
    if (tid < 16) ((float*)(dsm + OFF_B2))[tid] = b2[tid];
    if (tid < 8)  ((float*)(dsm + OFF_C2))[tid] = (tid < 3) ? c2[tid] : 0.f;
    __syncthreads();

    const float dtv = g_dt;
    const u32 FULL = 0xffffffffu;

    for (int ray = blockIdx.x; ray < NR; ray += GRIDF) {
        const int s = (w << 5) + lane;

        // ---------------- positional encoding, row = lane -------------------
        const float dx = dirs[ray * 3 + 0], dy = dirs[ray * 3 + 1], dz = dirs[ray * 3 + 2];
        const float t0 = tmin[ray], t1 = tmax[ray];
        const float tt = t0 + (float)s * (1.0f / (SS - 1)) * (t1 - t0);
        float enc[64];
        enc[0] = fmaf(dx, tt, orig[ray * 3 + 0]);
        enc[1] = fmaf(dy, tt, orig[ray * 3 + 1]);
        enc[2] = fmaf(dz, tt, orig[ray * 3 + 2]);
        {
            float sx, cx, sy, cy, sz, cz;
            sincosf(enc[0], &sx, &cx); sincosf(enc[1], &sy, &cy); sincosf(enc[2], &sz, &cz);
#pragma unroll
            for (int i = 0; i < 10; i++) {
                enc[3 + 6 * i + 0] = sx; enc[3 + 6 * i + 1] = sy; enc[3 + 6 * i + 2] = sz;
                enc[3 + 6 * i + 3] = cx; enc[3 + 6 * i + 4] = cy; enc[3 + 6 * i + 5] = cz;
                const float nsx = 2.f * sx * cx, ncx = fmaf(-2.f * sx, sx, 1.f);
                const float nsy = 2.f * sy * cy, ncy = fmaf(-2.f * sy, sy, 1.f);
                const float nsz = 2.f * sz * cz, ncz = fmaf(-2.f * sz, sz, 1.f);
                sx = nsx; cx = ncx; sy = nsy; cy = ncy; sz = nsz; cz = ncz;
            }
        }
        enc[63] = 0.f;
        {
            char* Ah = dsm + OFF_AH + w * 4608 + lane * 144;
#pragma unroll
            for (int j8 = 0; j8 < 8; j8++) {
                u32 h0 = pk2(__float2bfloat16(enc[8 * j8 + 0]), __float2bfloat16(enc[8 * j8 + 1]));
                u32 h1 = pk2(__float2bfloat16(enc[8 * j8 + 2]), __float2bfloat16(enc[8 * j8 + 3]));
                u32 h2 = pk2(__float2bfloat16(enc[8 * j8 + 4]), __float2bfloat16(enc[8 * j8 + 5]));
                u32 h3 = pk2(__float2bfloat16(enc[8 * j8 + 6]), __float2bfloat16(enc[8 * j8 + 7]));
                *(uint4*)(Ah + j8 * 16) = make_uint4(h0, h1, h2, h3);
            }
        }
        __syncwarp();

        // ---------------- MLP1: enc(64) @ W1 -> 32x64 (2-pass split) --------
        float acc[2][8][4];
#pragma unroll
        for (int mt = 0; mt < 2; mt++)
#pragma unroll
            for (int nt = 0; nt < 8; nt++)
#pragma unroll
                for (int r = 0; r < 4; r++) acc[mt][nt][r] = 0.f;

        const char* AHb = dsm + OFF_AH + w * 4608;
#pragma unroll
        for (int kt = 0; kt < 4; kt++) {
            u32 AH[2][4];
#pragma unroll
            for (int mt = 0; mt < 2; mt++) {
                int ab = mt * 2304 + g * 144 + kt * 32 + tig * 4;
                AH[mt][0] = *(const u32*)(AHb + ab);
                AH[mt][1] = *(const u32*)(AHb + ab + 1152);
                AH[mt][2] = *(const u32*)(AHb + ab + 16);
                AH[mt][3] = *(const u32*)(AHb + ab + 1168);
            }
#pragma unroll
            for (int nt = 0; nt < 8; nt++) {
                int bo = (nt * 8 + g) * 144 + kt * 32 + tig * 4;
                u32 bh0 = *(const u32*)(dsm + OFF_W1H + bo);
                u32 bh1 = *(const u32*)(dsm + OFF_W1H + bo + 16);
                u32 bl0 = *(const u32*)(dsm + OFF_W1L + bo);
                u32 bl1 = *(const u32*)(dsm + OFF_W1L + bo + 16);
#pragma unroll
                for (int mt = 0; mt < 2; mt++) {
                    mma4(acc[mt][nt], AH[mt], bh0, bh1);
                    mma4(acc[mt][nt], AH[mt], bl0, bl1);
                }
            }
        }

        // ---------------- epi1: h = relu(D + b1) -> A frags (regs) ----------
        u32 HF[2][4][4], HL[2][4][4];
#pragma unroll
        for (int kt = 0; kt < 4; kt++)
#pragma unroll
            for (int j = 0; j < 2; j++) {
                const int nt = 2 * kt + j;
                const float2 bb = *(const float2*)(dsm + OFF_B1 + (nt * 8 + tig * 2) * 4);
#pragma unroll
                for (int mt = 0; mt < 2; mt++) {
                    float v0 = fmaxf(acc[mt][nt][0] + bb.x, 0.f);
                    float v1 = fmaxf(acc[mt][nt][1] + bb.y, 0.f);
                    float v2 = fmaxf(acc[mt][nt][2] + bb.x, 0.f);
                    float v3 = fmaxf(acc[mt][nt][3] + bb.y, 0.f);
                    split2(v0, v1, HF[mt][kt][2 * j + 0], HL[mt][kt][2 * j + 0]);
                    split2(v2, v3, HF[mt][kt][2 * j + 1], HL[mt][kt][2 * j + 1]);
                }
            }

        // ---------------- MLP2: h @ W2 -> 32x16 -----------------------------
        float a2c[2][2][4];
#pragma unroll
        for (int mt = 0; mt < 2; mt++)
#pragma unroll
            for (int n2 = 0; n2 < 2; n2++)
#pragma unroll
                for (int r = 0; r < 4; r++) a2c[mt][n2][r] = 0.f;
#pragma unroll
        for (int kt = 0; kt < 4; kt++)
#pragma unroll
            for (int n2 = 0; n2 < 2; n2++) {
                int bo = (n2 * 8 + g) * 144 + kt * 32 + tig * 4;
                u32 bh0 = *(const u32*)(dsm + OFF_W2H + bo);
                u32 bh1 = *(const u32*)(dsm + OFF_W2H + bo + 16);
                u32 bl0 = *(const u32*)(dsm + OFF_W2L + bo);
                u32 bl1 = *(const u32*)(dsm + OFF_W2L + bo + 16);
#pragma unroll
                for (int mt = 0; mt < 2; mt++) {
                    mma4(a2c[mt][n2], HF[mt][kt], bh0, bh1);
                    mma4(a2c[mt][n2], HF[mt][kt], bl0, bl1);
                    mma4(a2c[mt][n2], HL[mt][kt], bh0, bh1);
                }
            }

        // ---------------- epi2: sigma raw + feat frags ----------------------
        float sgm[2][2];
        u32 FF[2][4], FL[2][4];
        {
            const float2 b20 = *(const float2*)(dsm + OFF_B2 + tig * 8);
            const float2 b21 = *(const float2*)(dsm + OFF_B2 + 32 + tig * 8);
#pragma unroll
            for (int mt = 0; mt < 2; mt++) {
                float v0 = a2c[mt][0][0] + b20.x;
                float v1 = a2c[mt][0][1] + b20.y;
                float v2 = a2c[mt][0][2] + b20.x;
                float v3 = a2c[mt][0][3] + b20.y;
                float u0 = a2c[mt][1][0] + b21.x;
                float u1 = a2c[mt][1][1] + b21.y;
                float u2 = a2c[mt][1][2] + b21.x;
                float u3 = a2c[mt][1][3] + b21.y;
                sgm[mt][0] = v0;
                sgm[mt][1] = v2;
                split2(v0, v1, FF[mt][0], FL[mt][0]);
                split2(v2, v3, FF[mt][1], FL[mt][1]);
                split2(u0, u1, FF[mt][2], FL[mt][2]);
                split2(u2, u3, FF[mt][3], FL[mt][3]);
            }
        }

        // ---------------- MLP3: feats(16) @ B3 -> 32x64 ---------------------
        float a3c[2][8][4];
#pragma unroll
        for (int mt = 0; mt < 2; mt++)
#pragma unroll
            for (int nt = 0; nt < 8; nt++)
#pragma unroll
                for (int r = 0; r < 4; r++) a3c[mt][nt][r] = 0.f;
#pragma unroll
        for (int nt = 0; nt < 8; nt++) {
            int bo = (nt * 8 + g) * 40 + tig * 4;
            u32 bh0 = *(const u32*)(dsm + OFF_B3H + bo);
            u32 bh1 = *(const u32*)(dsm + OFF_B3H + bo + 16);
            u32 bl0 = *(const u32*)(dsm + OFF_B3L + bo);
            u32 bl1 = *(const u32*)(dsm + OFF_B3L + bo + 16);
#pragma unroll
            for (int mt = 0; mt < 2; mt++) {
                mma4(a3c[mt][nt], FF[mt], bh0, bh1);
                mma4(a3c[mt][nt], FF[mt], bl0, bl1);
                mma4(a3c[mt][nt], FL[mt], bh0, bh1);
            }
        }

        // ---------------- epi3: g = relu(D + g_base) -> g frags -------------
        u32 GF[2][4][4], GL[2][4][4];
        const float* gb = g_base_arr + ray * 64;
#pragma unroll
        for (int kt = 0; kt < 4; kt++)
#pragma unroll
            for (int j = 0; j < 2; j++) {
                const int nt = 2 * kt + j;
                const float2 gv = __ldg((const float2*)(gb + nt * 8 + tig * 2));
#pragma unroll
                for (int mt = 0; mt < 2; mt++) {
                    float v0 = fmaxf(a3c[mt][nt][0] + gv.x, 0.f);
                    float v1 = fmaxf(a3c[mt][nt][1] + gv.y, 0.f);
                    float v2 = fmaxf(a3c[mt][nt][2] + gv.x, 0.f);
                    float v3 = fmaxf(a3c[mt][nt][3] + gv.y, 0.f);
                    split2(v0, v1, GF[mt][kt][2 * j + 0], GL[mt][kt][2 * j + 0]);
                    split2(v2, v3, GF[mt][kt][2 * j + 1], GL[mt][kt][2 * j + 1]);
                }
            }

        // ---------------- MLP4: g @ V2 -> 32x8 ------------------------------
        float a4[2][4];
#pragma unroll
        for (int mt = 0; mt < 2; mt++)
#pragma unroll
            for (int r = 0; r < 4; r++) a4[mt][r] = 0.f;
#pragma unroll
        for (int kt = 0; kt < 4; kt++) {
            int bo = g * 144 + kt * 32 + tig * 4;
            u32 bh0 = *(const u32*)(dsm + OFF_B4H + bo);
            u32 bh1 = *(const u32*)(dsm + OFF_B4H + bo + 16);
            u32 bl0 = *(const u32*)(dsm + OFF_B4L + bo);
            u32 bl1 = *(const u32*)(dsm + OFF_B4L + bo + 16);
#pragma unroll
            for (int mt = 0; mt < 2; mt++) {
                mma4(a4[mt], GF[mt][kt], bh0, bh1);
                mma4(a4[mt], GF[mt][kt], bl0, bl1);
                mma4(a4[mt], GL[mt][kt], bh0, bh1);
            }
        }

        // ---------------- epi4 + redistribution lane<->row ------------------
        float o0[2], o1[2], o2[2], o3[2];
        {
            const float2 cc = *(const float2*)(dsm + OFF_C2 + tig * 8);
#pragma unroll
            for (int mt = 0; mt < 2; mt++) {
                o0[mt] = a4[mt][0] + cc.x;
                o1[mt] = a4[mt][1] + cc.y;
                o2[mt] = a4[mt][2] + cc.x;
                o3[mt] = a4[mt][3] + cc.y;
            }
        }
        const int q4 = (lane & 7) * 4;
        const int selv = lane >> 3;
        float x0, x1, x2, x3;
        x0 = __shfl_sync(FULL, sgm[0][0], q4);
        x1 = __shfl_sync(FULL, sgm[0][1], q4);
        x2 = __shfl_sync(FULL, sgm[1][0], q4);
        x3 = __shfl_sync(FULL, sgm[1][1], q4);
        const float sigma = fmaxf(selv == 0 ? x0 : selv == 1 ? x1 : selv == 2 ? x2 : x3, 0.f);
        x0 = __shfl_sync(FULL, o0[0], q4);
        x1 = __shfl_sync(FULL, o2[0], q4);
        x2 = __shfl_sync(FULL, o0[1], q4);
        x3 = __shfl_sync(FULL, o2[1], q4);
        const float rv = selv == 0 ? x0 : selv == 1 ? x1 : selv == 2 ? x2 : x3;
        x0 = __shfl_sync(FULL, o1[0], q4);
        x1 = __shfl_sync(FULL, o3[0], q4);
        x2 = __shfl_sync(FULL, o1[1], q4);
        x3 = __shfl_sync(FULL, o3[1], q4);
        const float gvv = selv == 0 ? x0 : selv == 1 ? x1 : selv == 2 ? x2 : x3;
        x0 = __shfl_sync(FULL, o0[0], q4 + 1);
        x1 = __shfl_sync(FULL, o2[0], q4 + 1);
        x2 = __shfl_sync(FULL, o0[1], q4 + 1);
        x3 = __shfl_sync(FULL, o2[1], q4 + 1);
        const float bv = selv == 0 ? x0 : selv == 1 ? x1 : selv == 2 ? x2 : x3;
        const float rr = 1.f / (1.f + __expf(-rv));
        const float rg = 1.f / (1.f + __expf(-gvv));
        const float rb = 1.f / (1.f + __expf(-bv));

        // ---------------- transmittance scan --------------------------------
        {
            const float ex = __expf(-sigma * dtv);      // one_minus
            const float alpha = 1.f - ex;
            float p = ex;
#pragma unroll
            for (int o = 1; o < 32; o <<= 1) {
                float q = __shfl_up_sync(FULL, p, o);
                if (lane >= o) p *= q;
            }
            float* red = (float*)(dsm + OFF_RED);
            if (lane == 31) red[w] = p;
            __syncthreads();
            float wpre = 1.f;
#pragma unroll
            for (int k = 0; k < 3; k++)
                if (k < w) wpre *= red[k];
            const float pm1 = __shfl_up_sync(FULL, p, 1);
            const float excl = (lane == 0) ? wpre : wpre * pm1;
            const bool active = excl > 1e-4f;
            const float wgt = active ? excl * alpha : 0.f;
            float sr = wgt * rr, sg2 = wgt * rg, sb = wgt * rb;
            float ft = active ? ex : 1.f;
#pragma unroll
            for (int o = 16; o > 0; o >>= 1) {
                sr += __shfl_xor_sync(FULL, sr, o);
                sg2 += __shfl_xor_sync(FULL, sg2, o);
                sb += __shfl_xor_sync(FULL, sb, o);
                ft *= __shfl_xor_sync(FULL, ft, o);
            }
            float* part = (float*)(dsm + OFF_PART) + w * 4;
            if (lane == 0) { part[0] = sr; part[1] = sg2; part[2] = sb; part[3] = ft; }
            __syncthreads();
            if (tid == 0) {
                const float* pp = (const float*)(dsm + OFF_PART);
                float R = 0, G = 0, B = 0, T = 1.f;
#pragma unroll
                for (int k = 0; k < 4; k++) {
                    R += pp[k * 4 + 0]; G += pp[k * 4 + 1];
                    B += pp[k * 4 + 2]; T *= pp[k * 4 + 3];
                }
                outp[ray * 3 + 0] = R;
                outp[ray * 3 + 1] = G;
                outp[ray * 3 + 2] = B;
                outp[3 * NR + ray] = T;
            }
            __syncthreads();
        }
    }
}

// ---------------------------------------------------------------------------
extern "C" void kernel_launch(void* const* d_in, const int* in_sizes, int n_in,
                              void* d_out, int out_size) {
    const float* orig = (const float*)d_in[0];
    const float* dirs = (const float*)d_in[1];
    const float* tmin = (const float*)d_in[2];
    const float* tmax = (const float*)d_in[3];
    const float* W1   = (const float*)d_in[4];
    const float* b1   = (const float*)d_in[5];
    const float* W2   = (const float*)d_in[6];
    const float* b2   = (const float*)d_in[7];
    const float* V1   = (const float*)d_in[8];
    const float* c1   = (const float*)d_in[9];
    const float* V2   = (const float*)d_in[10];
    const float* c2   = (const float*)d_in[11];

    cudaFuncSetAttribute(fused_kernel, cudaFuncAttributeMaxDynamicSharedMemorySize, SMEM_TOTAL);

    dt_kernel<<<1, 1024>>>(tmin, tmax);
    ray_kernel<<<NR / 128, 128>>>(dirs, V1, c1);
    fused_kernel<<<GRIDF, THREADS, SMEM_TOTAL>>>(orig, dirs, tmin, tmax,
                                                 W1, b1, W2, b2, V1, V2, c2,
                                                 (float*)d_out);
}

// round 11
// speedup vs baseline: 2.0562x; 1.3942x over previous
#include <cuda_runtime.h>
#include <cuda_bf16.h>
#include <math.h>

#define NR 8192
#define SS 128
#define GRIDF 592          // 4 CTAs/SM x 148 SMs
#define THREADS 128        // 4 warps = 1 ray per iteration

typedef unsigned int u32;

__device__ float g_base_arr[NR * 64];   // c1 + vd_enc @ V1[15:42]  (per ray)
__device__ float g_dt;

// ---------------- smem layout (bytes), per CTA ----------------
#define OFF_AH   0                 // 4 warps x 32 rows x 144B (bf16 hi only)
#define OFF_W1H  18432             // W1^T [64n][72 bf16 stride], K pad 64
#define OFF_W1L  27648
#define OFF_W2H  36864             // W2^T [16n][72]
#define OFF_W2L  39168
#define OFF_B3H  41472             // V1[0:15]^T shifted: [64n][20 bf16 stride], k0=0
#define OFF_B3L  44032
#define OFF_B4H  46592             // V2^T [8n][72], n>=3 zero
#define OFF_B4L  47744
#define OFF_B1   48896             // b1 (64 f32)
#define OFF_B2   49152             // b2 (16 f32)
#define OFF_C2   49216             // c2 (8 f32, padded)
#define OFF_RED  49248             // 4 warp products
#define OFF_PART 49280             // 4 warps x 4 floats
#define SMEM_TOTAL 49408

static __device__ __forceinline__ u32 pk2(__nv_bfloat16 a, __nv_bfloat16 b) {
    return (u32)__bfloat16_as_ushort(a) | ((u32)__bfloat16_as_ushort(b) << 16);
}
// pack 2 floats -> bf16x2 in ONE instruction (low = x, high = y)
static __device__ __forceinline__ u32 pkbf2(float x, float y) {
    u32 r;
    asm("cvt.rn.satfinite.bf16x2.f32 %0, %1, %2;" : "=r"(r) : "f"(y), "f"(x));
    return r;
}
static __device__ __forceinline__ void mma4(float* d, const u32* a, u32 b0, u32 b1) {
    asm volatile(
        "mma.sync.aligned.m16n8k16.row.col.f32.bf16.bf16.f32 "
        "{%0,%1,%2,%3}, {%4,%5,%6,%7}, {%8,%9}, {%0,%1,%2,%3};"
        : "+f"(d[0]), "+f"(d[1]), "+f"(d[2]), "+f"(d[3])
        : "r"(a[0]), "r"(a[1]), "r"(a[2]), "r"(a[3]), "r"(b0), "r"(b1));
}

// ---------------------------------------------------------------------------
// dt = mean(tmax - tmin) / S
// ---------------------------------------------------------------------------
__global__ __launch_bounds__(1024)
void dt_kernel(const float* __restrict__ tmin, const float* __restrict__ tmax) {
    __shared__ float red[32];
    const int t = threadIdx.x;
    const float4* a = (const float4*)tmin;
    const float4* b = (const float4*)tmax;
    float s = 0.f;
    for (int i = t; i < NR / 4; i += 1024) {
        float4 x = a[i], y = b[i];
        s += (y.x - x.x) + (y.y - x.y) + (y.z - x.z) + (y.w - x.w);
    }
#pragma unroll
    for (int o = 16; o > 0; o >>= 1) s += __shfl_down_sync(0xffffffffu, s, o);
    if ((t & 31) == 0) red[t >> 5] = s;
    __syncthreads();
    if (t < 32) {
        float v = red[t];
#pragma unroll
        for (int o = 16; o > 0; o >>= 1) v += __shfl_down_sync(0xffffffffu, v, o);
        if (t == 0) g_dt = v / (float)(NR * SS);
    }
}

// ---------------------------------------------------------------------------
// Per-ray: g_base = c1 + vd_enc @ V1[15:42]   (accurate path)
// ---------------------------------------------------------------------------
__global__ __launch_bounds__(128)
void ray_kernel(const float* __restrict__ dirs,
                const float* __restrict__ V1, const float* __restrict__ c1) {
    const int ray = blockIdx.x * 128 + threadIdx.x;
    if (ray >= NR) return;
    const float dx = dirs[ray * 3 + 0], dy = dirs[ray * 3 + 1], dz = dirs[ray * 3 + 2];
    const float nrm = sqrtf(dx * dx + dy * dy + dz * dz) + 1e-8f;
    const float inv = 1.0f / nrm;
    const float vx = dx * inv, vy = dy * inv, vz = dz * inv;

    float v[27];
    v[0] = vx; v[1] = vy; v[2] = vz;
    {
        float sx, cx, sy, cy, sz, cz;
        sincosf(vx, &sx, &cx); sincosf(vy, &sy, &cy); sincosf(vz, &sz, &cz);
#pragma unroll
        for (int i = 0; i < 4; i++) {
            v[3 + 6 * i + 0] = sx; v[3 + 6 * i + 1] = sy; v[3 + 6 * i + 2] = sz;
            v[3 + 6 * i + 3] = cx; v[3 + 6 * i + 4] = cy; v[3 + 6 * i + 5] = cz;
            const float nsx = 2.f * sx * cx, ncx = fmaf(-2.f * sx, sx, 1.f);
            const float nsy = 2.f * sy * cy, ncy = fmaf(-2.f * sy, sy, 1.f);
            const float nsz = 2.f * sz * cz, ncz = fmaf(-2.f * sz, sz, 1.f);
            sx = nsx; cx = ncx; sy = nsy; cy = ncy; sz = nsz; cz = ncz;
        }
    }
    float acc[64];
#pragma unroll
    for (int j = 0; j < 64; j++) acc[j] = c1[j];
#pragma unroll 1
    for (int i = 0; i < 27; i++) {
        const float vi = v[i];
        const float* w = V1 + (15 + i) * 64;
#pragma unroll
        for (int j = 0; j < 64; j++) acc[j] = fmaf(vi, w[j], acc[j]);
    }
#pragma unroll
    for (int j = 0; j < 64; j++) g_base_arr[ray * 64 + j] = acc[j];
}

// ---------------------------------------------------------------------------
// Fused ray-marcher: CTA = 128 threads = 4 warps = one ray per iteration.
// All layers 2-pass split: A_hi x (B_hi + B_lo). Activations bf16-hi only.
// ---------------------------------------------------------------------------
__global__ __launch_bounds__(THREADS, 4)
void fused_kernel(const float* __restrict__ orig, const float* __restrict__ dirs,
                  const float* __restrict__ tmin, const float* __restrict__ tmax,
                  const float* __restrict__ W1, const float* __restrict__ b1,
                  const float* __restrict__ W2, const float* __restrict__ b2,
                  const float* __restrict__ V1, const float* __restrict__ V2,
                  const float* __restrict__ c2, float* __restrict__ outp) {
    extern __shared__ char dsm[];
    const int tid = threadIdx.x;
    const int w = tid >> 5, lane = tid & 31, g = lane >> 2, tig = lane & 3;

    // ---------------- stage weights: split bf16 hi/lo, K-major padded ------
    for (int i = tid; i < 64 * 64; i += THREADS) {            // W1^T, K pad 64
        int n = i >> 6, k = i & 63;
        float v = (k < 63) ? W1[k * 64 + n] : 0.f;
        __nv_bfloat16 h = __float2bfloat16(v);
        *(__nv_bfloat16*)(dsm + OFF_W1H + n * 144 + k * 2) = h;
        *(__nv_bfloat16*)(dsm + OFF_W1L + n * 144 + k * 2) =
            __float2bfloat16(v - __bfloat162float(h));
    }
    for (int i = tid; i < 16 * 64; i += THREADS) {            // W2^T
        int n = i >> 6, k = i & 63;
        float v = W2[k * 16 + n];
        __nv_bfloat16 h = __float2bfloat16(v);
        *(__nv_bfloat16*)(dsm + OFF_W2H + n * 144 + k * 2) = h;
        *(__nv_bfloat16*)(dsm + OFF_W2L + n * 144 + k * 2) =
            __float2bfloat16(v - __bfloat162float(h));
    }
    for (int i = tid; i < 64 * 16; i += THREADS) {            // B3 = shifted V1[0:15]^T
        int n = i >> 4, k = i & 15;
        float v = (k >= 1) ? V1[(k - 1) * 64 + n] : 0.f;
        __nv_bfloat16 h = __float2bfloat16(v);
        *(__nv_bfloat16*)(dsm + OFF_B3H + n * 40 + k * 2) = h;
        *(__nv_bfloat16*)(dsm + OFF_B3L + n * 40 + k * 2) =
            __float2bfloat16(v - __bfloat162float(h));
    }
    for (int i = tid; i < 8 * 64; i += THREADS) {             // B4 = V2^T, n pad 8
        int n = i >> 6, k = i & 63;
        float v = (n < 3) ? V2[k * 3 + n] : 0.f;
        __nv_bfloat16 h = __float2bfloat16(v);
        *(__nv_bfloat16*)(dsm + OFF_B4H + n * 144 + k * 2) = h;
        *(__nv_bfloat16*)(dsm + OFF_B4L + n * 144 + k * 2) =
            __float2bfloat16(v - __bfloat162float(h));
    }
    for (int i = tid; i < 64; i += THREADS) ((float*)(dsm + OFF_B1))[i] = b1[i];
    if (tid < 16) ((float*)(dsm + OFF_B2))[tid] = b2[tid];
    if (tid < 8)  ((float*)(dsm + OFF_C2))[tid] = (tid < 3) ? c2[tid] : 0.f;
    __syncthreads();

    const float dtv = g_dt;
    const u32 FULL = 0xffffffffu;

    for (int ray = blockIdx.x; ray < NR; ray += GRIDF) {
        const int s = (w << 5) + lane;

        // ---------------- positional encoding (fast sincos), row = lane -----
        const float dx = dirs[ray * 3 + 0], dy = dirs[ray * 3 + 1], dz = dirs[ray * 3 + 2];
        const float t0 = tmin[ray], t1 = tmax[ray];
        const float tt = t0 + (float)s * (1.0f / (SS - 1)) * (t1 - t0);
        float enc[64];
        enc[0] = fmaf(dx, tt, orig[ray * 3 + 0]);
        enc[1] = fmaf(dy, tt, orig[ray * 3 + 1]);
        enc[2] = fmaf(dz, tt, orig[ray * 3 + 2]);
        {
            float sx, cx, sy, cy, sz, cz;
            __sincosf(enc[0], &sx, &cx);
            __sincosf(enc[1], &sy, &cy);
            __sincosf(enc[2], &sz, &cz);
#pragma unroll
            for (int i = 0; i < 10; i++) {
                enc[3 + 6 * i + 0] = sx; enc[3 + 6 * i + 1] = sy; enc[3 + 6 * i + 2] = sz;
                enc[3 + 6 * i + 3] = cx; enc[3 + 6 * i + 4] = cy; enc[3 + 6 * i + 5] = cz;
                const float nsx = 2.f * sx * cx, ncx = fmaf(-2.f * sx, sx, 1.f);
                const float nsy = 2.f * sy * cy, ncy = fmaf(-2.f * sy, sy, 1.f);
                const float nsz = 2.f * sz * cz, ncz = fmaf(-2.f * sz, sz, 1.f);
                sx = nsx; cx = ncx; sy = nsy; cy = ncy; sz = nsz; cz = ncz;
            }
        }
        enc[63] = 0.f;
        {
            char* Ah = dsm + OFF_AH + w * 4608 + lane * 144;
#pragma unroll
            for (int j8 = 0; j8 < 8; j8++) {
                *(uint4*)(Ah + j8 * 16) = make_uint4(
                    pkbf2(enc[8 * j8 + 0], enc[8 * j8 + 1]),
                    pkbf2(enc[8 * j8 + 2], enc[8 * j8 + 3]),
                    pkbf2(enc[8 * j8 + 4], enc[8 * j8 + 5]),
                    pkbf2(enc[8 * j8 + 6], enc[8 * j8 + 7]));
            }
        }
        __syncwarp();

        // ---------------- MLP1: enc(64) @ W1 -> 32x64 (2-pass) --------------
        float acc[2][8][4];
#pragma unroll
        for (int mt = 0; mt < 2; mt++)
#pragma unroll
            for (int nt = 0; nt < 8; nt++)
#pragma unroll
                for (int r = 0; r < 4; r++) acc[mt][nt][r] = 0.f;

        const char* AHb = dsm + OFF_AH + w * 4608;
#pragma unroll
        for (int kt = 0; kt < 4; kt++) {
            u32 AH[2][4];
#pragma unroll
            for (int mt = 0; mt < 2; mt++) {
                int ab = mt * 2304 + g * 144 + kt * 32 + tig * 4;
                AH[mt][0] = *(const u32*)(AHb + ab);
                AH[mt][1] = *(const u32*)(AHb + ab + 1152);
                AH[mt][2] = *(const u32*)(AHb + ab + 16);
                AH[mt][3] = *(const u32*)(AHb + ab + 1168);
            }
#pragma unroll
            for (int nt = 0; nt < 8; nt++) {
                int bo = (nt * 8 + g) * 144 + kt * 32 + tig * 4;
                u32 bh0 = *(const u32*)(dsm + OFF_W1H + bo);
                u32 bh1 = *(const u32*)(dsm + OFF_W1H + bo + 16);
                u32 bl0 = *(const u32*)(dsm + OFF_W1L + bo);
                u32 bl1 = *(const u32*)(dsm + OFF_W1L + bo + 16);
#pragma unroll
                for (int mt = 0; mt < 2; mt++) {
                    mma4(acc[mt][nt], AH[mt], bh0, bh1);
                    mma4(acc[mt][nt], AH[mt], bl0, bl1);
                }
            }
        }

        // ---------------- epi1: h = relu(D + b1) -> hi frags only -----------
        u32 HF[2][4][4];
#pragma unroll
        for (int kt = 0; kt < 4; kt++)
#pragma unroll
            for (int j = 0; j < 2; j++) {
                const int nt = 2 * kt + j;
                const float2 bb = *(const float2*)(dsm + OFF_B1 + (nt * 8 + tig * 2) * 4);
#pragma unroll
                for (int mt = 0; mt < 2; mt++) {
                    float v0 = fmaxf(acc[mt][nt][0] + bb.x, 0.f);
                    float v1 = fmaxf(acc[mt][nt][1] + bb.y, 0.f);
                    float v2 = fmaxf(acc[mt][nt][2] + bb.x, 0.f);
                    float v3 = fmaxf(acc[mt][nt][3] + bb.y, 0.f);
                    HF[mt][kt][2 * j + 0] = pkbf2(v0, v1);
                    HF[mt][kt][2 * j + 1] = pkbf2(v2, v3);
                }
            }

        // ---------------- MLP2: h @ W2 -> 32x16 (2-pass) --------------------
        float a2c[2][2][4];
#pragma unroll
        for (int mt = 0; mt < 2; mt++)
#pragma unroll
            for (int n2 = 0; n2 < 2; n2++)
#pragma unroll
                for (int r = 0; r < 4; r++) a2c[mt][n2][r] = 0.f;
#pragma unroll
        for (int kt = 0; kt < 4; kt++)
#pragma unroll
            for (int n2 = 0; n2 < 2; n2++) {
                int bo = (n2 * 8 + g) * 144 + kt * 32 + tig * 4;
                u32 bh0 = *(const u32*)(dsm + OFF_W2H + bo);
                u32 bh1 = *(const u32*)(dsm + OFF_W2H + bo + 16);
                u32 bl0 = *(const u32*)(dsm + OFF_W2L + bo);
                u32 bl1 = *(const u32*)(dsm + OFF_W2L + bo + 16);
#pragma unroll
                for (int mt = 0; mt < 2; mt++) {
                    mma4(a2c[mt][n2], HF[mt][kt], bh0, bh1);
                    mma4(a2c[mt][n2], HF[mt][kt], bl0, bl1);
                }
            }

        // ---------------- epi2: sigma raw + feat hi frags -------------------
        float sgm[2][2];
        u32 FF[2][4];
        {
            const float2 b20 = *(const float2*)(dsm + OFF_B2 + tig * 8);
            const float2 b21 = *(const float2*)(dsm + OFF_B2 + 32 + tig * 8);
#pragma unroll
            for (int mt = 0; mt < 2; mt++) {
                float v0 = a2c[mt][0][0] + b20.x;
                float v1 = a2c[mt][0][1] + b20.y;
                float v2 = a2c[mt][0][2] + b20.x;
                float v3 = a2c[mt][0][3] + b20.y;
                float u0 = a2c[mt][1][0] + b21.x;
                float u1 = a2c[mt][1][1] + b21.y;
                float u2 = a2c[mt][1][2] + b21.x;
                float u3 = a2c[mt][1][3] + b21.y;
                sgm[mt][0] = v0;
                sgm[mt][1] = v2;
                FF[mt][0] = pkbf2(v0, v1);
                FF[mt][1] = pkbf2(v2, v3);
                FF[mt][2] = pkbf2(u0, u1);
                FF[mt][3] = pkbf2(u2, u3);
            }
        }

        // ---------------- MLP3: feats(16) @ B3 -> 32x64 (2-pass) ------------
        float a3c[2][8][4];
#pragma unroll
        for (int mt = 0; mt < 2; mt++)
#pragma unroll
            for (int nt = 0; nt < 8; nt++)
#pragma unroll
                for (int r = 0; r < 4; r++) a3c[mt][nt][r] = 0.f;
#pragma unroll
        for (int nt = 0; nt < 8; nt++) {
            int bo = (nt * 8 + g) * 40 + tig * 4;
            u32 bh0 = *(const u32*)(dsm + OFF_B3H + bo);
            u32 bh1 = *(const u32*)(dsm + OFF_B3H + bo + 16);
            u32 bl0 = *(const u32*)(dsm + OFF_B3L + bo);
            u32 bl1 = *(const u32*)(dsm + OFF_B3L + bo + 16);
#pragma unroll
            for (int mt = 0; mt < 2; mt++) {
                mma4(a3c[mt][nt], FF[mt], bh0, bh1);
                mma4(a3c[mt][nt], FF[mt], bl0, bl1);
            }
        }

        // ---------------- epi3: g = relu(D + g_base) -> hi frags ------------
        u32 GF[2][4][4];
        const float* gb = g_base_arr + ray * 64;
#pragma unroll
        for (int kt = 0; kt < 4; kt++)
#pragma unroll
            for (int j = 0; j < 2; j++) {
                const int nt = 2 * kt + j;
                const float2 gv = __ldg((const float2*)(gb + nt * 8 + tig * 2));
#pragma unroll
                for (int mt = 0; mt < 2; mt++) {
                    float v0 = fmaxf(a3c[mt][nt][0] + gv.x, 0.f);
                    float v1 = fmaxf(a3c[mt][nt][1] + gv.y, 0.f);
                    float v2 = fmaxf(a3c[mt][nt][2] + gv.x, 0.f);
                    float v3 = fmaxf(a3c[mt][nt][3] + gv.y, 0.f);
                    GF[mt][kt][2 * j + 0] = pkbf2(v0, v1);
                    GF[mt][kt][2 * j + 1] = pkbf2(v2, v3);
                }
            }

        // ---------------- MLP4: g @ V2 -> 32x8 (2-pass) ---------------------
        float a4[2][4];
#pragma unroll
        for (int mt = 0; mt < 2; mt++)
#pragma unroll
            for (int r = 0; r < 4; r++) a4[mt][r] = 0.f;
#pragma unroll
        for (int kt = 0; kt < 4; kt++) {
            int bo = g * 144 + kt * 32 + tig * 4;
            u32 bh0 = *(const u32*)(dsm + OFF_B4H + bo);
            u32 bh1 = *(const u32*)(dsm + OFF_B4H + bo + 16);
            u32 bl0 = *(const u32*)(dsm + OFF_B4L + bo);
            u32 bl1 = *(const u32*)(dsm + OFF_B4L + bo + 16);
#pragma unroll
            for (int mt = 0; mt < 2; mt++) {
                mma4(a4[mt], GF[mt][kt], bh0, bh1);
                mma4(a4[mt], GF[mt][kt], bl0, bl1);
            }
        }

        // ---------------- epi4 + redistribution lane<->row ------------------
        float o0[2], o1[2], o2[2], o3[2];
        {
            const float2 cc = *(const float2*)(dsm + OFF_C2 + tig * 8);
#pragma unroll
            for (int mt = 0; mt < 2; mt++) {
                o0[mt] = a4[mt][0] + cc.x;
                o1[mt] = a4[mt][1] + cc.y;
                o2[mt] = a4[mt][2] + cc.x;
                o3[mt] = a4[mt][3] + cc.y;
            }
        }
        const int q4 = (lane & 7) * 4;
        const int selv = lane >> 3;
        float x0, x1, x2, x3;
        x0 = __shfl_sync(FULL, sgm[0][0], q4);
        x1 = __shfl_sync(FULL, sgm[0][1], q4);
        x2 = __shfl_sync(FULL, sgm[1][0], q4);
        x3 = __shfl_sync(FULL, sgm[1][1], q4);
        const float sigma = fmaxf(selv == 0 ? x0 : selv == 1 ? x1 : selv == 2 ? x2 : x3, 0.f);
        x0 = __shfl_sync(FULL, o0[0], q4);
        x1 = __shfl_sync(FULL, o2[0], q4);
        x2 = __shfl_sync(FULL, o0[1], q4);
        x3 = __shfl_sync(FULL, o2[1], q4);
        const float rv = selv == 0 ? x0 : selv == 1 ? x1 : selv == 2 ? x2 : x3;
        x0 = __shfl_sync(FULL, o1[0], q4);
        x1 = __shfl_sync(FULL, o3[0], q4);
        x2 = __shfl_sync(FULL, o1[1], q4);
        x3 = __shfl_sync(FULL, o3[1], q4);
        const float gvv = selv == 0 ? x0 : selv == 1 ? x1 : selv == 2 ? x2 : x3;
        x0 = __shfl_sync(FULL, o0[0], q4 + 1);
        x1 = __shfl_sync(FULL, o2[0], q4 + 1);
        x2 = __shfl_sync(FULL, o0[1], q4 + 1);
        x3 = __shfl_sync(FULL, o2[1], q4 + 1);
        const float bv = selv == 0 ? x0 : selv == 1 ? x1 : selv == 2 ? x2 : x3;
        const float rr = 1.f / (1.f + __expf(-rv));
        const float rg = 1.f / (1.f + __expf(-gvv));
        const float rb = 1.f / (1.f + __expf(-bv));

        // ---------------- transmittance scan --------------------------------
        {
            const float ex = __expf(-sigma * dtv);      // one_minus
            const float alpha = 1.f - ex;
            float p = ex;
#pragma unroll
            for (int o = 1; o < 32; o <<= 1) {
                float q = __shfl_up_sync(FULL, p, o);
                if (lane >= o) p *= q;
            }
            float* red = (float*)(dsm + OFF_RED);
            if (lane == 31) red[w] = p;
            __syncthreads();
            float wpre = 1.f;
#pragma unroll
            for (int k = 0; k < 3; k++)
                if (k < w) wpre *= red[k];
            const float pm1 = __shfl_up_sync(FULL, p, 1);
            const float excl = (lane == 0) ? wpre : wpre * pm1;
            const bool active = excl > 1e-4f;
            const float wgt = active ? excl * alpha : 0.f;
            float sr = wgt * rr, sg2 = wgt * rg, sb = wgt * rb;
            float ft = active ? ex : 1.f;
#pragma unroll
            for (int o = 16; o > 0; o >>= 1) {
                sr += __shfl_xor_sync(FULL, sr, o);
                sg2 += __shfl_xor_sync(FULL, sg2, o);
                sb += __shfl_xor_sync(FULL, sb, o);
                ft *= __shfl_xor_sync(FULL, ft, o);
            }
            float* part = (float*)(dsm + OFF_PART) + w * 4;
            if (lane == 0) { part[0] = sr; part[1] = sg2; part[2] = sb; part[3] = ft; }
            __syncthreads();
            if (tid == 0) {
                const float* pp = (const float*)(dsm + OFF_PART);
                float R = 0, G = 0, B = 0, T = 1.f;
#pragma unroll
                for (int k = 0; k < 4; k++) {
                    R += pp[k * 4 + 0]; G += pp[k * 4 + 1];
                    B += pp[k * 4 + 2]; T *= pp[k * 4 + 3];
                }
                outp[ray * 3 + 0] = R;
                outp[ray * 3 + 1] = G;
                outp[ray * 3 + 2] = B;
                outp[3 * NR + ray] = T;
            }
            __syncthreads();
        }
    }
}

// ---------------------------------------------------------------------------
extern "C" void kernel_launch(void* const* d_in, const int* in_sizes, int n_in,
                              void* d_out, int out_size) {
    const float* orig = (const float*)d_in[0];
    const float* dirs = (const float*)d_in[1];
    const float* tmin = (const float*)d_in[2];
    const float* tmax = (const float*)d_in[3];
    const float* W1   = (const float*)d_in[4];
    const float* b1   = (const float*)d_in[5];
    const float* W2   = (const float*)d_in[6];
    const float* b2   = (const float*)d_in[7];
    const float* V1   = (const float*)d_in[8];
    const float* c1   = (const float*)d_in[9];
    const float* V2   = (const float*)d_in[10];
    const float* c2   = (const float*)d_in[11];

    cudaFuncSetAttribute(fused_kernel, cudaFuncAttributeMaxDynamicSharedMemorySize, SMEM_TOTAL);

    dt_kernel<<<1, 1024>>>(tmin, tmax);
    ray_kernel<<<NR / 128, 128>>>(dirs, V1, c1);
    fused_kernel<<<GRIDF, THREADS, SMEM_TOTAL>>>(orig, dirs, tmin, tmax,
                                                 W1, b1, W2, b2, V1, V2, c2,
                                                 (float*)d_out);
}

// round 12
// speedup vs baseline: 2.0848x; 1.0139x over previous
#include <cuda_runtime.h>
#include <cuda_bf16.h>
#include <math.h>

#define NR 8192
#define SS 128
#define GRIDF 592          // 4 CTAs/SM x 148 SMs
#define THREADS 128        // 4 warps = 1 ray per iteration

typedef unsigned int u32;

__device__ float g_base_arr[NR * 64];   // c1 + vd_enc @ V1[15:42]  (per ray)

// ---------------- smem layout (bytes), per CTA ----------------
#define OFF_AH   0                 // 4 warps x 32 rows x 144B (bf16 hi only)
#define OFF_W1H  18432             // W1^T [64n][72 bf16 stride], K row63 = b1
#define OFF_W1L  27648
#define OFF_W2H  36864             // W2^T [16n][72]
#define OFF_W2L  39168
#define OFF_B3H  41472             // V1[0:15]^T shifted: [64n][20 bf16 stride], k0=0
#define OFF_B3L  44032
#define OFF_B4H  46592             // V2^T [8n][72], n>=3 zero
#define OFF_B4L  47744
#define OFF_B2   48896             // b2 (16 f32)
#define OFF_C2   48960             // c2 (8 f32, padded)
#define OFF_RED  48992             // 4 warp products
#define OFF_PART 49024             // 4 warps x 4 floats
#define SMEM_TOTAL 49152

// pack 2 floats -> bf16x2 in ONE instruction (low = x, high = y)
static __device__ __forceinline__ u32 pkbf2(float x, float y) {
    u32 r;
    asm("cvt.rn.satfinite.bf16x2.f32 %0, %1, %2;" : "=r"(r) : "f"(y), "f"(x));
    return r;
}
static __device__ __forceinline__ void mma4(float* d, const u32* a, u32 b0, u32 b1) {
    asm volatile(
        "mma.sync.aligned.m16n8k16.row.col.f32.bf16.bf16.f32 "
        "{%0,%1,%2,%3}, {%4,%5,%6,%7}, {%8,%9}, {%0,%1,%2,%3};"
        : "+f"(d[0]), "+f"(d[1]), "+f"(d[2]), "+f"(d[3])
        : "r"(a[0]), "r"(a[1]), "r"(a[2]), "r"(a[3]), "r"(b0), "r"(b1));
}

// ---------------------------------------------------------------------------
// Per-ray: g_base = c1 + vd_enc @ V1[15:42]   (accurate path)
// ---------------------------------------------------------------------------
__global__ __launch_bounds__(128)
void ray_kernel(const float* __restrict__ dirs,
                const float* __restrict__ V1, const float* __restrict__ c1) {
    const int ray = blockIdx.x * 128 + threadIdx.x;
    if (ray >= NR) return;
    const float dx = dirs[ray * 3 + 0], dy = dirs[ray * 3 + 1], dz = dirs[ray * 3 + 2];
    const float nrm = sqrtf(dx * dx + dy * dy + dz * dz) + 1e-8f;
    const float inv = 1.0f / nrm;
    const float vx = dx * inv, vy = dy * inv, vz = dz * inv;

    float v[27];
    v[0] = vx; v[1] = vy; v[2] = vz;
    {
        float sx, cx, sy, cy, sz, cz;
        sincosf(vx, &sx, &cx); sincosf(vy, &sy, &cy); sincosf(vz, &sz, &cz);
#pragma unroll
        for (int i = 0; i < 4; i++) {
            v[3 + 6 * i + 0] = sx; v[3 + 6 * i + 1] = sy; v[3 + 6 * i + 2] = sz;
            v[3 + 6 * i + 3] = cx; v[3 + 6 * i + 4] = cy; v[3 + 6 * i + 5] = cz;
            const float nsx = 2.f * sx * cx, ncx = fmaf(-2.f * sx, sx, 1.f);
            const float nsy = 2.f * sy * cy, ncy = fmaf(-2.f * sy, sy, 1.f);
            const float nsz = 2.f * sz * cz, ncz = fmaf(-2.f * sz, sz, 1.f);
            sx = nsx; cx = ncx; sy = nsy; cy = ncy; sz = nsz; cz = ncz;
        }
    }
    float acc[64];
#pragma unroll
    for (int j = 0; j < 64; j++) acc[j] = c1[j];
#pragma unroll 1
    for (int i = 0; i < 27; i++) {
        const float vi = v[i];
        const float* w = V1 + (15 + i) * 64;
#pragma unroll
        for (int j = 0; j < 64; j++) acc[j] = fmaf(vi, w[j], acc[j]);
    }
#pragma unroll
    for (int j = 0; j < 64; j++) g_base_arr[ray * 64 + j] = acc[j];
}

// ---------------------------------------------------------------------------
// Fused ray-marcher: CTA = 128 threads = 4 warps = one ray per iteration.
// All layers 2-pass split: A_hi x (B_hi + B_lo). Activations bf16-hi only.
// dt computed per-CTA (deterministic, identical everywhere); b1 folded
// into W1 row 63 with enc[63] = 1.
// ---------------------------------------------------------------------------
__global__ __launch_bounds__(THREADS, 4)
void fused_kernel(const float* __restrict__ orig, const float* __restrict__ dirs,
                  const float* __restrict__ tmin, const float* __restrict__ tmax,
                  const float* __restrict__ W1, const float* __restrict__ b1,
                  const float* __restrict__ W2, const float* __restrict__ b2,
                  const float* __restrict__ V1, const float* __restrict__ V2,
                  const float* __restrict__ c2, float* __restrict__ outp) {
    extern __shared__ char dsm[];
    const int tid = threadIdx.x;
    const int w = tid >> 5, lane = tid & 31, g = lane >> 2, tig = lane & 3;
    const u32 FULL = 0xffffffffu;

    // ---------------- dt = mean(tmax - tmin)/SS (per-CTA, same order) -------
    float dtv;
    {
        float s = 0.f;
        const float4* a4p = (const float4*)tmin;
        const float4* b4p = (const float4*)tmax;
#pragma unroll 1
        for (int i = tid; i < NR / 4; i += THREADS) {
            float4 x = a4p[i], y = b4p[i];
            s += (y.x - x.x) + (y.y - x.y) + (y.z - x.z) + (y.w - x.w);
        }
#pragma unroll
        for (int o = 16; o > 0; o >>= 1) s += __shfl_down_sync(FULL, s, o);
        float* red = (float*)(dsm + OFF_RED);
        if (lane == 0) red[w] = s;
        __syncthreads();
        dtv = (red[0] + red[1] + red[2] + red[3]) / (float)(NR * SS);
        __syncthreads();
    }

    // ---------------- stage weights: split bf16 hi/lo, K-major padded ------
    for (int i = tid; i < 64 * 64; i += THREADS) {            // W1^T; row63 = b1
        int n = i >> 6, k = i & 63;
        float v = (k < 63) ? W1[k * 64 + n] : b1[n];
        __nv_bfloat16 h = __float2bfloat16(v);
        *(__nv_bfloat16*)(dsm + OFF_W1H + n * 144 + k * 2) = h;
        *(__nv_bfloat16*)(dsm + OFF_W1L + n * 144 + k * 2) =
            __float2bfloat16(v - __bfloat162float(h));
    }
    for (int i = tid; i < 16 * 64; i += THREADS) {            // W2^T
        int n = i >> 6, k = i & 63;
        float v = W2[k * 16 + n];
        __nv_bfloat16 h = __float2bfloat16(v);
        *(__nv_bfloat16*)(dsm + OFF_W2H + n * 144 + k * 2) = h;
        *(__nv_bfloat16*)(dsm + OFF_W2L + n * 144 + k * 2) =
            __float2bfloat16(v - __bfloat162float(h));
    }
    for (int i = tid; i < 64 * 16; i += THREADS) {            // B3 = shifted V1[0:15]^T
        int n = i >> 4, k = i & 15;
        float v = (k >= 1) ? V1[(k - 1) * 64 + n] : 0.f;
        __nv_bfloat16 h = __float2bfloat16(v);
        *(__nv_bfloat16*)(dsm + OFF_B3H + n * 40 + k * 2) = h;
        *(__nv_bfloat16*)(dsm + OFF_B3L + n * 40 + k * 2) =
            __float2bfloat16(v - __bfloat162float(h));
    }
    for (int i = tid; i < 8 * 64; i += THREADS) {             // B4 = V2^T, n pad 8
        int n = i >> 6, k = i & 63;
        float v = (n < 3) ? V2[k * 3 + n] : 0.f;
        __nv_bfloat16 h = __float2bfloat16(v);
        *(__nv_bfloat16*)(dsm + OFF_B4H + n * 144 + k * 2) = h;
        *(__nv_bfloat16*)(dsm + OFF_B4L + n * 144 + k * 2) =
            __float2bfloat16(v - __bfloat162float(h));
    }
    if (tid < 16) ((float*)(dsm + OFF_B2))[tid] = b2[tid];
    if (tid < 8)  ((float*)(dsm + OFF_C2))[tid] = (tid < 3) ? c2[tid] : 0.f;
    __syncthreads();

    for (int ray = blockIdx.x; ray < NR; ray += GRIDF) {
        const int s = (w << 5) + lane;

        // ---------------- positional encoding (fast sincos), row = lane -----
        const float dx = dirs[ray * 3 + 0], dy = dirs[ray * 3 + 1], dz = dirs[ray * 3 + 2];
        const float t0 = tmin[ray], t1 = tmax[ray];
        const float tt = t0 + (float)s * (1.0f / (SS - 1)) * (t1 - t0);
        float enc[64];
        enc[0] = fmaf(dx, tt, orig[ray * 3 + 0]);
        enc[1] = fmaf(dy, tt, orig[ray * 3 + 1]);
        enc[2] = fmaf(dz, tt, orig[ray * 3 + 2]);
        {
            float sx, cx, sy, cy, sz, cz;
            __sincosf(enc[0], &sx, &cx);
            __sincosf(enc[1], &sy, &cy);
            __sincosf(enc[2], &sz, &cz);
#pragma unroll
            for (int i = 0; i < 10; i++) {
                enc[3 + 6 * i + 0] = sx; enc[3 + 6 * i + 1] = sy; enc[3 + 6 * i + 2] = sz;
                enc[3 + 6 * i + 3] = cx; enc[3 + 6 * i + 4] = cy; enc[3 + 6 * i + 5] = cz;
                const float nsx = 2.f * sx * cx, ncx = fmaf(-2.f * sx, sx, 1.f);
                const float nsy = 2.f * sy * cy, ncy = fmaf(-2.f * sy, sy, 1.f);
                const float nsz = 2.f * sz * cz, ncz = fmaf(-2.f * sz, sz, 1.f);
                sx = nsx; cx = ncx; sy = nsy; cy = ncy; sz = nsz; cz = ncz;
            }
        }
        enc[63] = 1.0f;     // bias column: W1 row63 = b1
        {
            char* Ah = dsm + OFF_AH + w * 4608 + lane * 144;
#pragma unroll
            for (int j8 = 0; j8 < 8; j8++) {
                *(uint4*)(Ah + j8 * 16) = make_uint4(
                    pkbf2(enc[8 * j8 + 0], enc[8 * j8 + 1]),
                    pkbf2(enc[8 * j8 + 2], enc[8 * j8 + 3]),
                    pkbf2(enc[8 * j8 + 4], enc[8 * j8 + 5]),
                    pkbf2(enc[8 * j8 + 6], enc[8 * j8 + 7]));
            }
        }
        __syncwarp();

        // ---------------- MLP1: enc(64) @ W1 -> 32x64 (2-pass) --------------
        float acc[2][8][4];
#pragma unroll
        for (int mt = 0; mt < 2; mt++)
#pragma unroll
            for (int nt = 0; nt < 8; nt++)
#pragma unroll
                for (int r = 0; r < 4; r++) acc[mt][nt][r] = 0.f;

        const char* AHb = dsm + OFF_AH + w * 4608;
#pragma unroll
        for (int kt = 0; kt < 4; kt++) {
            u32 AH[2][4];
#pragma unroll
            for (int mt = 0; mt < 2; mt++) {
                int ab = mt * 2304 + g * 144 + kt * 32 + tig * 4;
                AH[mt][0] = *(const u32*)(AHb + ab);
                AH[mt][1] = *(const u32*)(AHb + ab + 1152);
                AH[mt][2] = *(const u32*)(AHb + ab + 16);
                AH[mt][3] = *(const u32*)(AHb + ab + 1168);
            }
#pragma unroll
            for (int nt = 0; nt < 8; nt++) {
                int bo = (nt * 8 + g) * 144 + kt * 32 + tig * 4;
                u32 bh0 = *(const u32*)(dsm + OFF_W1H + bo);
                u32 bh1 = *(const u32*)(dsm + OFF_W1H + bo + 16);
                u32 bl0 = *(const u32*)(dsm + OFF_W1L + bo);
                u32 bl1 = *(const u32*)(dsm + OFF_W1L + bo + 16);
#pragma unroll
                for (int mt = 0; mt < 2; mt++) {
                    mma4(acc[mt][nt], AH[mt], bh0, bh1);
                    mma4(acc[mt][nt], AH[mt], bl0, bl1);
                }
            }
        }

        // ---------------- epi1: h = relu(D) -> hi frags (bias already in) ---
        u32 HF[2][4][4];
#pragma unroll
        for (int kt = 0; kt < 4; kt++)
#pragma unroll
            for (int j = 0; j < 2; j++) {
                const int nt = 2 * kt + j;
#pragma unroll
                for (int mt = 0; mt < 2; mt++) {
                    float v0 = fmaxf(acc[mt][nt][0], 0.f);
                    float v1 = fmaxf(acc[mt][nt][1], 0.f);
                    float v2 = fmaxf(acc[mt][nt][2], 0.f);
                    float v3 = fmaxf(acc[mt][nt][3], 0.f);
                    HF[mt][kt][2 * j + 0] = pkbf2(v0, v1);
                    HF[mt][kt][2 * j + 1] = pkbf2(v2, v3);
                }
            }

        // ---------------- MLP2: h @ W2 -> 32x16 (2-pass) --------------------
        float a2c[2][2][4];
#pragma unroll
        for (int mt = 0; mt < 2; mt++)
#pragma unroll
            for (int n2 = 0; n2 < 2; n2++)
#pragma unroll
                for (int r = 0; r < 4; r++) a2c[mt][n2][r] = 0.f;
#pragma unroll
        for (int kt = 0; kt < 4; kt++)
#pragma unroll
            for (int n2 = 0; n2 < 2; n2++) {
                int bo = (n2 * 8 + g) * 144 + kt * 32 + tig * 4;
                u32 bh0 = *(const u32*)(dsm + OFF_W2H + bo);
                u32 bh1 = *(const u32*)(dsm + OFF_W2H + bo + 16);
                u32 bl0 = *(const u32*)(dsm + OFF_W2L + bo);
                u32 bl1 = *(const u32*)(dsm + OFF_W2L + bo + 16);
#pragma unroll
                for (int mt = 0; mt < 2; mt++) {
                    mma4(a2c[mt][n2], HF[mt][kt], bh0, bh1);
                    mma4(a2c[mt][n2], HF[mt][kt], bl0, bl1);
                }
            }

        // ---------------- epi2: sigma raw + feat hi frags -------------------
        float sgm[2][2];
        u32 FF[2][4];
        {
            const float2 b20 = *(const float2*)(dsm + OFF_B2 + tig * 8);
            const float2 b21 = *(const float2*)(dsm + OFF_B2 + 32 + tig * 8);
#pragma unroll
            for (int mt = 0; mt < 2; mt++) {
                float v0 = a2c[mt][0][0] + b20.x;
                float v1 = a2c[mt][0][1] + b20.y;
                float v2 = a2c[mt][0][2] + b20.x;
                float v3 = a2c[mt][0][3] + b20.y;
                float u0 = a2c[mt][1][0] + b21.x;
                float u1 = a2c[mt][1][1] + b21.y;
                float u2 = a2c[mt][1][2] + b21.x;
                float u3 = a2c[mt][1][3] + b21.y;
                sgm[mt][0] = v0;
                sgm[mt][1] = v2;
                FF[mt][0] = pkbf2(v0, v1);
                FF[mt][1] = pkbf2(v2, v3);
                FF[mt][2] = pkbf2(u0, u1);
                FF[mt][3] = pkbf2(u2, u3);
            }
        }

        // ---------------- MLP3: feats(16) @ B3 -> 32x64 (2-pass) ------------
        float a3c[2][8][4];
#pragma unroll
        for (int mt = 0; mt < 2; mt++)
#pragma unroll
            for (int nt = 0; nt < 8; nt++)
#pragma unroll
                for (int r = 0; r < 4; r++) a3c[mt][nt][r] = 0.f;
#pragma unroll
        for (int nt = 0; nt < 8; nt++) {
            int bo = (nt * 8 + g) * 40 + tig * 4;
            u32 bh0 = *(const u32*)(dsm + OFF_B3H + bo);
            u32 bh1 = *(const u32*)(dsm + OFF_B3H + bo + 16);
            u32 bl0 = *(const u32*)(dsm + OFF_B3L + bo);
            u32 bl1 = *(const u32*)(dsm + OFF_B3L + bo + 16);
#pragma unroll
            for (int mt = 0; mt < 2; mt++) {
                mma4(a3c[mt][nt], FF[mt], bh0, bh1);
                mma4(a3c[mt][nt], FF[mt], bl0, bl1);
            }
        }

        // ---------------- epi3: g = relu(D + g_base) -> hi frags ------------
        u32 GF[2][4][4];
        const float* gb = g_base_arr + ray * 64;
#pragma unroll
        for (int kt = 0; kt < 4; kt++)
#pragma unroll
            for (int j = 0; j < 2; j++) {
                const int nt = 2 * kt + j;
                const float2 gv = __ldg((const float2*)(gb + nt * 8 + tig * 2));
#pragma unroll
                for (int mt = 0; mt < 2; mt++) {
                    float v0 = fmaxf(a3c[mt][nt][0] + gv.x, 0.f);
                    float v1 = fmaxf(a3c[mt][nt][1] + gv.y, 0.f);
                    float v2 = fmaxf(a3c[mt][nt][2] + gv.x, 0.f);
                    float v3 = fmaxf(a3c[mt][nt][3] + gv.y, 0.f);
                    GF[mt][kt][2 * j + 0] = pkbf2(v0, v1);
                    GF[mt][kt][2 * j + 1] = pkbf2(v2, v3);
                }
            }

        // ---------------- MLP4: g @ V2 -> 32x8 (2-pass) ---------------------
        float a4[2][4];
#pragma unroll
        for (int mt = 0; mt < 2; mt++)
#pragma unroll
            for (int r = 0; r < 4; r++) a4[mt][r] = 0.f;
#pragma unroll
        for (int kt = 0; kt < 4; kt++) {
            int bo = g * 144 + kt * 32 + tig * 4;
            u32 bh0 = *(const u32*)(dsm + OFF_B4H + bo);
            u32 bh1 = *(const u32*)(dsm + OFF_B4H + bo + 16);
            u32 bl0 = *(const u32*)(dsm + OFF_B4L + bo);
            u32 bl1 = *(const u32*)(dsm + OFF_B4L + bo + 16);
#pragma unroll
            for (int mt = 0; mt < 2; mt++) {
                mma4(a4[mt], GF[mt][kt], bh0, bh1);
                mma4(a4[mt], GF[mt][kt], bl0, bl1);
            }
        }

        // ---------------- epi4 + redistribution lane<->row ------------------
        float o0[2], o1[2], o2[2], o3[2];
        {
            const float2 cc = *(const float2*)(dsm + OFF_C2 + tig * 8);
#pragma unroll
            for (int mt = 0; mt < 2; mt++) {
                o0[mt] = a4[mt][0] + cc.x;
                o1[mt] = a4[mt][1] + cc.y;
                o2[mt] = a4[mt][2] + cc.x;
                o3[mt] = a4[mt][3] + cc.y;
            }
        }
        const int q4 = (lane & 7) * 4;
        const int selv = lane >> 3;
        float x0, x1, x2, x3;
        x0 = __shfl_sync(FULL, sgm[0][0], q4);
        x1 = __shfl_sync(FULL, sgm[0][1], q4);
        x2 = __shfl_sync(FULL, sgm[1][0], q4);
        x3 = __shfl_sync(FULL, sgm[1][1], q4);
        const float sigma = fmaxf(selv == 0 ? x0 : selv == 1 ? x1 : selv == 2 ? x2 : x3, 0.f);
        x0 = __shfl_sync(FULL, o0[0], q4);
        x1 = __shfl_sync(FULL, o2[0], q4);
        x2 = __shfl_sync(FULL, o0[1], q4);
        x3 = __shfl_sync(FULL, o2[1], q4);
        const float rv = selv == 0 ? x0 : selv == 1 ? x1 : selv == 2 ? x2 : x3;
        x0 = __shfl_sync(FULL, o1[0], q4);
        x1 = __shfl_sync(FULL, o3[0], q4);
        x2 = __shfl_sync(FULL, o1[1], q4);
        x3 = __shfl_sync(FULL, o3[1], q4);
        const float gvv = selv == 0 ? x0 : selv == 1 ? x1 : selv == 2 ? x2 : x3;
        x0 = __shfl_sync(FULL, o0[0], q4 + 1);
        x1 = __shfl_sync(FULL, o2[0], q4 + 1);
        x2 = __shfl_sync(FULL, o0[1], q4 + 1);
        x3 = __shfl_sync(FULL, o2[1], q4 + 1);
        const float bv = selv == 0 ? x0 : selv == 1 ? x1 : selv == 2 ? x2 : x3;
        const float rr = 1.f / (1.f + __expf(-rv));
        const float rg = 1.f / (1.f + __expf(-gvv));
        const float rb = 1.f / (1.f + __expf(-bv));

        // ---------------- transmittance scan --------------------------------
        {
            const float ex = __expf(-sigma * dtv);      // one_minus
            const float alpha = 1.f - ex;
            float p = ex;
#pragma unroll
            for (int o = 1; o < 32; o <<= 1) {
                float q = __shfl_up_sync(FULL, p, o);
                if (lane >= o) p *= q;
            }
            float* red = (float*)(dsm + OFF_RED);
            if (lane == 31) red[w] = p;
            __syncthreads();
            float wpre = 1.f;
#pragma unroll
            for (int k = 0; k < 3; k++)
                if (k < w) wpre *= red[k];
            const float pm1 = __shfl_up_sync(FULL, p, 1);
            const float excl = (lane == 0) ? wpre : wpre * pm1;
            const bool active = excl > 1e-4f;
            const float wgt = active ? excl * alpha : 0.f;
            float sr = wgt * rr, sg2 = wgt * rg, sb = wgt * rb;
            float ft = active ? ex : 1.f;
#pragma unroll
            for (int o = 16; o > 0; o >>= 1) {
                sr += __shfl_xor_sync(FULL, sr, o);
                sg2 += __shfl_xor_sync(FULL, sg2, o);
                sb += __shfl_xor_sync(FULL, sb, o);
                ft *= __shfl_xor_sync(FULL, ft, o);
            }
            float* part = (float*)(dsm + OFF_PART) + w * 4;
            if (lane == 0) { part[0] = sr; part[1] = sg2; part[2] = sb; part[3] = ft; }
            __syncthreads();
            if (tid == 0) {
                const float* pp = (const float*)(dsm + OFF_PART);
                float R = 0, G = 0, B = 0, T = 1.f;
#pragma unroll
                for (int k = 0; k < 4; k++) {
                    R += pp[k * 4 + 0]; G += pp[k * 4 + 1];
                    B += pp[k * 4 + 2]; T *= pp[k * 4 + 3];
                }
                outp[ray * 3 + 0] = R;
                outp[ray * 3 + 1] = G;
                outp[ray * 3 + 2] = B;
                outp[3 * NR + ray] = T;
            }
            // NOTE: no 3rd barrier — next iteration's red write is fenced by
            // the sync above; part reuse is fenced by next iteration's red sync
            // (which requires tid 0 to have finished the output writes).
        }
    }
}

// ---------------------------------------------------------------------------
extern "C" void kernel_launch(void* const* d_in, const int* in_sizes, int n_in,
                              void* d_out, int out_size) {
    const float* orig = (const float*)d_in[0];
    const float* dirs = (const float*)d_in[1];
    const float* tmin = (const float*)d_in[2];
    const float* tmax = (const float*)d_in[3];
    const float* W1   = (const float*)d_in[4];
    const float* b1   = (const float*)d_in[5];
    const float* W2   = (const float*)d_in[6];
    const float* b2   = (const float*)d_in[7];
    const float* V1   = (const float*)d_in[8];
    const float* c1   = (const float*)d_in[9];
    const float* V2   = (const float*)d_in[10];
    const float* c2   = (const float*)d_in[11];

    cudaFuncSetAttribute(fused_kernel, cudaFuncAttributeMaxDynamicSharedMemorySize, SMEM_TOTAL);

    ray_kernel<<<NR / 128, 128>>>(dirs, V1, c1);
    fused_kernel<<<GRIDF, THREADS, SMEM_TOTAL>>>(orig, dirs, tmin, tmax,
                                                 W1, b1, W2, b2, V1, V2, c2,
                                                 (float*)d_out);
}

// round 13
// speedup vs baseline: 2.0928x; 1.0038x over previous
#include <cuda_runtime.h>
#include <cuda_bf16.h>
#include <math.h>

#define NR 8192
#define SS 128
#define GRIDF 592          // 4 CTAs/SM x 148 SMs
#define THREADS 128        // 4 warps = 1 ray per iteration
#define MAXRAYS 14         // ceil(NR / GRIDF)

typedef unsigned int u32;

// ---------------- smem layout (bytes), per CTA ----------------
#define OFF_AH   0                 // 4 warps x 32 rows x 144B (bf16 hi only)
#define OFF_W1H  18432             // W1^T [64n][72 bf16 stride], K row63 = b1
#define OFF_W1L  27648
#define OFF_W2H  36864             // W2^T [16n][72]
#define OFF_W2L  39168
#define OFF_B3H  41472             // V1[0:15]^T shifted: [64n][20 bf16 stride], k0=0
#define OFF_B3L  44032
#define OFF_B4H  46592             // V2^T [8n][72], n>=3 zero
#define OFF_B4L  47744
#define OFF_B2   48896             // b2 (16 f32)
#define OFF_C2   48960             // c2 (8 f32, padded)
#define OFF_RED  48992             // 4 warp products
#define OFF_PART 49024             // 4 warps x 4 floats
#define OFF_GB   49152             // per-CTA g_base table [MAXRAYS][64] f32
#define SMEM_TOTAL (OFF_GB + MAXRAYS * 64 * 4)   // 52736

// pack 2 floats -> bf16x2 in ONE instruction (low = x, high = y)
static __device__ __forceinline__ u32 pkbf2(float x, float y) {
    u32 r;
    asm("cvt.rn.satfinite.bf16x2.f32 %0, %1, %2;" : "=r"(r) : "f"(y), "f"(x));
    return r;
}
static __device__ __forceinline__ void mma4(float* d, const u32* a, u32 b0, u32 b1) {
    asm volatile(
        "mma.sync.aligned.m16n8k16.row.col.f32.bf16.bf16.f32 "
        "{%0,%1,%2,%3}, {%4,%5,%6,%7}, {%8,%9}, {%0,%1,%2,%3};"
        : "+f"(d[0]), "+f"(d[1]), "+f"(d[2]), "+f"(d[3])
        : "r"(a[0]), "r"(a[1]), "r"(a[2]), "r"(a[3]), "r"(b0), "r"(b1));
}

// ---------------------------------------------------------------------------
// Fused ray-marcher, SINGLE kernel. CTA = 128 threads = 4 warps = one ray/iter.
// Prologue: dt (deterministic per-CTA) + weight staging + per-CTA g_base table.
// ---------------------------------------------------------------------------
__global__ __launch_bounds__(THREADS, 4)
void fused_kernel(const float* __restrict__ orig, const float* __restrict__ dirs,
                  const float* __restrict__ tmin, const float* __restrict__ tmax,
                  const float* __restrict__ W1, const float* __restrict__ b1,
                  const float* __restrict__ W2, const float* __restrict__ b2,
                  const float* __restrict__ V1, const float* __restrict__ c1,
                  const float* __restrict__ V2, const float* __restrict__ c2,
                  float* __restrict__ outp) {
    extern __shared__ char dsm[];
    const int tid = threadIdx.x;
    const int w = tid >> 5, lane = tid & 31, g = lane >> 2, tig = lane & 3;
    const u32 FULL = 0xffffffffu;

    // ---------------- dt = mean(tmax - tmin)/SS (per-CTA, same order) -------
    float dtv;
    {
        float s = 0.f;
        const float4* a4p = (const float4*)tmin;
        const float4* b4p = (const float4*)tmax;
#pragma unroll 1
        for (int i = tid; i < NR / 4; i += THREADS) {
            float4 x = a4p[i], y = b4p[i];
            s += (y.x - x.x) + (y.y - x.y) + (y.z - x.z) + (y.w - x.w);
        }
#pragma unroll
        for (int o = 16; o > 0; o >>= 1) s += __shfl_down_sync(FULL, s, o);
        float* red = (float*)(dsm + OFF_RED);
        if (lane == 0) red[w] = s;
        __syncthreads();
        dtv = (red[0] + red[1] + red[2] + red[3]) / (float)(NR * SS);
        __syncthreads();
    }

    // ---------------- stage weights: split bf16 hi/lo, K-major padded ------
    for (int i = tid; i < 64 * 64; i += THREADS) {            // W1^T; row63 = b1
        int n = i >> 6, k = i & 63;
        float v = (k < 63) ? W1[k * 64 + n] : b1[n];
        __nv_bfloat16 h = __float2bfloat16(v);
        *(__nv_bfloat16*)(dsm + OFF_W1H + n * 144 + k * 2) = h;
        *(__nv_bfloat16*)(dsm + OFF_W1L + n * 144 + k * 2) =
            __float2bfloat16(v - __bfloat162float(h));
    }
    for (int i = tid; i < 16 * 64; i += THREADS) {            // W2^T
        int n = i >> 6, k = i & 63;
        float v = W2[k * 16 + n];
        __nv_bfloat16 h = __float2bfloat16(v);
        *(__nv_bfloat16*)(dsm + OFF_W2H + n * 144 + k * 2) = h;
        *(__nv_bfloat16*)(dsm + OFF_W2L + n * 144 + k * 2) =
            __float2bfloat16(v - __bfloat162float(h));
    }
    for (int i = tid; i < 64 * 16; i += THREADS) {            // B3 = shifted V1[0:15]^T
        int n = i >> 4, k = i & 15;
        float v = (k >= 1) ? V1[(k - 1) * 64 + n] : 0.f;
        __nv_bfloat16 h = __float2bfloat16(v);
        *(__nv_bfloat16*)(dsm + OFF_B3H + n * 40 + k * 2) = h;
        *(__nv_bfloat16*)(dsm + OFF_B3L + n * 40 + k * 2) =
            __float2bfloat16(v - __bfloat162float(h));
    }
    for (int i = tid; i < 8 * 64; i += THREADS) {             // B4 = V2^T, n pad 8
        int n = i >> 6, k = i & 63;
        float v = (n < 3) ? V2[k * 3 + n] : 0.f;
        __nv_bfloat16 h = __float2bfloat16(v);
        *(__nv_bfloat16*)(dsm + OFF_B4H + n * 144 + k * 2) = h;
        *(__nv_bfloat16*)(dsm + OFF_B4L + n * 144 + k * 2) =
            __float2bfloat16(v - __bfloat162float(h));
    }
    if (tid < 16) ((float*)(dsm + OFF_B2))[tid] = b2[tid];
    if (tid < 8)  ((float*)(dsm + OFF_C2))[tid] = (tid < 3) ? c2[tid] : 0.f;

    // ---------------- per-CTA g_base table (2 rays in parallel) -------------
    {
        const int j = tid & 63;
        float* gbt = (float*)(dsm + OFF_GB);
#pragma unroll 1
        for (int rr = tid >> 6; rr < MAXRAYS; rr += 2) {
            const int ray = blockIdx.x + rr * GRIDF;
            if (ray >= NR) break;
            const float dx = dirs[ray * 3 + 0], dy = dirs[ray * 3 + 1], dz = dirs[ray * 3 + 2];
            const float nrm = sqrtf(dx * dx + dy * dy + dz * dz) + 1e-8f;
            const float inv = 1.0f / nrm;
            const float vx = dx * inv, vy = dy * inv, vz = dz * inv;
            float v[27];
            v[0] = vx; v[1] = vy; v[2] = vz;
            {
                float sx, cx, sy, cy, sz, cz;
                sincosf(vx, &sx, &cx); sincosf(vy, &sy, &cy); sincosf(vz, &sz, &cz);
#pragma unroll
                for (int i = 0; i < 4; i++) {
                    v[3 + 6 * i + 0] = sx; v[3 + 6 * i + 1] = sy; v[3 + 6 * i + 2] = sz;
                    v[3 + 6 * i + 3] = cx; v[3 + 6 * i + 4] = cy; v[3 + 6 * i + 5] = cz;
                    const float nsx = 2.f * sx * cx, ncx = fmaf(-2.f * sx, sx, 1.f);
                    const float nsy = 2.f * sy * cy, ncy = fmaf(-2.f * sy, sy, 1.f);
                    const float nsz = 2.f * sz * cz, ncz = fmaf(-2.f * sz, sz, 1.f);
                    sx = nsx; cx = ncx; sy = nsy; cy = ncy; sz = nsz; cz = ncz;
                }
            }
            float acc0 = c1[j];
#pragma unroll 1
            for (int i = 0; i < 27; i++) acc0 = fmaf(v[i], V1[(15 + i) * 64 + j], acc0);
            gbt[rr * 64 + j] = acc0;
        }
    }
    __syncthreads();

    int rloc = 0;
    for (int ray = blockIdx.x; ray < NR; ray += GRIDF, rloc++) {
        const int s = (w << 5) + lane;

        // ---------------- positional encoding (fast sincos), row = lane -----
        const float dx = dirs[ray * 3 + 0], dy = dirs[ray * 3 + 1], dz = dirs[ray * 3 + 2];
        const float t0 = tmin[ray], t1 = tmax[ray];
        const float tt = t0 + (float)s * (1.0f / (SS - 1)) * (t1 - t0);
        float enc[64];
        enc[0] = fmaf(dx, tt, orig[ray * 3 + 0]);
        enc[1] = fmaf(dy, tt, orig[ray * 3 + 1]);
        enc[2] = fmaf(dz, tt, orig[ray * 3 + 2]);
        {
            float sx, cx, sy, cy, sz, cz;
            __sincosf(enc[0], &sx, &cx);
            __sincosf(enc[1], &sy, &cy);
            __sincosf(enc[2], &sz, &cz);
#pragma unroll
            for (int i = 0; i < 10; i++) {
                enc[3 + 6 * i + 0] = sx; enc[3 + 6 * i + 1] = sy; enc[3 + 6 * i + 2] = sz;
                enc[3 + 6 * i + 3] = cx; enc[3 + 6 * i + 4] = cy; enc[3 + 6 * i + 5] = cz;
                const float nsx = 2.f * sx * cx, ncx = fmaf(-2.f * sx, sx, 1.f);
                const float nsy = 2.f * sy * cy, ncy = fmaf(-2.f * sy, sy, 1.f);
                const float nsz = 2.f * sz * cz, ncz = fmaf(-2.f * sz, sz, 1.f);
                sx = nsx; cx = ncx; sy = nsy; cy = ncy; sz = nsz; cz = ncz;
            }
        }
        enc[63] = 1.0f;     // bias column: W1 row63 = b1
        {
            char* Ah = dsm + OFF_AH + w * 4608 + lane * 144;
#pragma unroll
            for (int j8 = 0; j8 < 8; j8++) {
                *(uint4*)(Ah + j8 * 16) = make_uint4(
                    pkbf2(enc[8 * j8 + 0], enc[8 * j8 + 1]),
                    pkbf2(enc[8 * j8 + 2], enc[8 * j8 + 3]),
                    pkbf2(enc[8 * j8 + 4], enc[8 * j8 + 5]),
                    pkbf2(enc[8 * j8 + 6], enc[8 * j8 + 7]));
            }
        }
        __syncwarp();

        // ---------------- MLP1: enc(64) @ W1 -> 32x64 (2-pass) --------------
        float acc[2][8][4];
#pragma unroll
        for (int mt = 0; mt < 2; mt++)
#pragma unroll
            for (int nt = 0; nt < 8; nt++)
#pragma unroll
                for (int r = 0; r < 4; r++) acc[mt][nt][r] = 0.f;

        const char* AHb = dsm + OFF_AH + w * 4608;
#pragma unroll
        for (int kt = 0; kt < 4; kt++) {
            u32 AH[2][4];
#pragma unroll
            for (int mt = 0; mt < 2; mt++) {
                int ab = mt * 2304 + g * 144 + kt * 32 + tig * 4;
                AH[mt][0] = *(const u32*)(AHb + ab);
                AH[mt][1] = *(const u32*)(AHb + ab + 1152);
                AH[mt][2] = *(const u32*)(AHb + ab + 16);
                AH[mt][3] = *(const u32*)(AHb + ab + 1168);
            }
#pragma unroll
            for (int nt = 0; nt < 8; nt++) {
                int bo = (nt * 8 + g) * 144 + kt * 32 + tig * 4;
                u32 bh0 = *(const u32*)(dsm + OFF_W1H + bo);
                u32 bh1 = *(const u32*)(dsm + OFF_W1H + bo + 16);
                u32 bl0 = *(const u32*)(dsm + OFF_W1L + bo);
                u32 bl1 = *(const u32*)(dsm + OFF_W1L + bo + 16);
#pragma unroll
                for (int mt = 0; mt < 2; mt++) {
                    mma4(acc[mt][nt], AH[mt], bh0, bh1);
                    mma4(acc[mt][nt], AH[mt], bl0, bl1);
                }
            }
        }

        // ---------------- epi1: h = relu(D) -> hi frags (bias already in) ---
        u32 HF[2][4][4];
#pragma unroll
        for (int kt = 0; kt < 4; kt++)
#pragma unroll
            for (int j = 0; j < 2; j++) {
                const int nt = 2 * kt + j;
#pragma unroll
                for (int mt = 0; mt < 2; mt++) {
                    float v0 = fmaxf(acc[mt][nt][0], 0.f);
                    float v1 = fmaxf(acc[mt][nt][1], 0.f);
                    float v2 = fmaxf(acc[mt][nt][2], 0.f);
                    float v3 = fmaxf(acc[mt][nt][3], 0.f);
                    HF[mt][kt][2 * j + 0] = pkbf2(v0, v1);
                    HF[mt][kt][2 * j + 1] = pkbf2(v2, v3);
                }
            }

        // ---------------- MLP2: h @ W2 -> 32x16 (2-pass) --------------------
        float a2c[2][2][4];
#pragma unroll
        for (int mt = 0; mt < 2; mt++)
#pragma unroll
            for (int n2 = 0; n2 < 2; n2++)
#pragma unroll
                for (int r = 0; r < 4; r++) a2c[mt][n2][r] = 0.f;
#pragma unroll
        for (int kt = 0; kt < 4; kt++)
#pragma unroll
            for (int n2 = 0; n2 < 2; n2++) {
                int bo = (n2 * 8 + g) * 144 + kt * 32 + tig * 4;
                u32 bh0 = *(const u32*)(dsm + OFF_W2H + bo);
                u32 bh1 = *(const u32*)(dsm + OFF_W2H + bo + 16);
                u32 bl0 = *(const u32*)(dsm + OFF_W2L + bo);
                u32 bl1 = *(const u32*)(dsm + OFF_W2L + bo + 16);
#pragma unroll
                for (int mt = 0; mt < 2; mt++) {
                    mma4(a2c[mt][n2], HF[mt][kt], bh0, bh1);
                    mma4(a2c[mt][n2], HF[mt][kt], bl0, bl1);
                }
            }

        // ---------------- epi2: sigma raw + feat hi frags -------------------
        float sgm[2][2];
        u32 FF[2][4];
        {
            const float2 b20 = *(const float2*)(dsm + OFF_B2 + tig * 8);
            const float2 b21 = *(const float2*)(dsm + OFF_B2 + 32 + tig * 8);
#pragma unroll
            for (int mt = 0; mt < 2; mt++) {
                float v0 = a2c[mt][0][0] + b20.x;
                float v1 = a2c[mt][0][1] + b20.y;
                float v2 = a2c[mt][0][2] + b20.x;
                float v3 = a2c[mt][0][3] + b20.y;
                float u0 = a2c[mt][1][0] + b21.x;
                float u1 = a2c[mt][1][1] + b21.y;
                float u2 = a2c[mt][1][2] + b21.x;
                float u3 = a2c[mt][1][3] + b21.y;
                sgm[mt][0] = v0;
                sgm[mt][1] = v2;
                FF[mt][0] = pkbf2(v0, v1);
                FF[mt][1] = pkbf2(v2, v3);
                FF[mt][2] = pkbf2(u0, u1);
                FF[mt][3] = pkbf2(u2, u3);
            }
        }

        // ---------------- MLP3: feats(16) @ B3 -> 32x64 (2-pass) ------------
        float a3c[2][8][4];
#pragma unroll
        for (int mt = 0; mt < 2; mt++)
#pragma unroll
            for (int nt = 0; nt < 8; nt++)
#pragma unroll
                for (int r = 0; r < 4; r++) a3c[mt][nt][r] = 0.f;
#pragma unroll
        for (int nt = 0; nt < 8; nt++) {
            int bo = (nt * 8 + g) * 40 + tig * 4;
            u32 bh0 = *(const u32*)(dsm + OFF_B3H + bo);
            u32 bh1 = *(const u32*)(dsm + OFF_B3H + bo + 16);
            u32 bl0 = *(const u32*)(dsm + OFF_B3L + bo);
            u32 bl1 = *(const u32*)(dsm + OFF_B3L + bo + 16);
#pragma unroll
            for (int mt = 0; mt < 2; mt++) {
                mma4(a3c[mt][nt], FF[mt], bh0, bh1);
                mma4(a3c[mt][nt], FF[mt], bl0, bl1);
            }
        }

        // ---------------- epi3: g = relu(D + g_base) -> hi frags ------------
        u32 GF[2][4][4];
        const float* gb = (const float*)(dsm + OFF_GB) + rloc * 64;
#pragma unroll
        for (int kt = 0; kt < 4; kt++)
#pragma unroll
            for (int j = 0; j < 2; j++) {
                const int nt = 2 * kt + j;
                const float2 gv = *(const float2*)(gb + nt * 8 + tig * 2);
#pragma unroll
                for (int mt = 0; mt < 2; mt++) {
                    float v0 = fmaxf(a3c[mt][nt][0] + gv.x, 0.f);
                    float v1 = fmaxf(a3c[mt][nt][1] + gv.y, 0.f);
                    float v2 = fmaxf(a3c[mt][nt][2] + gv.x, 0.f);
                    float v3 = fmaxf(a3c[mt][nt][3] + gv.y, 0.f);
                    GF[mt][kt][2 * j + 0] = pkbf2(v0, v1);
                    GF[mt][kt][2 * j + 1] = pkbf2(v2, v3);
                }
            }

        // ---------------- MLP4: g @ V2 -> 32x8 (2-pass) ---------------------
        float a4[2][4];
#pragma unroll
        for (int mt = 0; mt < 2; mt++)
#pragma unroll
            for (int r = 0; r < 4; r++) a4[mt][r] = 0.f;
#pragma unroll
        for (int kt = 0; kt < 4; kt++) {
            int bo = g * 144 + kt * 32 + tig * 4;
            u32 bh0 = *(const u32*)(dsm + OFF_B4H + bo);
            u32 bh1 = *(const u32*)(dsm + OFF_B4H + bo + 16);
            u32 bl0 = *(const u32*)(dsm + OFF_B4L + bo);
            u32 bl1 = *(const u32*)(dsm + OFF_B4L + bo + 16);
#pragma unroll
            for (int mt = 0; mt < 2; mt++) {
                mma4(a4[mt], GF[mt][kt], bh0, bh1);
                mma4(a4[mt], GF[mt][kt], bl0, bl1);
            }
        }

        // ---------------- epi4 + redistribution lane<->row ------------------
        float o0[2], o1[2], o2[2], o3[2];
        {
            const float2 cc = *(const float2*)(dsm + OFF_C2 + tig * 8);
#pragma unroll
            for (int mt = 0; mt < 2; mt++) {
                o0[mt] = a4[mt][0] + cc.x;
                o1[mt] = a4[mt][1] + cc.y;
                o2[mt] = a4[mt][2] + cc.x;
                o3[mt] = a4[mt][3] + cc.y;
            }
        }
        const int q4 = (lane & 7) * 4;
        const int selv = lane >> 3;
        float x0, x1, x2, x3;
        x0 = __shfl_sync(FULL, sgm[0][0], q4);
        x1 = __shfl_sync(FULL, sgm[0][1], q4);
        x2 = __shfl_sync(FULL, sgm[1][0], q4);
        x3 = __shfl_sync(FULL, sgm[1][1], q4);
        const float sigma = fmaxf(selv == 0 ? x0 : selv == 1 ? x1 : selv == 2 ? x2 : x3, 0.f);
        x0 = __shfl_sync(FULL, o0[0], q4);
        x1 = __shfl_sync(FULL, o2[0], q4);
        x2 = __shfl_sync(FULL, o0[1], q4);
        x3 = __shfl_sync(FULL, o2[1], q4);
        const float rv = selv == 0 ? x0 : selv == 1 ? x1 : selv == 2 ? x2 : x3;
        x0 = __shfl_sync(FULL, o1[0], q4);
        x1 = __shfl_sync(FULL, o3[0], q4);
        x2 = __shfl_sync(FULL, o1[1], q4);
        x3 = __shfl_sync(FULL, o3[1], q4);
        const float gvv = selv == 0 ? x0 : selv == 1 ? x1 : selv == 2 ? x2 : x3;
        x0 = __shfl_sync(FULL, o0[0], q4 + 1);
        x1 = __shfl_sync(FULL, o2[0], q4 + 1);
        x2 = __shfl_sync(FULL, o0[1], q4 + 1);
        x3 = __shfl_sync(FULL, o2[1], q4 + 1);
        const float bv = selv == 0 ? x0 : selv == 1 ? x1 : selv == 2 ? x2 : x3;
        const float rr = 1.f / (1.f + __expf(-rv));
        const float rg = 1.f / (1.f + __expf(-gvv));
        const float rb = 1.f / (1.f + __expf(-bv));

        // ---------------- transmittance scan --------------------------------
        {
            const float ex = __expf(-sigma * dtv);      // one_minus
            const float alpha = 1.f - ex;
            float p = ex;
#pragma unroll
            for (int o = 1; o < 32; o <<= 1) {
                float q = __shfl_up_sync(FULL, p, o);
                if (lane >= o) p *= q;
            }
            float* red = (float*)(dsm + OFF_RED);
            if (lane == 31) red[w] = p;
            __syncthreads();
            float wpre = 1.f;
#pragma unroll
            for (int k = 0; k < 3; k++)
                if (k < w) wpre *= red[k];
            const float pm1 = __shfl_up_sync(FULL, p, 1);
            const float excl = (lane == 0) ? wpre : wpre * pm1;
            const bool active = excl > 1e-4f;
            const float wgt = active ? excl * alpha : 0.f;
            float sr = wgt * rr, sg2 = wgt * rg, sb = wgt * rb;
            float ft = active ? ex : 1.f;
#pragma unroll
            for (int o = 16; o > 0; o >>= 1) {
                sr += __shfl_xor_sync(FULL, sr, o);
                sg2 += __shfl_xor_sync(FULL, sg2, o);
                sb += __shfl_xor_sync(FULL, sb, o);
                ft *= __shfl_xor_sync(FULL, ft, o);
            }
            float* part = (float*)(dsm + OFF_PART) + w * 4;
            if (lane == 0) { part[0] = sr; part[1] = sg2; part[2] = sb; part[3] = ft; }
            __syncthreads();
            if (tid == 0) {
                const float* pp = (const float*)(dsm + OFF_PART);
                float R = 0, G = 0, B = 0, T = 1.f;
#pragma unroll
                for (int k = 0; k < 4; k++) {
                    R += pp[k * 4 + 0]; G += pp[k * 4 + 1];
                    B += pp[k * 4 + 2]; T *= pp[k * 4 + 3];
                }
                outp[ray * 3 + 0] = R;
                outp[ray * 3 + 1] = G;
                outp[ray * 3 + 2] = B;
                outp[3 * NR + ray] = T;
            }
            // no 3rd barrier (validated in R12): next iteration's red-sync
            // fences both red and part reuse.
        }
    }
}

// ---------------------------------------------------------------------------
extern "C" void kernel_launch(void* const* d_in, const int* in_sizes, int n_in,
                              void* d_out, int out_size) {
    const float* orig = (const float*)d_in[0];
    const float* dirs = (const float*)d_in[1];
    const float* tmin = (const float*)d_in[2];
    const float* tmax = (const float*)d_in[3];
    const float* W1   = (const float*)d_in[4];
    const float* b1   = (const float*)d_in[5];
    const float* W2   = (const float*)d_in[6];
    const float* b2   = (const float*)d_in[7];
    const float* V1   = (const float*)d_in[8];
    const float* c1   = (const float*)d_in[9];
    const float* V2   = (const float*)d_in[10];
    const float* c2   = (const float*)d_in[11];

    cudaFuncSetAttribute(fused_kernel, cudaFuncAttributeMaxDynamicSharedMemorySize, SMEM_TOTAL);

    fused_kernel<<<GRIDF, THREADS, SMEM_TOTAL>>>(orig, dirs, tmin, tmax,
                                                 W1, b1, W2, b2, V1, c1, V2, c2,
                                                 (float*)d_out);
}

// round 14
// speedup vs baseline: 2.1131x; 1.0097x over previous
#include <cuda_runtime.h>
#include <cuda_bf16.h>
#include <math.h>

#define NR 8192
#define SS 128
#define GRIDF 592            // 4 CTAs/SM x 148 SMs
#define THREADS 128          // 4 warps = 4 independent rays per iteration
#define RAYS_PER_ITER (GRIDF * 4)   // 2368
#define MAXI 4               // ceil(NR / RAYS_PER_ITER)

typedef unsigned int u32;

// ---------------- smem layout (bytes), per CTA ----------------
#define OFF_AH   0                 // 4 warps x 32 rows x 144B (bf16 hi only)
#define OFF_W1H  18432             // W1^T [64n][72 bf16 stride], K row63 = b1
#define OFF_W1L  27648
#define OFF_W2H  36864             // W2^T [16n][72]
#define OFF_W2L  39168
#define OFF_B3H  41472             // V1[0:15]^T shifted: [64n][20 bf16 stride], k0=0
#define OFF_B3L  44032
#define OFF_B4H  46592             // V2^T [8n][72], n>=3 zero
#define OFF_B4L  47744
#define OFF_B2   48896             // b2 (16 f32)
#define OFF_C2   48960             // c2 (8 f32, padded)
#define OFF_RED  48992             // 4 warp partials (dt prologue only)
#define OFF_GB   49024             // g_base table [MAXI*4][64] f32
#define SMEM_TOTAL (OFF_GB + MAXI * 4 * 64 * 4)   // 53120

// pack 2 floats -> bf16x2 in ONE instruction (low = x, high = y)
static __device__ __forceinline__ u32 pkbf2(float x, float y) {
    u32 r;
    asm("cvt.rn.satfinite.bf16x2.f32 %0, %1, %2;" : "=r"(r) : "f"(y), "f"(x));
    return r;
}
static __device__ __forceinline__ void mma4(float* d, const u32* a, u32 b0, u32 b1) {
    asm volatile(
        "mma.sync.aligned.m16n8k16.row.col.f32.bf16.bf16.f32 "
        "{%0,%1,%2,%3}, {%4,%5,%6,%7}, {%8,%9}, {%0,%1,%2,%3};"
        : "+f"(d[0]), "+f"(d[1]), "+f"(d[2]), "+f"(d[3])
        : "r"(a[0]), "r"(a[1]), "r"(a[2]), "r"(a[3]), "r"(b0), "r"(b1));
}

// ---------------------------------------------------------------------------
// Fused ray-marcher, single kernel, warp-autonomous rays.
// CTA prologue: dt + weights + g_base table (barriers only here).
// Main loop: warp w owns ray blockIdx.x*4 + w + i*RAYS_PER_ITER; processes it
// in 4 chunks of 32 samples with the transmittance scan carried in registers.
// NO __syncthreads in the main loop.
// ---------------------------------------------------------------------------
__global__ __launch_bounds__(THREADS, 4)
void fused_kernel(const float* __restrict__ orig, const float* __restrict__ dirs,
                  const float* __restrict__ tmin, const float* __restrict__ tmax,
                  const float* __restrict__ W1, const float* __restrict__ b1,
                  const float* __restrict__ W2, const float* __restrict__ b2,
                  const float* __restrict__ V1, const float* __restrict__ c1,
                  const float* __restrict__ V2, const float* __restrict__ c2,
                  float* __restrict__ outp) {
    extern __shared__ char dsm[];
    const int tid = threadIdx.x;
    const int w = tid >> 5, lane = tid & 31, g = lane >> 2, tig = lane & 3;
    const u32 FULL = 0xffffffffu;

    // ---------------- dt = mean(tmax - tmin)/SS (per-CTA, same order) -------
    float dtv;
    {
        float s = 0.f;
        const float4* a4p = (const float4*)tmin;
        const float4* b4p = (const float4*)tmax;
#pragma unroll 1
        for (int i = tid; i < NR / 4; i += THREADS) {
            float4 x = a4p[i], y = b4p[i];
            s += (y.x - x.x) + (y.y - x.y) + (y.z - x.z) + (y.w - x.w);
        }
#pragma unroll
        for (int o = 16; o > 0; o >>= 1) s += __shfl_down_sync(FULL, s, o);
        float* red = (float*)(dsm + OFF_RED);
        if (lane == 0) red[w] = s;
        __syncthreads();
        dtv = (red[0] + red[1] + red[2] + red[3]) / (float)(NR * SS);
        __syncthreads();
    }

    // ---------------- stage weights: split bf16 hi/lo, K-major padded ------
    for (int i = tid; i < 64 * 64; i += THREADS) {            // W1^T; row63 = b1
        int n = i >> 6, k = i & 63;
        float v = (k < 63) ? W1[k * 64 + n] : b1[n];
        __nv_bfloat16 h = __float2bfloat16(v);
        *(__nv_bfloat16*)(dsm + OFF_W1H + n * 144 + k * 2) = h;
        *(__nv_bfloat16*)(dsm + OFF_W1L + n * 144 + k * 2) =
            __float2bfloat16(v - __bfloat162float(h));
    }
    for (int i = tid; i < 16 * 64; i += THREADS) {            // W2^T
        int n = i >> 6, k = i & 63;
        float v = W2[k * 16 + n];
        __nv_bfloat16 h = __float2bfloat16(v);
        *(__nv_bfloat16*)(dsm + OFF_W2H + n * 144 + k * 2) = h;
        *(__nv_bfloat16*)(dsm + OFF_W2L + n * 144 + k * 2) =
            __float2bfloat16(v - __bfloat162float(h));
    }
    for (int i = tid; i < 64 * 16; i += THREADS) {            // B3 = shifted V1[0:15]^T
        int n = i >> 4, k = i & 15;
        float v = (k >= 1) ? V1[(k - 1) * 64 + n] : 0.f;
        __nv_bfloat16 h = __float2bfloat16(v);
        *(__nv_bfloat16*)(dsm + OFF_B3H + n * 40 + k * 2) = h;
        *(__nv_bfloat16*)(dsm + OFF_B3L + n * 40 + k * 2) =
            __float2bfloat16(v - __bfloat162float(h));
    }
    for (int i = tid; i < 8 * 64; i += THREADS) {             // B4 = V2^T, n pad 8
        int n = i >> 6, k = i & 63;
        float v = (n < 3) ? V2[k * 3 + n] : 0.f;
        __nv_bfloat16 h = __float2bfloat16(v);
        *(__nv_bfloat16*)(dsm + OFF_B4H + n * 144 + k * 2) = h;
        *(__nv_bfloat16*)(dsm + OFF_B4L + n * 144 + k * 2) =
            __float2bfloat16(v - __bfloat162float(h));
    }
    if (tid < 16) ((float*)(dsm + OFF_B2))[tid] = b2[tid];
    if (tid < 8)  ((float*)(dsm + OFF_C2))[tid] = (tid < 3) ? c2[tid] : 0.f;

    // ---------------- per-CTA g_base table (entry e = i*4 + warp) -----------
    {
        const int j = tid & 63;
        float* gbt = (float*)(dsm + OFF_GB);
#pragma unroll 1
        for (int e = tid >> 6; e < MAXI * 4; e += 2) {
            const int ray = blockIdx.x * 4 + (e & 3) + (e >> 2) * RAYS_PER_ITER;
            if (ray >= NR) continue;
            const float dx = dirs[ray * 3 + 0], dy = dirs[ray * 3 + 1], dz = dirs[ray * 3 + 2];
            const float nrm = sqrtf(dx * dx + dy * dy + dz * dz) + 1e-8f;
            const float inv = 1.0f / nrm;
            const float vx = dx * inv, vy = dy * inv, vz = dz * inv;
            float v[27];
            v[0] = vx; v[1] = vy; v[2] = vz;
            {
                float sx, cx, sy, cy, sz, cz;
                sincosf(vx, &sx, &cx); sincosf(vy, &sy, &cy); sincosf(vz, &sz, &cz);
#pragma unroll
                for (int i = 0; i < 4; i++) {
                    v[3 + 6 * i + 0] = sx; v[3 + 6 * i + 1] = sy; v[3 + 6 * i + 2] = sz;
                    v[3 + 6 * i + 3] = cx; v[3 + 6 * i + 4] = cy; v[3 + 6 * i + 5] = cz;
                    const float nsx = 2.f * sx * cx, ncx = fmaf(-2.f * sx, sx, 1.f);
                    const float nsy = 2.f * sy * cy, ncy = fmaf(-2.f * sy, sy, 1.f);
                    const float nsz = 2.f * sz * cz, ncz = fmaf(-2.f * sz, sz, 1.f);
                    sx = nsx; cx = ncx; sy = nsy; cy = ncy; sz = nsz; cz = ncz;
                }
            }
            float acc0 = c1[j];
#pragma unroll 1
            for (int i = 0; i < 27; i++) acc0 = fmaf(v[i], V1[(15 + i) * 64 + j], acc0);
            gbt[e * 64 + j] = acc0;
        }
    }
    __syncthreads();   // last CTA-wide barrier — main loop is warp-autonomous

    char* const Ah_base = dsm + OFF_AH + w * 4608;

#pragma unroll 1
    for (int it = 0; it < MAXI; it++) {
        const int ray = blockIdx.x * 4 + w + it * RAYS_PER_ITER;
        if (ray >= NR) break;

        const float dx = dirs[ray * 3 + 0], dy = dirs[ray * 3 + 1], dz = dirs[ray * 3 + 2];
        const float ox = orig[ray * 3 + 0], oy = orig[ray * 3 + 1], oz = orig[ray * 3 + 2];
        const float t0 = tmin[ray], t1 = tmax[ray];
        const float* gb = (const float*)(dsm + OFF_GB) + (it * 4 + w) * 64;

        float carry = 1.f, ftacc = 1.f, sr = 0.f, sg2 = 0.f, sb = 0.f;

#pragma unroll 1
        for (int chunk = 0; chunk < 4; chunk++) {
            const int s = chunk * 32 + lane;

            // ------------ positional encoding (fast sincos), row = lane -----
            const float tt = t0 + (float)s * (1.0f / (SS - 1)) * (t1 - t0);
            float enc[64];
            enc[0] = fmaf(dx, tt, ox);
            enc[1] = fmaf(dy, tt, oy);
            enc[2] = fmaf(dz, tt, oz);
            {
                float sx, cx, sy, cy, sz, cz;
                __sincosf(enc[0], &sx, &cx);
                __sincosf(enc[1], &sy, &cy);
                __sincosf(enc[2], &sz, &cz);
#pragma unroll
                for (int i = 0; i < 10; i++) {
                    enc[3 + 6 * i + 0] = sx; enc[3 + 6 * i + 1] = sy; enc[3 + 6 * i + 2] = sz;
                    enc[3 + 6 * i + 3] = cx; enc[3 + 6 * i + 4] = cy; enc[3 + 6 * i + 5] = cz;
                    const float nsx = 2.f * sx * cx, ncx = fmaf(-2.f * sx, sx, 1.f);
                    const float nsy = 2.f * sy * cy, ncy = fmaf(-2.f * sy, sy, 1.f);
                    const float nsz = 2.f * sz * cz, ncz = fmaf(-2.f * sz, sz, 1.f);
                    sx = nsx; cx = ncx; sy = nsy; cy = ncy; sz = nsz; cz = ncz;
                }
            }
            enc[63] = 1.0f;     // bias column: W1 row63 = b1
            {
                char* Ah = Ah_base + lane * 144;
#pragma unroll
                for (int j8 = 0; j8 < 8; j8++) {
                    *(uint4*)(Ah + j8 * 16) = make_uint4(
                        pkbf2(enc[8 * j8 + 0], enc[8 * j8 + 1]),
                        pkbf2(enc[8 * j8 + 2], enc[8 * j8 + 3]),
                        pkbf2(enc[8 * j8 + 4], enc[8 * j8 + 5]),
                        pkbf2(enc[8 * j8 + 6], enc[8 * j8 + 7]));
                }
            }
            __syncwarp();

            // ------------ MLP1: enc(64) @ W1 -> 32x64 (2-pass) --------------
            float acc[2][8][4];
#pragma unroll
            for (int mt = 0; mt < 2; mt++)
#pragma unroll
                for (int nt = 0; nt < 8; nt++)
#pragma unroll
                    for (int r = 0; r < 4; r++) acc[mt][nt][r] = 0.f;

#pragma unroll
            for (int kt = 0; kt < 4; kt++) {
                u32 AH[2][4];
#pragma unroll
                for (int mt = 0; mt < 2; mt++) {
                    int ab = mt * 2304 + g * 144 + kt * 32 + tig * 4;
                    AH[mt][0] = *(const u32*)(Ah_base + ab);
                    AH[mt][1] = *(const u32*)(Ah_base + ab + 1152);
                    AH[mt][2] = *(const u32*)(Ah_base + ab + 16);
                    AH[mt][3] = *(const u32*)(Ah_base + ab + 1168);
                }
#pragma unroll
                for (int nt = 0; nt < 8; nt++) {
                    int bo = (nt * 8 + g) * 144 + kt * 32 + tig * 4;
                    u32 bh0 = *(const u32*)(dsm + OFF_W1H + bo);
                    u32 bh1 = *(const u32*)(dsm + OFF_W1H + bo + 16);
                    u32 bl0 = *(const u32*)(dsm + OFF_W1L + bo);
                    u32 bl1 = *(const u32*)(dsm + OFF_W1L + bo + 16);
#pragma unroll
                    for (int mt = 0; mt < 2; mt++) {
                        mma4(acc[mt][nt], AH[mt], bh0, bh1);
                        mma4(acc[mt][nt], AH[mt], bl0, bl1);
                    }
                }
            }
            __syncwarp();   // A-tile reads done before next chunk's writes

            // ------------ epi1: h = relu(D) -> hi frags ---------------------
            u32 HF[2][4][4];
#pragma unroll
            for (int kt = 0; kt < 4; kt++)
#pragma unroll
                for (int j = 0; j < 2; j++) {
                    const int nt = 2 * kt + j;
#pragma unroll
                    for (int mt = 0; mt < 2; mt++) {
                        float v0 = fmaxf(acc[mt][nt][0], 0.f);
                        float v1 = fmaxf(acc[mt][nt][1], 0.f);
                        float v2 = fmaxf(acc[mt][nt][2], 0.f);
                        float v3 = fmaxf(acc[mt][nt][3], 0.f);
                        HF[mt][kt][2 * j + 0] = pkbf2(v0, v1);
                        HF[mt][kt][2 * j + 1] = pkbf2(v2, v3);
                    }
                }

            // ------------ MLP2: h @ W2 -> 32x16 (2-pass) --------------------
            float a2c[2][2][4];
#pragma unroll
            for (int mt = 0; mt < 2; mt++)
#pragma unroll
                for (int n2 = 0; n2 < 2; n2++)
#pragma unroll
                    for (int r = 0; r < 4; r++) a2c[mt][n2][r] = 0.f;
#pragma unroll
            for (int kt = 0; kt < 4; kt++)
#pragma unroll
                for (int n2 = 0; n2 < 2; n2++) {
                    int bo = (n2 * 8 + g) * 144 + kt * 32 + tig * 4;
                    u32 bh0 = *(const u32*)(dsm + OFF_W2H + bo);
                    u32 bh1 = *(const u32*)(dsm + OFF_W2H + bo + 16);
                    u32 bl0 = *(const u32*)(dsm + OFF_W2L + bo);
                    u32 bl1 = *(const u32*)(dsm + OFF_W2L + bo + 16);
#pragma unroll
                    for (int mt = 0; mt < 2; mt++) {
                        mma4(a2c[mt][n2], HF[mt][kt], bh0, bh1);
                        mma4(a2c[mt][n2], HF[mt][kt], bl0, bl1);
                    }
                }

            // ------------ epi2: sigma raw + feat hi frags -------------------
            float sgm[2][2];
            u32 FF[2][4];
            {
                const float2 b20 = *(const float2*)(dsm + OFF_B2 + tig * 8);
                const float2 b21 = *(const float2*)(dsm + OFF_B2 + 32 + tig * 8);
#pragma unroll
                for (int mt = 0; mt < 2; mt++) {
                    float v0 = a2c[mt][0][0] + b20.x;
                    float v1 = a2c[mt][0][1] + b20.y;
                    float v2 = a2c[mt][0][2] + b20.x;
                    float v3 = a2c[mt][0][3] + b20.y;
                    float u0 = a2c[mt][1][0] + b21.x;
                    float u1 = a2c[mt][1][1] + b21.y;
                    float u2 = a2c[mt][1][2] + b21.x;
                    float u3 = a2c[mt][1][3] + b21.y;
                    sgm[mt][0] = v0;
                    sgm[mt][1] = v2;
                    FF[mt][0] = pkbf2(v0, v1);
                    FF[mt][1] = pkbf2(v2, v3);
                    FF[mt][2] = pkbf2(u0, u1);
                    FF[mt][3] = pkbf2(u2, u3);
                }
            }

            // ------------ MLP3: feats(16) @ B3 -> 32x64 (2-pass) ------------
            float a3c[2][8][4];
#pragma unroll
            for (int mt = 0; mt < 2; mt++)
#pragma unroll
                for (int nt = 0; nt < 8; nt++)
#pragma unroll
                    for (int r = 0; r < 4; r++) a3c[mt][nt][r] = 0.f;
#pragma unroll
            for (int nt = 0; nt < 8; nt++) {
                int bo = (nt * 8 + g) * 40 + tig * 4;
                u32 bh0 = *(const u32*)(dsm + OFF_B3H + bo);
                u32 bh1 = *(const u32*)(dsm + OFF_B3H + bo + 16);
                u32 bl0 = *(const u32*)(dsm + OFF_B3L + bo);
                u32 bl1 = *(const u32*)(dsm + OFF_B3L + bo + 16);
#pragma unroll
                for (int mt = 0; mt < 2; mt++) {
                    mma4(a3c[mt][nt], FF[mt], bh0, bh1);
                    mma4(a3c[mt][nt], FF[mt], bl0, bl1);
                }
            }

            // ------------ epi3: g = relu(D + g_base) -> hi frags ------------
            u32 GF[2][4][4];
#pragma unroll
            for (int kt = 0; kt < 4; kt++)
#pragma unroll
                for (int j = 0; j < 2; j++) {
                    const int nt = 2 * kt + j;
                    const float2 gv = *(const float2*)(gb + nt * 8 + tig * 2);
#pragma unroll
                    for (int mt = 0; mt < 2; mt++) {
                        float v0 = fmaxf(a3c[mt][nt][0] + gv.x, 0.f);
                        float v1 = fmaxf(a3c[mt][nt][1] + gv.y, 0.f);
                        float v2 = fmaxf(a3c[mt][nt][2] + gv.x, 0.f);
                        float v3 = fmaxf(a3c[mt][nt][3] + gv.y, 0.f);
                        GF[mt][kt][2 * j + 0] = pkbf2(v0, v1);
                        GF[mt][kt][2 * j + 1] = pkbf2(v2, v3);
                    }
                }

            // ------------ MLP4: g @ V2 -> 32x8 (2-pass) ---------------------
            float a4[2][4];
#pragma unroll
            for (int mt = 0; mt < 2; mt++)
#pragma unroll
                for (int r = 0; r < 4; r++) a4[mt][r] = 0.f;
#pragma unroll
            for (int kt = 0; kt < 4; kt++) {
                int bo = g * 144 + kt * 32 + tig * 4;
                u32 bh0 = *(const u32*)(dsm + OFF_B4H + bo);
                u32 bh1 = *(const u32*)(dsm + OFF_B4H + bo + 16);
                u32 bl0 = *(const u32*)(dsm + OFF_B4L + bo);
                u32 bl1 = *(const u32*)(dsm + OFF_B4L + bo + 16);
#pragma unroll
                for (int mt = 0; mt < 2; mt++) {
                    mma4(a4[mt], GF[mt][kt], bh0, bh1);
                    mma4(a4[mt], GF[mt][kt], bl0, bl1);
                }
            }

            // ------------ epi4 + redistribution lane<->row ------------------
            float o0[2], o1[2], o2[2], o3[2];
            {
                const float2 cc = *(const float2*)(dsm + OFF_C2 + tig * 8);
#pragma unroll
                for (int mt = 0; mt < 2; mt++) {
                    o0[mt] = a4[mt][0] + cc.x;
                    o1[mt] = a4[mt][1] + cc.y;
                    o2[mt] = a4[mt][2] + cc.x;
                    o3[mt] = a4[mt][3] + cc.y;
                }
            }
            const int q4 = (lane & 7) * 4;
            const int selv = lane >> 3;
            float x0, x1, x2, x3;
            x0 = __shfl_sync(FULL, sgm[0][0], q4);
            x1 = __shfl_sync(FULL, sgm[0][1], q4);
            x2 = __shfl_sync(FULL, sgm[1][0], q4);
            x3 = __shfl_sync(FULL, sgm[1][1], q4);
            const float sigma = fmaxf(selv == 0 ? x0 : selv == 1 ? x1 : selv == 2 ? x2 : x3, 0.f);
            x0 = __shfl_sync(FULL, o0[0], q4);
            x1 = __shfl_sync(FULL, o2[0], q4);
            x2 = __shfl_sync(FULL, o0[1], q4);
            x3 = __shfl_sync(FULL, o2[1], q4);
            const float rv = selv == 0 ? x0 : selv == 1 ? x1 : selv == 2 ? x2 : x3;
            x0 = __shfl_sync(FULL, o1[0], q4);
            x1 = __shfl_sync(FULL, o3[0], q4);
            x2 = __shfl_sync(FULL, o1[1], q4);
            x3 = __shfl_sync(FULL, o3[1], q4);
            const float gvv = selv == 0 ? x0 : selv == 1 ? x1 : selv == 2 ? x2 : x3;
            x0 = __shfl_sync(FULL, o0[0], q4 + 1);
            x1 = __shfl_sync(FULL, o2[0], q4 + 1);
            x2 = __shfl_sync(FULL, o0[1], q4 + 1);
            x3 = __shfl_sync(FULL, o2[1], q4 + 1);
            const float bv = selv == 0 ? x0 : selv == 1 ? x1 : selv == 2 ? x2 : x3;
            const float rr = 1.f / (1.f + __expf(-rv));
            const float rg = 1.f / (1.f + __expf(-gvv));
            const float rb = 1.f / (1.f + __expf(-bv));

            // ------------ in-register transmittance scan (this chunk) -------
            const float ex = __expf(-sigma * dtv);      // one_minus
            const float alpha = 1.f - ex;
            float p = ex;
#pragma unroll
            for (int o = 1; o < 32; o <<= 1) {
                float q = __shfl_up_sync(FULL, p, o);
                if (lane >= o) p *= q;
            }
            const float pm1 = __shfl_up_sync(FULL, p, 1);
            const float excl = carry * ((lane == 0) ? 1.f : pm1);   // T_excl
            const bool active = excl > 1e-4f;
            const float wgt = active ? excl * alpha : 0.f;
            sr  = fmaf(wgt, rr, sr);
            sg2 = fmaf(wgt, rg, sg2);
            sb  = fmaf(wgt, rb, sb);
            ftacc *= active ? ex : 1.f;
            carry *= __shfl_sync(FULL, p, 31);
        }

        // ---------------- final per-ray reduction (in-warp) -----------------
#pragma unroll
        for (int o = 16; o > 0; o >>= 1) {
            sr  += __shfl_xor_sync(FULL, sr, o);
            sg2 += __shfl_xor_sync(FULL, sg2, o);
            sb  += __shfl_xor_sync(FULL, sb, o);
            ftacc *= __shfl_xor_sync(FULL, ftacc, o);
        }
        if (lane == 0) {
            outp[ray * 3 + 0] = sr;
            outp[ray * 3 + 1] = sg2;
            outp[ray * 3 + 2] = sb;
            outp[3 * NR + ray] = ftacc;
        }
    }
}

// ---------------------------------------------------------------------------
extern "C" void kernel_launch(void* const* d_in, const int* in_sizes, int n_in,
                              void* d_out, int out_size) {
    const float* orig = (const float*)d_in[0];
    const float* dirs = (const float*)d_in[1];
    const float* tmin = (const float*)d_in[2];
    const float* tmax = (const float*)d_in[3];
    const float* W1   = (const float*)d_in[4];
    const float* b1   = (const float*)d_in[5];
    const float* W2   = (const float*)d_in[6];
    const float* b2   = (const float*)d_in[7];
    const float* V1   = (const float*)d_in[8];
    const float* c1   = (const float*)d_in[9];
    const float* V2   = (const float*)d_in[10];
    const float* c2   = (const float*)d_in[11];

    cudaFuncSetAttribute(fused_kernel, cudaFuncAttributeMaxDynamicSharedMemorySize, SMEM_TOTAL);

    fused_kernel<<<GRIDF, THREADS, SMEM_TOTAL>>>(orig, dirs, tmin, tmax,
                                                 W1, b1, W2, b2, V1, c1, V2, c2,
                                                 (float*)d_out);
}

// round 15
// speedup vs baseline: 2.2584x; 1.0687x over previous
#include <cuda_runtime.h>
#include <cuda_bf16.h>
#include <math.h>

#define NR 8192
#define SS 128
#define GRIDF 592            // 4 CTAs/SM x 148 SMs
#define THREADS 128          // 4 warps = 4 independent rays per iteration
#define RAYS_PER_ITER (GRIDF * 4)   // 2368
#define MAXI 4               // ceil(NR / RAYS_PER_ITER)

typedef unsigned int u32;

// ---------------- smem layout (bytes), per CTA ----------------
// Packed B-fragments: per fragment-set fs, per lane: 16B = {bh0,bh1,bl0,bl1}
#define OFF_AH   0                 // 4 warps x 32 rows x 144B (bf16 hi only)
#define OFF_W1P  18432             // 32 sets (kt*8+nt) x 512B          = 16384
#define OFF_W2P  34816             // 8 sets (kt*2+n2) x 512B           = 4096
#define OFF_B3P  38912             // 8 sets (nt) x 512B                = 4096
#define OFF_B4P  43008             // 4 sets (kt) x 512B                = 2048
#define OFF_B2   45056             // b2 (16 f32)
#define OFF_C2   45120             // c2 (8 f32, padded)
#define OFF_RED  45152             // 4 warp partials (dt prologue only)
#define OFF_GB   45184             // g_base table [MAXI*4][64] f32     = 4096
#define SMEM_TOTAL (OFF_GB + MAXI * 4 * 64 * 4)   // 49280

// pack 2 floats -> bf16x2 in ONE instruction (low = x, high = y)
static __device__ __forceinline__ u32 pkbf2(float x, float y) {
    u32 r;
    asm("cvt.rn.satfinite.bf16x2.f32 %0, %1, %2;" : "=r"(r) : "f"(y), "f"(x));
    return r;
}
// hi/lo split of two floats -> packed hi word + packed lo word
static __device__ __forceinline__ void hisplit(float a, float b, u32& hi, u32& lo) {
    const float ha = __bfloat162float(__float2bfloat16(a));
    const float hb = __bfloat162float(__float2bfloat16(b));
    hi = pkbf2(ha, hb);              // exact (values already bf16)
    lo = pkbf2(a - ha, b - hb);
}
static __device__ __forceinline__ void mma4(float* d, const u32* a, u32 b0, u32 b1) {
    asm volatile(
        "mma.sync.aligned.m16n8k16.row.col.f32.bf16.bf16.f32 "
        "{%0,%1,%2,%3}, {%4,%5,%6,%7}, {%8,%9}, {%0,%1,%2,%3};"
        : "+f"(d[0]), "+f"(d[1]), "+f"(d[2]), "+f"(d[3])
        : "r"(a[0]), "r"(a[1]), "r"(a[2]), "r"(a[3]), "r"(b0), "r"(b1));
}

// ---------------------------------------------------------------------------
// Fused ray-marcher, single kernel, warp-autonomous rays, packed B-fragments.
// ---------------------------------------------------------------------------
__global__ __launch_bounds__(THREADS, 4)
void fused_kernel(const float* __restrict__ orig, const float* __restrict__ dirs,
                  const float* __restrict__ tmin, const float* __restrict__ tmax,
                  const float* __restrict__ W1, const float* __restrict__ b1,
                  const float* __restrict__ W2, const float* __restrict__ b2,
                  const float* __restrict__ V1, const float* __restrict__ c1,
                  const float* __restrict__ V2, const float* __restrict__ c2,
                  float* __restrict__ outp) {
    extern __shared__ char dsm[];
    const int tid = threadIdx.x;
    const int w = tid >> 5, lane = tid & 31, g = lane >> 2, tig = lane & 3;
    const u32 FULL = 0xffffffffu;

    // ---------------- dt = mean(tmax - tmin)/SS (per-CTA, same order) -------
    float dtv;
    {
        float s = 0.f;
        const float4* a4p = (const float4*)tmin;
        const float4* b4p = (const float4*)tmax;
#pragma unroll 1
        for (int i = tid; i < NR / 4; i += THREADS) {
            float4 x = a4p[i], y = b4p[i];
            s += (y.x - x.x) + (y.y - x.y) + (y.z - x.z) + (y.w - x.w);
        }
#pragma unroll
        for (int o = 16; o > 0; o >>= 1) s += __shfl_down_sync(FULL, s, o);
        float* red = (float*)(dsm + OFF_RED);
        if (lane == 0) red[w] = s;
        __syncthreads();
        dtv = (red[0] + red[1] + red[2] + red[3]) / (float)(NR * SS);
        __syncthreads();
    }

    // ---------------- pack B-fragments (per-lane 16B, LDS.128-ready) -------
    // W1P: fs = kt*8+nt; n = nt*8+g; k in {k0,k0+1,k0+8,k0+9}, k0=kt*16+tig*2
    // row 63 of W1^T = b1 (bias column).
    for (int idx = tid; idx < 32 * 32; idx += THREADS) {
        const int ln = idx & 31, fs = idx >> 5;
        const int kt = fs >> 3, nt = fs & 7;
        const int gg = ln >> 2, tg = ln & 3;
        const int n = nt * 8 + gg;
        const int k0 = kt * 16 + tg * 2;
        const float a0 = (k0     < 63) ? W1[(k0    ) * 64 + n] : b1[n];
        const float a1 = (k0 + 1 < 63) ? W1[(k0 + 1) * 64 + n] : b1[n];
        const float a8 = (k0 + 8 < 63) ? W1[(k0 + 8) * 64 + n] : b1[n];
        const float a9 = (k0 + 9 < 63) ? W1[(k0 + 9) * 64 + n] : b1[n];
        u32 h0, l0, h1, l1;
        hisplit(a0, a1, h0, l0);
        hisplit(a8, a9, h1, l1);
        *(uint4*)(dsm + OFF_W1P + (fs * 32 + ln) * 16) = make_uint4(h0, h1, l0, l1);
    }
    // W2P: fs = kt*2+n2; n = n2*8+g
    for (int idx = tid; idx < 8 * 32; idx += THREADS) {
        const int ln = idx & 31, fs = idx >> 5;
        const int kt = fs >> 1, n2 = fs & 1;
        const int gg = ln >> 2, tg = ln & 3;
        const int n = n2 * 8 + gg;
        const int k0 = kt * 16 + tg * 2;
        const float a0 = W2[(k0    ) * 16 + n];
        const float a1 = W2[(k0 + 1) * 16 + n];
        const float a8 = W2[(k0 + 8) * 16 + n];
        const float a9 = W2[(k0 + 9) * 16 + n];
        u32 h0, l0, h1, l1;
        hisplit(a0, a1, h0, l0);
        hisplit(a8, a9, h1, l1);
        *(uint4*)(dsm + OFF_W2P + (fs * 32 + ln) * 16) = make_uint4(h0, h1, l0, l1);
    }
    // B3P: fs = nt; K=16 shifted V1[0:15]^T (k=0 -> 0, else V1[k-1])
    for (int idx = tid; idx < 8 * 32; idx += THREADS) {
        const int ln = idx & 31, nt = idx >> 5;
        const int gg = ln >> 2, tg = ln & 3;
        const int n = nt * 8 + gg;
        const int k0 = tg * 2;
        const float a0 = (k0     >= 1) ? V1[(k0     - 1) * 64 + n] : 0.f;
        const float a1 = (k0 + 1 >= 1) ? V1[(k0 + 1 - 1) * 64 + n] : 0.f;
        const float a8 = V1[(k0 + 8 - 1) * 64 + n];
        const float a9 = V1[(k0 + 9 - 1) * 64 + n];
        u32 h0, l0, h1, l1;
        hisplit(a0, a1, h0, l0);
        hisplit(a8, a9, h1, l1);
        *(uint4*)(dsm + OFF_B3P + (nt * 32 + ln) * 16) = make_uint4(h0, h1, l0, l1);
    }
    // B4P: fs = kt; n = g (n>=3 zero)
    for (int idx = tid; idx < 4 * 32; idx += THREADS) {
        const int ln = idx & 31, kt = idx >> 5;
        const int gg = ln >> 2, tg = ln & 3;
        const int k0 = kt * 16 + tg * 2;
        const bool nb = gg < 3;
        const float a0 = nb ? V2[(k0    ) * 3 + gg] : 0.f;
        const float a1 = nb ? V2[(k0 + 1) * 3 + gg] : 0.f;
        const float a8 = nb ? V2[(k0 + 8) * 3 + gg] : 0.f;
        const float a9 = nb ? V2[(k0 + 9) * 3 + gg] : 0.f;
        u32 h0, l0, h1, l1;
        hisplit(a0, a1, h0, l0);
        hisplit(a8, a9, h1, l1);
        *(uint4*)(dsm + OFF_B4P + (kt * 32 + ln) * 16) = make_uint4(h0, h1, l0, l1);
    }
    if (tid < 16) ((float*)(dsm + OFF_B2))[tid] = b2[tid];
    if (tid < 8)  ((float*)(dsm + OFF_C2))[tid] = (tid < 3) ? c2[tid] : 0.f;

    // ---------------- per-CTA g_base table (entry e = i*4 + warp) -----------
    {
        const int j = tid & 63;
        float* gbt = (float*)(dsm + OFF_GB);
#pragma unroll 1
        for (int e = tid >> 6; e < MAXI * 4; e += 2) {
            const int ray = blockIdx.x * 4 + (e & 3) + (e >> 2) * RAYS_PER_ITER;
            if (ray >= NR) continue;
            const float dx = dirs[ray * 3 + 0], dy = dirs[ray * 3 + 1], dz = dirs[ray * 3 + 2];
            const float nrm = sqrtf(dx * dx + dy * dy + dz * dz) + 1e-8f;
            const float inv = 1.0f / nrm;
            const float vx = dx * inv, vy = dy * inv, vz = dz * inv;
            float v[27];
            v[0] = vx; v[1] = vy; v[2] = vz;
            {
                float sx, cx, sy, cy, sz, cz;
                sincosf(vx, &sx, &cx); sincosf(vy, &sy, &cy); sincosf(vz, &sz, &cz);
#pragma unroll
                for (int i = 0; i < 4; i++) {
                    v[3 + 6 * i + 0] = sx; v[3 + 6 * i + 1] = sy; v[3 + 6 * i + 2] = sz;
                    v[3 + 6 * i + 3] = cx; v[3 + 6 * i + 4] = cy; v[3 + 6 * i + 5] = cz;
                    const float nsx = 2.f * sx * cx, ncx = fmaf(-2.f * sx, sx, 1.f);
                    const float nsy = 2.f * sy * cy, ncy = fmaf(-2.f * sy, sy, 1.f);
                    const float nsz = 2.f * sz * cz, ncz = fmaf(-2.f * sz, sz, 1.f);
                    sx = nsx; cx = ncx; sy = nsy; cy = ncy; sz = nsz; cz = ncz;
                }
            }
            float acc0 = c1[j];
#pragma unroll 1
            for (int i = 0; i < 27; i++) acc0 = fmaf(v[i], V1[(15 + i) * 64 + j], acc0);
            gbt[e * 64 + j] = acc0;
        }
    }
    __syncthreads();   // last CTA-wide barrier — main loop is warp-autonomous

    char* const Ah_base = dsm + OFF_AH + w * 4608;
    const uint4* const W1P = (const uint4*)(dsm + OFF_W1P);
    const uint4* const W2P = (const uint4*)(dsm + OFF_W2P);
    const uint4* const B3P = (const uint4*)(dsm + OFF_B3P);
    const uint4* const B4P = (const uint4*)(dsm + OFF_B4P);

#pragma unroll 1
    for (int it = 0; it < MAXI; it++) {
        const int ray = blockIdx.x * 4 + w + it * RAYS_PER_ITER;
        if (ray >= NR) break;

        const float dx = dirs[ray * 3 + 0], dy = dirs[ray * 3 + 1], dz = dirs[ray * 3 + 2];
        const float ox = orig[ray * 3 + 0], oy = orig[ray * 3 + 1], oz = orig[ray * 3 + 2];
        const float t0 = tmin[ray], t1 = tmax[ray];
        const float* gb = (const float*)(dsm + OFF_GB) + (it * 4 + w) * 64;

        float carry = 1.f, ftacc = 1.f, sr = 0.f, sg2 = 0.f, sb = 0.f;

#pragma unroll 1
        for (int chunk = 0; chunk < 4; chunk++) {
            const int s = chunk * 32 + lane;

            // ------------ positional encoding (fast sincos), row = lane -----
            const float tt = t0 + (float)s * (1.0f / (SS - 1)) * (t1 - t0);
            float enc[64];
            enc[0] = fmaf(dx, tt, ox);
            enc[1] = fmaf(dy, tt, oy);
            enc[2] = fmaf(dz, tt, oz);
            {
                float sx, cx, sy, cy, sz, cz;
                __sincosf(enc[0], &sx, &cx);
                __sincosf(enc[1], &sy, &cy);
                __sincosf(enc[2], &sz, &cz);
#pragma unroll
                for (int i = 0; i < 10; i++) {
                    enc[3 + 6 * i + 0] = sx; enc[3 + 6 * i + 1] = sy; enc[3 + 6 * i + 2] = sz;
                    enc[3 + 6 * i + 3] = cx; enc[3 + 6 * i + 4] = cy; enc[3 + 6 * i + 5] = cz;
                    const float nsx = 2.f * sx * cx, ncx = fmaf(-2.f * sx, sx, 1.f);
                    const float nsy = 2.f * sy * cy, ncy = fmaf(-2.f * sy, sy, 1.f);
                    const float nsz = 2.f * sz * cz, ncz = fmaf(-2.f * sz, sz, 1.f);
                    sx = nsx; cx = ncx; sy = nsy; cy = ncy; sz = nsz; cz = ncz;
                }
            }
            enc[63] = 1.0f;     // bias column: W1 row63 = b1
            {
                char* Ah = Ah_base + lane * 144;
#pragma unroll
                for (int j8 = 0; j8 < 8; j8++) {
                    *(uint4*)(Ah + j8 * 16) = make_uint4(
                        pkbf2(enc[8 * j8 + 0], enc[8 * j8 + 1]),
                        pkbf2(enc[8 * j8 + 2], enc[8 * j8 + 3]),
                        pkbf2(enc[8 * j8 + 4], enc[8 * j8 + 5]),
                        pkbf2(enc[8 * j8 + 6], enc[8 * j8 + 7]));
                }
            }
            __syncwarp();

            // ------------ MLP1: enc(64) @ W1 -> 32x64 (2-pass) --------------
            float acc[2][8][4];
#pragma unroll
            for (int mt = 0; mt < 2; mt++)
#pragma unroll
                for (int nt = 0; nt < 8; nt++)
#pragma unroll
                    for (int r = 0; r < 4; r++) acc[mt][nt][r] = 0.f;

#pragma unroll
            for (int kt = 0; kt < 4; kt++) {
                u32 AH[2][4];
#pragma unroll
                for (int mt = 0; mt < 2; mt++) {
                    int ab = mt * 2304 + g * 144 + kt * 32 + tig * 4;
                    AH[mt][0] = *(const u32*)(Ah_base + ab);
                    AH[mt][1] = *(const u32*)(Ah_base + ab + 1152);
                    AH[mt][2] = *(const u32*)(Ah_base + ab + 16);
                    AH[mt][3] = *(const u32*)(Ah_base + ab + 1168);
                }
#pragma unroll
                for (int nt = 0; nt < 8; nt++) {
                    const uint4 bq = W1P[(kt * 8 + nt) * 32 + lane];
#pragma unroll
                    for (int mt = 0; mt < 2; mt++) {
                        mma4(acc[mt][nt], AH[mt], bq.x, bq.y);
                        mma4(acc[mt][nt], AH[mt], bq.z, bq.w);
                    }
                }
            }
            __syncwarp();   // A-tile reads done before next chunk's writes

            // ------------ epi1: h = relu(D) -> hi frags ---------------------
            u32 HF[2][4][4];
#pragma unroll
            for (int kt = 0; kt < 4; kt++)
#pragma unroll
                for (int j = 0; j < 2; j++) {
                    const int nt = 2 * kt + j;
#pragma unroll
                    for (int mt = 0; mt < 2; mt++) {
                        float v0 = fmaxf(acc[mt][nt][0], 0.f);
                        float v1 = fmaxf(acc[mt][nt][1], 0.f);
                        float v2 = fmaxf(acc[mt][nt][2], 0.f);
                        float v3 = fmaxf(acc[mt][nt][3], 0.f);
                        HF[mt][kt][2 * j + 0] = pkbf2(v0, v1);
                        HF[mt][kt][2 * j + 1] = pkbf2(v2, v3);
                    }
                }

            // ------------ MLP2: h @ W2 -> 32x16 (2-pass) --------------------
            float a2c[2][2][4];
#pragma unroll
            for (int mt = 0; mt < 2; mt++)
#pragma unroll
                for (int n2 = 0; n2 < 2; n2++)
#pragma unroll
                    for (int r = 0; r < 4; r++) a2c[mt][n2][r] = 0.f;
#pragma unroll
            for (int kt = 0; kt < 4; kt++)
#pragma unroll
                for (int n2 = 0; n2 < 2; n2++) {
                    const uint4 bq = W2P[(kt * 2 + n2) * 32 + lane];
#pragma unroll
                    for (int mt = 0; mt < 2; mt++) {
                        mma4(a2c[mt][n2], HF[mt][kt], bq.x, bq.y);
                        mma4(a2c[mt][n2], HF[mt][kt], bq.z, bq.w);
                    }
                }

            // ------------ epi2: sigma raw + feat hi frags -------------------
            float sgm[2][2];
            u32 FF[2][4];
            {
                const float2 b20 = *(const float2*)(dsm + OFF_B2 + tig * 8);
                const float2 b21 = *(const float2*)(dsm + OFF_B2 + 32 + tig * 8);
#pragma unroll
                for (int mt = 0; mt < 2; mt++) {
                    float v0 = a2c[mt][0][0] + b20.x;
                    float v1 = a2c[mt][0][1] + b20.y;
                    float v2 = a2c[mt][0][2] + b20.x;
                    float v3 = a2c[mt][0][3] + b20.y;
                    float u0 = a2c[mt][1][0] + b21.x;
                    float u1 = a2c[mt][1][1] + b21.y;
                    float u2 = a2c[mt][1][2] + b21.x;
                    float u3 = a2c[mt][1][3] + b21.y;
                    sgm[mt][0] = v0;
                    sgm[mt][1] = v2;
                    FF[mt][0] = pkbf2(v0, v1);
                    FF[mt][1] = pkbf2(v2, v3);
                    FF[mt][2] = pkbf2(u0, u1);
                    FF[mt][3] = pkbf2(u2, u3);
                }
            }

            // ------------ MLP3: feats(16) @ B3 -> 32x64 (2-pass) ------------
            float a3c[2][8][4];
#pragma unroll
            for (int mt = 0; mt < 2; mt++)
#pragma unroll
                for (int nt = 0; nt < 8; nt++)
#pragma unroll
                    for (int r = 0; r < 4; r++) a3c[mt][nt][r] = 0.f;
#pragma unroll
            for (int nt = 0; nt < 8; nt++) {
                const uint4 bq = B3P[nt * 32 + lane];
#pragma unroll
                for (int mt = 0; mt < 2; mt++) {
                    mma4(a3c[mt][nt], FF[mt], bq.x, bq.y);
                    mma4(a3c[mt][nt], FF[mt], bq.z, bq.w);
                }
            }

            // ------------ epi3: g = relu(D + g_base) -> hi frags ------------
            u32 GF[2][4][4];
#pragma unroll
            for (int kt = 0; kt < 4; kt++)
#pragma unroll
                for (int j = 0; j < 2; j++) {
                    const int nt = 2 * kt + j;
                    const float2 gv = *(const float2*)(gb + nt * 8 + tig * 2);
#pragma unroll
                    for (int mt = 0; mt < 2; mt++) {
                        float v0 = fmaxf(a3c[mt][nt][0] + gv.x, 0.f);
                        float v1 = fmaxf(a3c[mt][nt][1] + gv.y, 0.f);
                        float v2 = fmaxf(a3c[mt][nt][2] + gv.x, 0.f);
                        float v3 = fmaxf(a3c[mt][nt][3] + gv.y, 0.f);
                        GF[mt][kt][2 * j + 0] = pkbf2(v0, v1);
                        GF[mt][kt][2 * j + 1] = pkbf2(v2, v3);
                    }
                }

            // ------------ MLP4: g @ V2 -> 32x8 (2-pass) ---------------------
            float a4[2][4];
#pragma unroll
            for (int mt = 0; mt < 2; mt++)
#pragma unroll
                for (int r = 0; r < 4; r++) a4[mt][r] = 0.f;
#pragma unroll
            for (int kt = 0; kt < 4; kt++) {
                const uint4 bq = B4P[kt * 32 + lane];
#pragma unroll
                for (int mt = 0; mt < 2; mt++) {
                    mma4(a4[mt], GF[mt][kt], bq.x, bq.y);
                    mma4(a4[mt], GF[mt][kt], bq.z, bq.w);
                }
            }

            // ------------ epi4 + redistribution lane<->row ------------------
            float o0[2], o1[2], o2[2], o3[2];
            {
                const float2 cc = *(const float2*)(dsm + OFF_C2 + tig * 8);
#pragma unroll
                for (int mt = 0; mt < 2; mt++) {
                    o0[mt] = a4[mt][0] + cc.x;
                    o1[mt] = a4[mt][1] + cc.y;
                    o2[mt] = a4[mt][2] + cc.x;
                    o3[mt] = a4[mt][3] + cc.y;
                }
            }
            const int q4 = (lane & 7) * 4;
            const int selv = lane >> 3;
            float x0, x1, x2, x3;
            x0 = __shfl_sync(FULL, sgm[0][0], q4);
            x1 = __shfl_sync(FULL, sgm[0][1], q4);
            x2 = __shfl_sync(FULL, sgm[1][0], q4);
            x3 = __shfl_sync(FULL, sgm[1][1], q4);
            const float sigma = fmaxf(selv == 0 ? x0 : selv == 1 ? x1 : selv == 2 ? x2 : x3, 0.f);
            x0 = __shfl_sync(FULL, o0[0], q4);
            x1 = __shfl_sync(FULL, o2[0], q4);
            x2 = __shfl_sync(FULL, o0[1], q4);
            x3 = __shfl_sync(FULL, o2[1], q4);
            const float rv = selv == 0 ? x0 : selv == 1 ? x1 : selv == 2 ? x2 : x3;
            x0 = __shfl_sync(FULL, o1[0], q4);
            x1 = __shfl_sync(FULL, o3[0], q4);
            x2 = __shfl_sync(FULL, o1[1], q4);
            x3 = __shfl_sync(FULL, o3[1], q4);
            const float gvv = selv == 0 ? x0 : selv == 1 ? x1 : selv == 2 ? x2 : x3;
            x0 = __shfl_sync(FULL, o0[0], q4 + 1);
            x1 = __shfl_sync(FULL, o2[0], q4 + 1);
            x2 = __shfl_sync(FULL, o0[1], q4 + 1);
            x3 = __shfl_sync(FULL, o2[1], q4 + 1);
            const float bv = selv == 0 ? x0 : selv == 1 ? x1 : selv == 2 ? x2 : x3;
            const float rr = 1.f / (1.f + __expf(-rv));
            const float rg = 1.f / (1.f + __expf(-gvv));
            const float rb = 1.f / (1.f + __expf(-bv));

            // ------------ in-register transmittance scan (this chunk) -------
            const float ex = __expf(-sigma * dtv);      // one_minus
            const float alpha = 1.f - ex;
            float p = ex;
#pragma unroll
            for (int o = 1; o < 32; o <<= 1) {
                float q = __shfl_up_sync(FULL, p, o);
                if (lane >= o) p *= q;
            }
            const float pm1 = __shfl_up_sync(FULL, p, 1);
            const float excl = carry * ((lane == 0) ? 1.f : pm1);   // T_excl
            const bool active = excl > 1e-4f;
            const float wgt = active ? excl * alpha : 0.f;
            sr  = fmaf(wgt, rr, sr);
            sg2 = fmaf(wgt, rg, sg2);
            sb  = fmaf(wgt, rb, sb);
            ftacc *= active ? ex : 1.f;
            carry *= __shfl_sync(FULL, p, 31);
        }

        // ---------------- final per-ray reduction (in-warp) -----------------
#pragma unroll
        for (int o = 16; o > 0; o >>= 1) {
            sr  += __shfl_xor_sync(FULL, sr, o);
            sg2 += __shfl_xor_sync(FULL, sg2, o);
            sb  += __shfl_xor_sync(FULL, sb, o);
            ftacc *= __shfl_xor_sync(FULL, ftacc, o);
        }
        if (lane == 0) {
            outp[ray * 3 + 0] = sr;
            outp[ray * 3 + 1] = sg2;
            outp[ray * 3 + 2] = sb;
            outp[3 * NR + ray] = ftacc;
        }
    }
}

// ---------------------------------------------------------------------------
extern "C" void kernel_launch(void* const* d_in, const int* in_sizes, int n_in,
                              void* d_out, int out_size) {
    const float* orig = (const float*)d_in[0];
    const float* dirs = (const float*)d_in[1];
    const float* tmin = (const float*)d_in[2];
    const float* tmax = (const float*)d_in[3];
    const float* W1   = (const float*)d_in[4];
    const float* b1   = (const float*)d_in[5];
    const float* W2   = (const float*)d_in[6];
    const float* b2   = (const float*)d_in[7];
    const float* V1   = (const float*)d_in[8];
    const float* c1   = (const float*)d_in[9];
    const float* V2   = (const float*)d_in[10];
    const float* c2   = (const float*)d_in[11];

    cudaFuncSetAttribute(fused_kernel, cudaFuncAttributeMaxDynamicSharedMemorySize, SMEM_TOTAL);

    fused_kernel<<<GRIDF, THREADS, SMEM_TOTAL>>>(orig, dirs, tmin, tmax,
                                                 W1, b1, W2, b2, V1, c1, V2, c2,
                                                 (float*)d_out);
}

// round 16
// speedup vs baseline: 2.2660x; 1.0034x over previous
#include <cuda_runtime.h>
#include <cuda_bf16.h>
#include <math.h>

#define NR 8192
#define SS 128
#define GRIDF 592            // 4 CTAs/SM x 148 SMs
#define THREADS 128          // 4 warps = 4 independent rays per iteration
#define RAYS_PER_ITER (GRIDF * 4)   // 2368
#define MAXI 4               // ceil(NR / RAYS_PER_ITER)

typedef unsigned int u32;

// ---------------- smem layout (bytes), per CTA ----------------
#define OFF_AH   0                 // 4 warps x 32 rows x 144B (bf16 hi only)
#define OFF_W1P  18432             // 32 sets (kt*8+nt) x 512B          = 16384
#define OFF_W2P  34816             // 8 sets (kt*2+n2) x 512B           = 4096
#define OFF_B3P  38912             // 8 sets (nt) x 512B                = 4096
#define OFF_B4P  43008             // 4 sets (kt) x 512B                = 2048
#define OFF_B2   45056             // b2 (16 f32)
#define OFF_C2   45120             // c2 (8 f32, padded)
#define OFF_RED  45152             // 4 warp partials (dt prologue only)
#define OFF_GB   45184             // g_base table [MAXI*4][64] f32     = 4096
#define SMEM_TOTAL (OFF_GB + MAXI * 4 * 64 * 4)   // 49280

// pack 2 floats -> bf16x2 in ONE instruction (low = x, high = y)
static __device__ __forceinline__ u32 pkbf2(float x, float y) {
    u32 r;
    asm("cvt.rn.satfinite.bf16x2.f32 %0, %1, %2;" : "=r"(r) : "f"(y), "f"(x));
    return r;
}
// hi/lo split of two floats -> packed hi word + packed lo word
static __device__ __forceinline__ void hisplit(float a, float b, u32& hi, u32& lo) {
    const float ha = __bfloat162float(__float2bfloat16(a));
    const float hb = __bfloat162float(__float2bfloat16(b));
    hi = pkbf2(ha, hb);
    lo = pkbf2(a - ha, b - hb);
}
static __device__ __forceinline__ void mma4(float* d, const u32* a, u32 b0, u32 b1) {
    asm volatile(
        "mma.sync.aligned.m16n8k16.row.col.f32.bf16.bf16.f32 "
        "{%0,%1,%2,%3}, {%4,%5,%6,%7}, {%8,%9}, {%0,%1,%2,%3};"
        : "+f"(d[0]), "+f"(d[1]), "+f"(d[2]), "+f"(d[3])
        : "r"(a[0]), "r"(a[1]), "r"(a[2]), "r"(a[3]), "r"(b0), "r"(b1));
}
#define LDSM4(r, a) \
    asm volatile("ldmatrix.sync.aligned.m8n8.x4.shared.b16 {%0,%1,%2,%3}, [%4];" \
        : "=r"((r)[0]), "=r"((r)[1]), "=r"((r)[2]), "=r"((r)[3]) : "r"(a))

// ---------------------------------------------------------------------------
// Fused ray-marcher: single kernel, warp-autonomous rays, packed B-fragments,
// ldmatrix A-fragments, split MLP2/MLP4 accumulator chains.
// ---------------------------------------------------------------------------
__global__ __launch_bounds__(THREADS, 4)
void fused_kernel(const float* __restrict__ orig, const float* __restrict__ dirs,
                  const float* __restrict__ tmin, const float* __restrict__ tmax,
                  const float* __restrict__ W1, const float* __restrict__ b1,
                  const float* __restrict__ W2, const float* __restrict__ b2,
                  const float* __restrict__ V1, const float* __restrict__ c1,
                  const float* __restrict__ V2, const float* __restrict__ c2,
                  float* __restrict__ outp) {
    extern __shared__ char dsm[];
    const int tid = threadIdx.x;
    const int w = tid >> 5, lane = tid & 31, g = lane >> 2, tig = lane & 3;
    const u32 FULL = 0xffffffffu;

    // ---------------- dt = mean(tmax - tmin)/SS (per-CTA, same order) -------
    float dtv;
    {
        float s = 0.f;
        const float4* a4p = (const float4*)tmin;
        const float4* b4p = (const float4*)tmax;
#pragma unroll 1
        for (int i = tid; i < NR / 4; i += THREADS) {
            float4 x = a4p[i], y = b4p[i];
            s += (y.x - x.x) + (y.y - x.y) + (y.z - x.z) + (y.w - x.w);
        }
#pragma unroll
        for (int o = 16; o > 0; o >>= 1) s += __shfl_down_sync(FULL, s, o);
        float* red = (float*)(dsm + OFF_RED);
        if (lane == 0) red[w] = s;
        __syncthreads();
        dtv = (red[0] + red[1] + red[2] + red[3]) / (float)(NR * SS);
        __syncthreads();
    }

    // ---------------- pack B-fragments (per-lane 16B, LDS.128-ready) -------
    for (int idx = tid; idx < 32 * 32; idx += THREADS) {      // W1P
        const int ln = idx & 31, fs = idx >> 5;
        const int kt = fs >> 3, nt = fs & 7;
        const int gg = ln >> 2, tg = ln & 3;
        const int n = nt * 8 + gg;
        const int k0 = kt * 16 + tg * 2;
        const float a0 = (k0     < 63) ? W1[(k0    ) * 64 + n] : b1[n];
        const float a1 = (k0 + 1 < 63) ? W1[(k0 + 1) * 64 + n] : b1[n];
        const float a8 = (k0 + 8 < 63) ? W1[(k0 + 8) * 64 + n] : b1[n];
        const float a9 = (k0 + 9 < 63) ? W1[(k0 + 9) * 64 + n] : b1[n];
        u32 h0, l0, h1, l1;
        hisplit(a0, a1, h0, l0);
        hisplit(a8, a9, h1, l1);
        *(uint4*)(dsm + OFF_W1P + (fs * 32 + ln) * 16) = make_uint4(h0, h1, l0, l1);
    }
    for (int idx = tid; idx < 8 * 32; idx += THREADS) {       // W2P
        const int ln = idx & 31, fs = idx >> 5;
        const int kt = fs >> 1, n2 = fs & 1;
        const int gg = ln >> 2, tg = ln & 3;
        const int n = n2 * 8 + gg;
        const int k0 = kt * 16 + tg * 2;
        const float a0 = W2[(k0    ) * 16 + n];
        const float a1 = W2[(k0 + 1) * 16 + n];
        const float a8 = W2[(k0 + 8) * 16 + n];
        const float a9 = W2[(k0 + 9) * 16 + n];
        u32 h0, l0, h1, l1;
        hisplit(a0, a1, h0, l0);
        hisplit(a8, a9, h1, l1);
        *(uint4*)(dsm + OFF_W2P + (fs * 32 + ln) * 16) = make_uint4(h0, h1, l0, l1);
    }
    for (int idx = tid; idx < 8 * 32; idx += THREADS) {       // B3P
        const int ln = idx & 31, nt = idx >> 5;
        const int gg = ln >> 2, tg = ln & 3;
        const int n = nt * 8 + gg;
        const int k0 = tg * 2;
        const float a0 = (k0     >= 1) ? V1[(k0     - 1) * 64 + n] : 0.f;
        const float a1 = V1[(k0 + 1 - 1) * 64 + n];
        const float a8 = V1[(k0 + 8 - 1) * 64 + n];
        const float a9 = V1[(k0 + 9 - 1) * 64 + n];
        u32 h0, l0, h1, l1;
        hisplit(a0, a1, h0, l0);
        hisplit(a8, a9, h1, l1);
        *(uint4*)(dsm + OFF_B3P + (nt * 32 + ln) * 16) = make_uint4(h0, h1, l0, l1);
    }
    for (int idx = tid; idx < 4 * 32; idx += THREADS) {       // B4P
        const int ln = idx & 31, kt = idx >> 5;
        const int gg = ln >> 2, tg = ln & 3;
        const int k0 = kt * 16 + tg * 2;
        const bool nb = gg < 3;
        const float a0 = nb ? V2[(k0    ) * 3 + gg] : 0.f;
        const float a1 = nb ? V2[(k0 + 1) * 3 + gg] : 0.f;
        const float a8 = nb ? V2[(k0 + 8) * 3 + gg] : 0.f;
        const float a9 = nb ? V2[(k0 + 9) * 3 + gg] : 0.f;
        u32 h0, l0, h1, l1;
        hisplit(a0, a1, h0, l0);
        hisplit(a8, a9, h1, l1);
        *(uint4*)(dsm + OFF_B4P + (kt * 32 + ln) * 16) = make_uint4(h0, h1, l0, l1);
    }
    if (tid < 16) ((float*)(dsm + OFF_B2))[tid] = b2[tid];
    if (tid < 8)  ((float*)(dsm + OFF_C2))[tid] = (tid < 3) ? c2[tid] : 0.f;

    // ---------------- per-CTA g_base table (entry e = i*4 + warp) -----------
    {
        const int j = tid & 63;
        float* gbt = (float*)(dsm + OFF_GB);
#pragma unroll 1
        for (int e = tid >> 6; e < MAXI * 4; e += 2) {
            const int ray = blockIdx.x * 4 + (e & 3) + (e >> 2) * RAYS_PER_ITER;
            if (ray >= NR) continue;
            const float dx = dirs[ray * 3 + 0], dy = dirs[ray * 3 + 1], dz = dirs[ray * 3 + 2];
            const float nrm = sqrtf(dx * dx + dy * dy + dz * dz) + 1e-8f;
            const float inv = 1.0f / nrm;
            const float vx = dx * inv, vy = dy * inv, vz = dz * inv;
            float v[27];
            v[0] = vx; v[1] = vy; v[2] = vz;
            {
                float sx, cx, sy, cy, sz, cz;
                sincosf(vx, &sx, &cx); sincosf(vy, &sy, &cy); sincosf(vz, &sz, &cz);
#pragma unroll
                for (int i = 0; i < 4; i++) {
                    v[3 + 6 * i + 0] = sx; v[3 + 6 * i + 1] = sy; v[3 + 6 * i + 2] = sz;
                    v[3 + 6 * i + 3] = cx; v[3 + 6 * i + 4] = cy; v[3 + 6 * i + 5] = cz;
                    const float nsx = 2.f * sx * cx, ncx = fmaf(-2.f * sx, sx, 1.f);
                    const float nsy = 2.f * sy * cy, ncy = fmaf(-2.f * sy, sy, 1.f);
                    const float nsz = 2.f * sz * cz, ncz = fmaf(-2.f * sz, sz, 1.f);
                    sx = nsx; cx = ncx; sy = nsy; cy = ncy; sz = nsz; cz = ncz;
                }
            }
            float acc0 = c1[j];
#pragma unroll 1
            for (int i = 0; i < 27; i++) acc0 = fmaf(v[i], V1[(15 + i) * 64 + j], acc0);
            gbt[e * 64 + j] = acc0;
        }
    }
    __syncthreads();   // last CTA-wide barrier — main loop is warp-autonomous

    char* const Ah_base = dsm + OFF_AH + w * 4608;
    // ldmatrix lane address: row = lane&15, k-offset = (lane>>4)*16
    const u32 AhS = (u32)__cvta_generic_to_shared(Ah_base)
                    + (u32)((lane & 15) * 144) + (u32)((lane >> 4) * 16);
    const uint4* const W1P = (const uint4*)(dsm + OFF_W1P);
    const uint4* const W2P = (const uint4*)(dsm + OFF_W2P);
    const uint4* const B3P = (const uint4*)(dsm + OFF_B3P);
    const uint4* const B4P = (const uint4*)(dsm + OFF_B4P);

#pragma unroll 1
    for (int it = 0; it < MAXI; it++) {
        const int ray = blockIdx.x * 4 + w + it * RAYS_PER_ITER;
        if (ray >= NR) break;

        const float dx = dirs[ray * 3 + 0], dy = dirs[ray * 3 + 1], dz = dirs[ray * 3 + 2];
        const float ox = orig[ray * 3 + 0], oy = orig[ray * 3 + 1], oz = orig[ray * 3 + 2];
        const float t0 = tmin[ray], t1 = tmax[ray];
        const float* gb = (const float*)(dsm + OFF_GB) + (it * 4 + w) * 64;

        float carry = 1.f, ftacc = 1.f, sr = 0.f, sg2 = 0.f, sb = 0.f;

#pragma unroll 1
        for (int chunk = 0; chunk < 4; chunk++) {
            const int s = chunk * 32 + lane;

            // ------------ positional encoding (fast sincos), row = lane -----
            const float tt = t0 + (float)s * (1.0f / (SS - 1)) * (t1 - t0);
            float enc[64];
            enc[0] = fmaf(dx, tt, ox);
            enc[1] = fmaf(dy, tt, oy);
            enc[2] = fmaf(dz, tt, oz);
            {
                float sx, cx, sy, cy, sz, cz;
                __sincosf(enc[0], &sx, &cx);
                __sincosf(enc[1], &sy, &cy);
                __sincosf(enc[2], &sz, &cz);
#pragma unroll
                for (int i = 0; i < 10; i++) {
                    enc[3 + 6 * i + 0] = sx; enc[3 + 6 * i + 1] = sy; enc[3 + 6 * i + 2] = sz;
                    enc[3 + 6 * i + 3] = cx; enc[3 + 6 * i + 4] = cy; enc[3 + 6 * i + 5] = cz;
                    const float nsx = 2.f * sx * cx, ncx = fmaf(-2.f * sx, sx, 1.f);
                    const float nsy = 2.f * sy * cy, ncy = fmaf(-2.f * sy, sy, 1.f);
                    const float nsz = 2.f * sz * cz, ncz = fmaf(-2.f * sz, sz, 1.f);
                    sx = nsx; cx = ncx; sy = nsy; cy = ncy; sz = nsz; cz = ncz;
                }
            }
            enc[63] = 1.0f;     // bias column: W1 row63 = b1
            {
                char* Ah = Ah_base + lane * 144;
#pragma unroll
                for (int j8 = 0; j8 < 8; j8++) {
                    *(uint4*)(Ah + j8 * 16) = make_uint4(
                        pkbf2(enc[8 * j8 + 0], enc[8 * j8 + 1]),
                        pkbf2(enc[8 * j8 + 2], enc[8 * j8 + 3]),
                        pkbf2(enc[8 * j8 + 4], enc[8 * j8 + 5]),
                        pkbf2(enc[8 * j8 + 6], enc[8 * j8 + 7]));
                }
            }
            __syncwarp();

            // ------------ MLP1: enc(64) @ W1 -> 32x64 (2-pass) --------------
            float acc[2][8][4];
#pragma unroll
            for (int mt = 0; mt < 2; mt++)
#pragma unroll
                for (int nt = 0; nt < 8; nt++)
#pragma unroll
                    for (int r = 0; r < 4; r++) acc[mt][nt][r] = 0.f;

#pragma unroll
            for (int kt = 0; kt < 4; kt++) {
                u32 AH[2][4];
                LDSM4(AH[0], AhS + kt * 32);
                LDSM4(AH[1], AhS + kt * 32 + 2304);
#pragma unroll
                for (int nt = 0; nt < 8; nt++) {
                    const uint4 bq = W1P[(kt * 8 + nt) * 32 + lane];
#pragma unroll
                    for (int mt = 0; mt < 2; mt++) {
                        mma4(acc[mt][nt], AH[mt], bq.x, bq.y);
                        mma4(acc[mt][nt], AH[mt], bq.z, bq.w);
                    }
                }
            }
            __syncwarp();   // A-tile reads done before next chunk's writes

            // ------------ epi1: h = relu(D) -> hi frags ---------------------
            u32 HF[2][4][4];
#pragma unroll
            for (int kt = 0; kt < 4; kt++)
#pragma unroll
                for (int j = 0; j < 2; j++) {
                    const int nt = 2 * kt + j;
#pragma unroll
                    for (int mt = 0; mt < 2; mt++) {
                        float v0 = fmaxf(acc[mt][nt][0], 0.f);
                        float v1 = fmaxf(acc[mt][nt][1], 0.f);
                        float v2 = fmaxf(acc[mt][nt][2], 0.f);
                        float v3 = fmaxf(acc[mt][nt][3], 0.f);
                        HF[mt][kt][2 * j + 0] = pkbf2(v0, v1);
                        HF[mt][kt][2 * j + 1] = pkbf2(v2, v3);
                    }
                }

            // ------------ MLP2: h @ W2 -> 32x16 (split accumulators) --------
            float a2e[2][2][4], a2o[2][2][4];
#pragma unroll
            for (int mt = 0; mt < 2; mt++)
#pragma unroll
                for (int n2 = 0; n2 < 2; n2++)
#pragma unroll
                    for (int r = 0; r < 4; r++) { a2e[mt][n2][r] = 0.f; a2o[mt][n2][r] = 0.f; }
#pragma unroll
            for (int kt = 0; kt < 4; kt++)
#pragma unroll
                for (int n2 = 0; n2 < 2; n2++) {
                    const uint4 bq = W2P[(kt * 2 + n2) * 32 + lane];
                    float (*dst)[2][4] = (kt & 1) ? a2o : a2e;
#pragma unroll
                    for (int mt = 0; mt < 2; mt++) {
                        mma4(dst[mt][n2], HF[mt][kt], bq.x, bq.y);
                        mma4(dst[mt][n2], HF[mt][kt], bq.z, bq.w);
                    }
                }

            // ------------ epi2: sigma raw + feat hi frags -------------------
            float sgm[2][2];
            u32 FF[2][4];
            {
                const float2 b20 = *(const float2*)(dsm + OFF_B2 + tig * 8);
                const float2 b21 = *(const float2*)(dsm + OFF_B2 + 32 + tig * 8);
#pragma unroll
                for (int mt = 0; mt < 2; mt++) {
                    float v0 = (a2e[mt][0][0] + a2o[mt][0][0]) + b20.x;
                    float v1 = (a2e[mt][0][1] + a2o[mt][0][1]) + b20.y;
                    float v2 = (a2e[mt][0][2] + a2o[mt][0][2]) + b20.x;
                    float v3 = (a2e[mt][0][3] + a2o[mt][0][3]) + b20.y;
                    float u0 = (a2e[mt][1][0] + a2o[mt][1][0]) + b21.x;
                    float u1 = (a2e[mt][1][1] + a2o[mt][1][1]) + b21.y;
                    float u2 = (a2e[mt][1][2] + a2o[mt][1][2]) + b21.x;
                    float u3 = (a2e[mt][1][3] + a2o[mt][1][3]) + b21.y;
                    sgm[mt][0] = v0;
                    sgm[mt][1] = v2;
                    FF[mt][0] = pkbf2(v0, v1);
                    FF[mt][1] = pkbf2(v2, v3);
                    FF[mt][2] = pkbf2(u0, u1);
                    FF[mt][3] = pkbf2(u2, u3);
                }
            }

            // ------------ MLP3: feats(16) @ B3 -> 32x64 (2-pass) ------------
            float a3c[2][8][4];
#pragma unroll
            for (int mt = 0; mt < 2; mt++)
#pragma unroll
                for (int nt = 0; nt < 8; nt++)
#pragma unroll
                    for (int r = 0; r < 4; r++) a3c[mt][nt][r] = 0.f;
#pragma unroll
            for (int nt = 0; nt < 8; nt++) {
                const uint4 bq = B3P[nt * 32 + lane];
#pragma unroll
                for (int mt = 0; mt < 2; mt++) {
                    mma4(a3c[mt][nt], FF[mt], bq.x, bq.y);
                    mma4(a3c[mt][nt], FF[mt], bq.z, bq.w);
                }
            }

            // ------------ epi3: g = relu(D + g_base) -> hi frags ------------
            u32 GF[2][4][4];
#pragma unroll
            for (int kt = 0; kt < 4; kt++)
#pragma unroll
                for (int j = 0; j < 2; j++) {
                    const int nt = 2 * kt + j;
                    const float2 gv = *(const float2*)(gb + nt * 8 + tig * 2);
#pragma unroll
                    for (int mt = 0; mt < 2; mt++) {
                        float v0 = fmaxf(a3c[mt][nt][0] + gv.x, 0.f);
                        float v1 = fmaxf(a3c[mt][nt][1] + gv.y, 0.f);
                        float v2 = fmaxf(a3c[mt][nt][2] + gv.x, 0.f);
                        float v3 = fmaxf(a3c[mt][nt][3] + gv.y, 0.f);
                        GF[mt][kt][2 * j + 0] = pkbf2(v0, v1);
                        GF[mt][kt][2 * j + 1] = pkbf2(v2, v3);
                    }
                }

            // ------------ MLP4: g @ V2 -> 32x8 (split accumulators) ---------
            float a4e[2][4], a4o[2][4];
#pragma unroll
            for (int mt = 0; mt < 2; mt++)
#pragma unroll
                for (int r = 0; r < 4; r++) { a4e[mt][r] = 0.f; a4o[mt][r] = 0.f; }
#pragma unroll
            for (int kt = 0; kt < 4; kt++) {
                const uint4 bq = B4P[kt * 32 + lane];
                float (*dst)[4] = (kt & 1) ? a4o : a4e;
#pragma unroll
                for (int mt = 0; mt < 2; mt++) {
                    mma4(dst[mt], GF[mt][kt], bq.x, bq.y);
                    mma4(dst[mt], GF[mt][kt], bq.z, bq.w);
                }
            }

            // ------------ epi4 + redistribution lane<->row ------------------
            float o0[2], o1[2], o2[2], o3[2];
            {
                const float2 cc = *(const float2*)(dsm + OFF_C2 + tig * 8);
#pragma unroll
                for (int mt = 0; mt < 2; mt++) {
                    o0[mt] = (a4e[mt][0] + a4o[mt][0]) + cc.x;
                    o1[mt] = (a4e[mt][1] + a4o[mt][1]) + cc.y;
                    o2[mt] = (a4e[mt][2] + a4o[mt][2]) + cc.x;
                    o3[mt] = (a4e[mt][3] + a4o[mt][3]) + cc.y;
                }
            }
            const int q4 = (lane & 7) * 4;
            const int selv = lane >> 3;
            float x0, x1, x2, x3;
            x0 = __shfl_sync(FULL, sgm[0][0], q4);
            x1 = __shfl_sync(FULL, sgm[0][1], q4);
            x2 = __shfl_sync(FULL, sgm[1][0], q4);
            x3 = __shfl_sync(FULL, sgm[1][1], q4);
            const float sigma = fmaxf(selv == 0 ? x0 : selv == 1 ? x1 : selv == 2 ? x2 : x3, 0.f);
            x0 = __shfl_sync(FULL, o0[0], q4);
            x1 = __shfl_sync(FULL, o2[0], q4);
            x2 = __shfl_sync(FULL, o0[1], q4);
            x3 = __shfl_sync(FULL, o2[1], q4);
            const float rv = selv == 0 ? x0 : selv == 1 ? x1 : selv == 2 ? x2 : x3;
            x0 = __shfl_sync(FULL, o1[0], q4);
            x1 = __shfl_sync(FULL, o3[0], q4);
            x2 = __shfl_sync(FULL, o1[1], q4);
            x3 = __shfl_sync(FULL, o3[1], q4);
            const float gvv = selv == 0 ? x0 : selv == 1 ? x1 : selv == 2 ? x2 : x3;
            x0 = __shfl_sync(FULL, o0[0], q4 + 1);
            x1 = __shfl_sync(FULL, o2[0], q4 + 1);
            x2 = __shfl_sync(FULL, o0[1], q4 + 1);
            x3 = __shfl_sync(FULL, o2[1], q4 + 1);
            const float bv = selv == 0 ? x0 : selv == 1 ? x1 : selv == 2 ? x2 : x3;
            const float rr = 1.f / (1.f + __expf(-rv));
            const float rg = 1.f / (1.f + __expf(-gvv));
            const float rb = 1.f / (1.f + __expf(-bv));

            // ------------ in-register transmittance scan (this chunk) -------
            const float ex = __expf(-sigma * dtv);      // one_minus
            const float alpha = 1.f - ex;
            float p = ex;
#pragma unroll
            for (int o = 1; o < 32; o <<= 1) {
                float q = __shfl_up_sync(FULL, p, o);
                if (lane >= o) p *= q;
            }
            const float pm1 = __shfl_up_sync(FULL, p, 1);
            const float excl = carry * ((lane == 0) ? 1.f : pm1);   // T_excl
            const bool active = excl > 1e-4f;
            const float wgt = active ? excl * alpha : 0.f;
            sr  = fmaf(wgt, rr, sr);
            sg2 = fmaf(wgt, rg, sg2);
            sb  = fmaf(wgt, rb, sb);
            ftacc *= active ? ex : 1.f;
            carry *= __shfl_sync(FULL, p, 31);
        }

        // ---------------- final per-ray reduction (in-warp) -----------------
#pragma unroll
        for (int o = 16; o > 0; o >>= 1) {
            sr  += __shfl_xor_sync(FULL, sr, o);
            sg2 += __shfl_xor_sync(FULL, sg2, o);
            sb  += __shfl_xor_sync(FULL, sb, o);
            ftacc *= __shfl_xor_sync(FULL, ftacc, o);
        }
        if (lane == 0) {
            outp[ray * 3 + 0] = sr;
            outp[ray * 3 + 1] = sg2;
            outp[ray * 3 + 2] = sb;
            outp[3 * NR + ray] = ftacc;
        }
    }
}

// ---------------------------------------------------------------------------
extern "C" void kernel_launch(void* const* d_in, const int* in_sizes, int n_in,
                              void* d_out, int out_size) {
    const float* orig = (const float*)d_in[0];
    const float* dirs = (const float*)d_in[1];
    const float* tmin = (const float*)d_in[2];
    const float* tmax = (const float*)d_in[3];
    const float* W1   = (const float*)d_in[4];
    const float* b1   = (const float*)d_in[5];
    const float* W2   = (const float*)d_in[6];
    const float* b2   = (const float*)d_in[7];
    const float* V1   = (const float*)d_in[8];
    const float* c1   = (const float*)d_in[9];
    const float* V2   = (const float*)d_in[10];
    const float* c2   = (const float*)d_in[11];

    cudaFuncSetAttribute(fused_kernel, cudaFuncAttributeMaxDynamicSharedMemorySize, SMEM_TOTAL);

    fused_kernel<<<GRIDF, THREADS, SMEM_TOTAL>>>(orig, dirs, tmin, tmax,
                                                 W1, b1, W2, b2, V1, c1, V2, c2,
                                                 (float*)d_out);
}